// round 10
// baseline (speedup 1.0000x reference)
#include <cuda_runtime.h>
#include <cuda_bf16.h>
#include <cuda_fp16.h>
#include <cstdint>

// ---------------------------------------------------------------------------
// Net_46368466928157 — round 10:
//   L1: fp16 scaled 2-part split HMMA (K 784->800), writes h fp16-pair direct
//   L2: fp16 scaled 2-part split HMMA (validated), c fp32
//   topk: margins (tau1=5e-5) + flagged rows get reference-class exact
//         recompute: h_fix (serial fp32) -> c_fix -> re-topk
//   L3: sparse row-gather GEMV fp32 (validated R9)
//   L4: bf16 2-part split HMMA (validated R7)
// ---------------------------------------------------------------------------

#define BATCH   16384
#define IN_DIM  784
#define K1P     800
#define INTER   1024
#define CODE    2048
#define N4P     896
#define NSTRIPE 32
#define KNEUR   64
#define KSTRIPE 4

#define TAU1 5e-5f
#define TAU2 2e-3f

typedef __nv_bfloat16 bf16;

// ---- scratch --------------------------------------------------------------
__device__ __half g_x0[(size_t)BATCH * K1P],  g_x1[(size_t)BATCH * K1P];
__device__ __half g_w1h[(size_t)INTER * K1P], g_w1l[(size_t)INTER * K1P];
__device__ __half g_hh16[(size_t)BATCH * INTER], g_hl16[(size_t)BATCH * INTER];
__device__ __half g_w2h16[(size_t)CODE * INTER], g_w2l16[(size_t)CODE * INTER];
__device__ float  g_c[(size_t)BATCH * CODE];
__device__ float  g_w3t[(size_t)CODE * INTER];
__device__ bf16   g_d0[(size_t)BATCH * INTER],  g_d1[(size_t)BATCH * INTER];
__device__ bf16   g_w4_0[(size_t)N4P * INTER],  g_w4_1[(size_t)N4P * INTER];
__device__ int    g_flag_cnt;
__device__ int    g_flag_rows[BATCH];
__device__ float  g_hfix[(size_t)BATCH * INTER];   // exact h rows, by flag slot
__device__ int    g_cnt[BATCH];
__device__ int    g_idx[(size_t)BATCH * KNEUR];
__device__ float  g_val[(size_t)BATCH * KNEUR];

// ===========================================================================
// PTX helpers
// ===========================================================================
__device__ __forceinline__ uint32_t smem_u32(const void* p) {
    uint32_t a;
    asm("{ .reg .u64 t; cvta.to.shared.u64 t, %1; cvt.u32.u64 %0, t; }" : "=r"(a) : "l"(p));
    return a;
}
#define CP_ASYNC16(dst, src) \
    asm volatile("cp.async.cg.shared.global [%0], [%1], 16;" :: "r"(dst), "l"(src) : "memory")
#define CP_COMMIT()  asm volatile("cp.async.commit_group;" ::: "memory")
#define CP_WAIT(n)   asm volatile("cp.async.wait_group %0;" :: "n"(n) : "memory")

__device__ __forceinline__ void ldsm_x4(uint32_t& r0, uint32_t& r1, uint32_t& r2,
                                        uint32_t& r3, uint32_t addr) {
    asm volatile("ldmatrix.sync.aligned.m8n8.x4.shared.b16 {%0,%1,%2,%3}, [%4];"
        : "=r"(r0), "=r"(r1), "=r"(r2), "=r"(r3) : "r"(addr));
}
__device__ __forceinline__ void mma_bf(float* c, const uint32_t* a, const uint32_t* b) {
    asm volatile("mma.sync.aligned.m16n8k16.row.col.f32.bf16.bf16.f32 "
        "{%0,%1,%2,%3}, {%4,%5,%6,%7}, {%8,%9}, {%0,%1,%2,%3};"
        : "+f"(c[0]), "+f"(c[1]), "+f"(c[2]), "+f"(c[3])
        : "r"(a[0]), "r"(a[1]), "r"(a[2]), "r"(a[3]), "r"(b[0]), "r"(b[1]));
}
__device__ __forceinline__ void mma_fp16(float* c, const uint32_t* a, const uint32_t* b) {
    asm volatile("mma.sync.aligned.m16n8k16.row.col.f32.f16.f16.f32 "
        "{%0,%1,%2,%3}, {%4,%5,%6,%7}, {%8,%9}, {%0,%1,%2,%3};"
        : "+f"(c[0]), "+f"(c[1]), "+f"(c[2]), "+f"(c[3])
        : "r"(a[0]), "r"(a[1]), "r"(a[2]), "r"(a[3]), "r"(b[0]), "r"(b[1]));
}

#define ROWB   80
#define TILE_B (128 * ROWB)
#define SM_TILES 1024
#define SMEM_HMMA (SM_TILES + 2 * 4 * TILE_B)

// ===========================================================================
// fp16 scaled-split GEMM: C = relu(bias + A@B^T), A1/B1 are lo*2048.
// acc1 = Ah*Bh ; acc2 = Al*Bh + Ah*Bl ; v = acc1 + acc2/2048 + bias
// OUTMODE 0: fp32 out. OUTMODE 1: fp16 pair out (hi, (v-hi)*2048).
// ===========================================================================
template<int OUTMODE>
__global__ __launch_bounds__(256, 1) void gemm_f16(
    const __half* __restrict__ A0, const __half* __restrict__ A1,
    const __half* __restrict__ B0, const __half* __restrict__ B1,
    const float* __restrict__ bias, float* __restrict__ Cf,
    __half* __restrict__ H0, __half* __restrict__ H1,
    int Kp, int Nvalid, int outStride)
{
    extern __shared__ char smem[];
    const uint32_t sbase = smem_u32(smem) + SM_TILES;
    const int tid  = threadIdx.x;
    const int warp = tid >> 5, lane = tid & 31;
    const int wm = (warp >> 2) * 64;
    const int wn = (warp & 3) * 32;
    const int m0 = blockIdx.y * 128;
    const int n0 = blockIdx.x * 128;

    if (tid < 128) {
        int n = n0 + tid;
        ((float*)smem)[tid] = (n < Nvalid) ? bias[n] : 0.0f;
    }

    float acc1[4][4][4], acc2[4][4][4];
#pragma unroll
    for (int i = 0; i < 4; i++)
#pragma unroll
        for (int j = 0; j < 4; j++)
#pragma unroll
            for (int q = 0; q < 4; q++) { acc1[i][j][q] = 0.0f; acc2[i][j][q] = 0.0f; }

    const __half* Ap[2] = { A0, A1 };
    const __half* Bp[2] = { B0, B1 };
    const int nk = Kp / 32;

    auto load_stage = [&](int kc, int s) {
        const int k0 = kc * 32;
        const uint32_t stb = sbase + s * 4 * TILE_B;
#pragma unroll
        for (int t = 0; t < 4; t++) {
            const __half* base = (t < 2) ? (Ap[t] + (size_t)m0 * Kp)
                                         : (Bp[t - 2] + (size_t)n0 * Kp);
#pragma unroll
            for (int i = 0; i < 2; i++) {
                int f = tid + i * 256;
                int row = f >> 2, c = f & 3;
                uint32_t dst = stb + t * TILE_B + row * ROWB + c * 16;
                CP_ASYNC16(dst, base + (size_t)row * Kp + k0 + c * 8);
            }
        }
        CP_COMMIT();
    };

    auto compute_stage = [&](int s) {
        const uint32_t stb = sbase + s * 4 * TILE_B;
#pragma unroll
        for (int ks = 0; ks < 2; ks++) {
            uint32_t afr[2][4][4];
#pragma unroll
            for (int p = 0; p < 2; p++) {
                const uint32_t Ab = stb + p * TILE_B;
#pragma unroll
                for (int mf = 0; mf < 4; mf++) {
                    int row = wm + mf * 16 + (lane & 15);
                    uint32_t off = row * ROWB + ks * 32 + (lane >> 4) * 16;
                    ldsm_x4(afr[p][mf][0], afr[p][mf][1], afr[p][mf][2], afr[p][mf][3], Ab + off);
                }
            }
#pragma unroll
            for (int j = 0; j < 2; j++) {
                const uint32_t Bb = stb + (2 + j) * TILE_B;
                uint32_t bfr[4][2];
#pragma unroll
                for (int p = 0; p < 2; p++) {
                    int g = lane >> 3, ri = lane & 7;
                    int row = wn + p * 16 + ((g >> 1) << 3) + ri;
                    uint32_t off = row * ROWB + (2 * ks + (g & 1)) * 16;
                    uint32_t t0, t1, t2, t3;
                    ldsm_x4(t0, t1, t2, t3, Bb + off);
                    bfr[p*2][0] = t0; bfr[p*2][1] = t1;
                    bfr[p*2+1][0] = t2; bfr[p*2+1][1] = t3;
                }
                if (j == 0) {
#pragma unroll
                    for (int mf = 0; mf < 4; mf++)
#pragma unroll
                        for (int nf = 0; nf < 4; nf++) {
                            mma_fp16(acc1[mf][nf], afr[0][mf], bfr[nf]);
                            mma_fp16(acc2[mf][nf], afr[1][mf], bfr[nf]);
                        }
                } else {
#pragma unroll
                    for (int mf = 0; mf < 4; mf++)
#pragma unroll
                        for (int nf = 0; nf < 4; nf++)
                            mma_fp16(acc2[mf][nf], afr[0][mf], bfr[nf]);
                }
            }
        }
    };

    load_stage(0, 0);
    for (int kc = 0; kc < nk; kc++) {
        if (kc + 1 < nk) { load_stage(kc + 1, (kc + 1) & 1); CP_WAIT(1); }
        else             { CP_WAIT(0); }
        __syncthreads();
        compute_stage(kc & 1);
        __syncthreads();
    }

    const float* bs = (const float*)smem;
    const float INV = 1.0f / 2048.0f;
    const int lr = lane >> 2;
    const int lc = (lane & 3) * 2;
#pragma unroll
    for (int mf = 0; mf < 4; mf++) {
#pragma unroll
        for (int nf = 0; nf < 4; nf++) {
            int nrel = wn + nf * 8 + lc;
            int n = n0 + nrel;
            float b0 = bs[nrel], b1 = bs[nrel + 1];
#pragma unroll
            for (int half = 0; half < 2; half++) {
                int m = m0 + wm + mf * 16 + lr + half * 8;
                float v0 = fmaxf(fmaf(acc2[mf][nf][half*2+0], INV, acc1[mf][nf][half*2+0]) + b0, 0.0f);
                float v1 = fmaxf(fmaf(acc2[mf][nf][half*2+1], INV, acc1[mf][nf][half*2+1]) + b1, 0.0f);
                if (OUTMODE == 0) {
                    if (n < Nvalid)
                        *(float2*)(Cf + (size_t)m * outStride + n) = make_float2(v0, v1);
                } else {
                    __half h0 = __float2half_rn(v0), h1 = __float2half_rn(v1);
                    __half2 hh = __halves2half2(h0, h1);
                    __half2 ll = __halves2half2(
                        __float2half_rn((v0 - __half2float(h0)) * 2048.0f),
                        __float2half_rn((v1 - __half2float(h1)) * 2048.0f));
                    *(__half2*)(H0 + (size_t)m * outStride + n) = hh;
                    *(__half2*)(H1 + (size_t)m * outStride + n) = ll;
                }
            }
        }
    }
}

// ===========================================================================
// L4 GEMM (bf16 2-part split — validated)
// ===========================================================================
__global__ __launch_bounds__(256, 1) void gemm_split2_f(
    const bf16* __restrict__ A0, const bf16* __restrict__ A1,
    const bf16* __restrict__ B0, const bf16* __restrict__ B1,
    const float* __restrict__ bias, float* __restrict__ Cf,
    int Kp, int Nvalid, int outStride)
{
    extern __shared__ char smem[];
    const uint32_t sbase = smem_u32(smem) + SM_TILES;
    const int tid  = threadIdx.x;
    const int warp = tid >> 5, lane = tid & 31;
    const int wm = (warp >> 2) * 64;
    const int wn = (warp & 3) * 32;
    const int m0 = blockIdx.y * 128;
    const int n0 = blockIdx.x * 128;

    if (tid < 128) {
        int n = n0 + tid;
        ((float*)smem)[tid] = (n < Nvalid) ? bias[n] : 0.0f;
    }

    float acc[4][4][4];
#pragma unroll
    for (int i = 0; i < 4; i++)
#pragma unroll
        for (int j = 0; j < 4; j++)
#pragma unroll
            for (int q = 0; q < 4; q++) acc[i][j][q] = 0.0f;

    const bf16* Ap[2] = { A0, A1 };
    const bf16* Bp[2] = { B0, B1 };
    const int nk = Kp / 32;

    auto load_stage = [&](int kc, int s) {
        const int k0 = kc * 32;
        const uint32_t stb = sbase + s * 4 * TILE_B;
#pragma unroll
        for (int t = 0; t < 4; t++) {
            const bf16* base = (t < 2) ? (Ap[t] + (size_t)m0 * Kp)
                                       : (Bp[t - 2] + (size_t)n0 * Kp);
#pragma unroll
            for (int i = 0; i < 2; i++) {
                int f = tid + i * 256;
                int row = f >> 2, c = f & 3;
                uint32_t dst = stb + t * TILE_B + row * ROWB + c * 16;
                CP_ASYNC16(dst, base + (size_t)row * Kp + k0 + c * 8);
            }
        }
        CP_COMMIT();
    };

    auto compute_stage = [&](int s) {
        const uint32_t stb = sbase + s * 4 * TILE_B;
#pragma unroll
        for (int ks = 0; ks < 2; ks++) {
            uint32_t afr[2][4][4];
#pragma unroll
            for (int p = 0; p < 2; p++) {
                const uint32_t Ab = stb + p * TILE_B;
#pragma unroll
                for (int mf = 0; mf < 4; mf++) {
                    int row = wm + mf * 16 + (lane & 15);
                    uint32_t off = row * ROWB + ks * 32 + (lane >> 4) * 16;
                    ldsm_x4(afr[p][mf][0], afr[p][mf][1], afr[p][mf][2], afr[p][mf][3], Ab + off);
                }
            }
#pragma unroll
            for (int j = 0; j < 2; j++) {
                const uint32_t Bb = stb + (2 + j) * TILE_B;
                uint32_t bfr[4][2];
#pragma unroll
                for (int p = 0; p < 2; p++) {
                    int g = lane >> 3, ri = lane & 7;
                    int row = wn + p * 16 + ((g >> 1) << 3) + ri;
                    uint32_t off = row * ROWB + (2 * ks + (g & 1)) * 16;
                    uint32_t t0, t1, t2, t3;
                    ldsm_x4(t0, t1, t2, t3, Bb + off);
                    bfr[p*2][0] = t0; bfr[p*2][1] = t1;
                    bfr[p*2+1][0] = t2; bfr[p*2+1][1] = t3;
                }
#pragma unroll
                for (int i = 0; i < 2 - j; i++)
#pragma unroll
                    for (int mf = 0; mf < 4; mf++)
#pragma unroll
                        for (int nf = 0; nf < 4; nf++)
                            mma_bf(acc[mf][nf], afr[i][mf], bfr[nf]);
            }
        }
    };

    load_stage(0, 0);
    for (int kc = 0; kc < nk; kc++) {
        if (kc + 1 < nk) { load_stage(kc + 1, (kc + 1) & 1); CP_WAIT(1); }
        else             { CP_WAIT(0); }
        __syncthreads();
        compute_stage(kc & 1);
        __syncthreads();
    }

    const float* bs = (const float*)smem;
    const int lr = lane >> 2;
    const int lc = (lane & 3) * 2;
#pragma unroll
    for (int mf = 0; mf < 4; mf++) {
#pragma unroll
        for (int nf = 0; nf < 4; nf++) {
            int nrel = wn + nf * 8 + lc;
            int n = n0 + nrel;
            float b0 = bs[nrel], b1 = bs[nrel + 1];
#pragma unroll
            for (int half = 0; half < 2; half++) {
                int m = m0 + wm + mf * 16 + lr + half * 8;
                float v0 = fmaxf(acc[mf][nf][half * 2 + 0] + b0, 0.0f);
                float v1 = fmaxf(acc[mf][nf][half * 2 + 1] + b1, 0.0f);
                if (n < Nvalid)
                    *(float2*)(Cf + (size_t)m * outStride + n) = make_float2(v0, v1);
            }
        }
    }
}

// ---------------------------------------------------------------------------
// prep kernels
// ---------------------------------------------------------------------------
__global__ __launch_bounds__(256) void split16_pad(
    const float* __restrict__ src, __half* __restrict__ H, __half* __restrict__ L,
    int srows, int scols, int orows, int ocols)
{
    size_t i = (size_t)blockIdx.x * blockDim.x + threadIdx.x;
    size_t tot = (size_t)orows * ocols;
    if (i >= tot) return;
    int r = (int)(i / ocols), c = (int)(i % ocols);
    float v = (r < srows && c < scols) ? src[(size_t)r * scols + c] : 0.0f;
    __half h = __float2half_rn(v);
    H[i] = h;
    L[i] = __float2half_rn((v - __half2float(h)) * 2048.0f);
}

__global__ __launch_bounds__(256) void split_pad2(
    const float* __restrict__ src, bf16* __restrict__ P0, bf16* __restrict__ P1,
    int srows, int scols, int orows, int ocols)
{
    size_t i = (size_t)blockIdx.x * blockDim.x + threadIdx.x;
    size_t tot = (size_t)orows * ocols;
    if (i >= tot) return;
    int r = (int)(i / ocols), c = (int)(i % ocols);
    float v = (r < srows && c < scols) ? src[(size_t)r * scols + c] : 0.0f;
    bf16 a = __float2bfloat16(v);
    P0[i] = a;
    P1[i] = __float2bfloat16(v - __bfloat162float(a));
}

__global__ void transpose_w3(const float* __restrict__ W3, float* __restrict__ W3T)
{
    __shared__ float t[32][33];
    int bx = blockIdx.x * 32;
    int by = blockIdx.y * 32;
    for (int i = threadIdx.y; i < 32; i += 8)
        t[i][threadIdx.x] = W3[(size_t)(by + i) * CODE + bx + threadIdx.x];
    __syncthreads();
    for (int i = threadIdx.y; i < 32; i += 8)
        W3T[(size_t)(bx + i) * INTER + by + threadIdx.x] = t[threadIdx.x][i];
}

// ---------------------------------------------------------------------------
// topk body (validated) — flags tight rows, emits compact (idx,val) lists
// ---------------------------------------------------------------------------
struct TopkSmem {
    unsigned int hist[256];
    unsigned int eqscan[256];
    float psum[256];
    float bmaxs[256];
    float ssum[NSTRIPE];
    float smask[NSTRIPE];
    unsigned int s_prefix, s_remk, s_total;
};

__device__ __forceinline__ void topk_body(
    TopkSmem& S, const float* __restrict__ C, int row, bool flagmode)
{
    const int tid = threadIdx.x;
    const float* crow = C + (size_t)row * CODE;

    float f[8];
    *(float4*)&f[0] = *(const float4*)(crow + tid * 8);
    *(float4*)&f[4] = *(const float4*)(crow + tid * 8 + 4);
    unsigned int u[8];
#pragma unroll
    for (int j = 0; j < 8; j++) u[j] = __float_as_uint(f[j]);

    if (tid == 0) { S.s_prefix = 0; S.s_remk = KNEUR; }
    __syncthreads();

#pragma unroll
    for (int pass = 0; pass < 4; pass++) {
        const int shift = 24 - pass * 8;
        const unsigned int pm = (pass == 0) ? 0u : (0xFFFFFFFFu << (shift + 8));
        S.hist[tid] = 0;
        __syncthreads();
        unsigned int pref = S.s_prefix;
#pragma unroll
        for (int j = 0; j < 8; j++)
            if ((u[j] & pm) == pref) atomicAdd(&S.hist[(u[j] >> shift) & 0xFF], 1u);
        __syncthreads();
        if (tid == 0) {
            unsigned int remk = S.s_remk, acc = 0;
            int b = 255;
            for (; b > 0; b--) { acc += S.hist[b]; if (acc >= remk) break; }
            if (acc < remk) acc += S.hist[0];
            S.s_prefix = pref | ((unsigned int)b << shift);
            S.s_remk = remk - (acc - S.hist[b]);
        }
        __syncthreads();
    }

    const unsigned int t = S.s_prefix;
    const unsigned int need_eq = S.s_remk;

    unsigned int cnt = 0;
    float bmax = 0.0f;
#pragma unroll
    for (int j = 0; j < 8; j++) {
        cnt += (u[j] == t);
        if (u[j] < t) bmax = fmaxf(bmax, f[j]);
    }
    S.eqscan[tid] = cnt;
    S.bmaxs[tid] = bmax;
    __syncthreads();
    if (tid == 0) {
        unsigned int run = 0;
        for (int i = 0; i < 256; i++) { unsigned int v = S.eqscan[i]; S.eqscan[i] = run; run += v; }
        S.s_total = run;
    }
#pragma unroll
    for (int off = 128; off > 0; off >>= 1) {
        __syncthreads();
        if (tid < off) S.bmaxs[tid] = fmaxf(S.bmaxs[tid], S.bmaxs[tid + off]);
    }
    __syncthreads();

    unsigned int rank = S.eqscan[tid];
    float part = 0.0f;
#pragma unroll
    for (int j = 0; j < 8; j++) {
        bool keep;
        if (u[j] > t) keep = true;
        else if (u[j] == t) { keep = (rank < need_eq); rank++; }
        else keep = false;
        if (!keep) f[j] = 0.0f;
        part += f[j];
    }
    S.psum[tid] = part;
    __syncthreads();

    if (tid < NSTRIPE) {
        float s = 0.0f;
#pragma unroll
        for (int i = 0; i < 8; i++) s += S.psum[tid * 8 + i];
        S.ssum[tid] = s;
    }
    __syncthreads();

    if (tid == 0) {
        bool sel[NSTRIPE];
#pragma unroll
        for (int s = 0; s < NSTRIPE; s++) sel[s] = false;
        float v4 = 0.0f, v5 = 0.0f;
        for (int it = 0; it < KSTRIPE + 1; it++) {
            int best = -1; float bv = -1.0f;
            for (int s = 0; s < NSTRIPE; s++)
                if (!sel[s] && S.ssum[s] > bv) { bv = S.ssum[s]; best = s; }
            if (it < KSTRIPE) { sel[best] = true; if (it == KSTRIPE - 1) v4 = bv; }
            else v5 = bv;
        }
#pragma unroll
        for (int s = 0; s < NSTRIPE; s++) S.smask[s] = sel[s] ? 1.0f : 0.0f;

        if (flagmode) {
            float gap_n = __uint_as_float(t) - S.bmaxs[0];
            if (need_eq < S.s_total) gap_n = 0.0f;
            float gap_s = v4 - v5;
            if (gap_n < TAU1 || gap_s < TAU2) {
                int ix = atomicAdd(&g_flag_cnt, 1);
                g_flag_rows[ix] = row;
            }
        }
    }
    __syncthreads();

    const float sm = S.smask[tid >> 3];
    float mv[8];
    unsigned int myc = 0;
#pragma unroll
    for (int j = 0; j < 8; j++) { mv[j] = f[j] * sm; myc += (mv[j] != 0.0f); }
    S.eqscan[tid] = myc;
    __syncthreads();
    if (tid == 0) {
        unsigned int run = 0;
        for (int i = 0; i < 256; i++) { unsigned int v = S.eqscan[i]; S.eqscan[i] = run; run += v; }
        g_cnt[row] = (int)run;
    }
    __syncthreads();
    int base = (int)S.eqscan[tid];
    const int gb = row * KNEUR;
#pragma unroll
    for (int j = 0; j < 8; j++) {
        if (mv[j] != 0.0f) {
            g_idx[gb + base] = tid * 8 + j;
            g_val[gb + base] = mv[j];
            base++;
        }
    }
}

__global__ __launch_bounds__(256) void topk_flag_kernel(const float* __restrict__ C)
{
    __shared__ TopkSmem S;
    topk_body(S, C, blockIdx.x, true);
}

__global__ __launch_bounds__(256) void reset_cnt_kernel()
{
    if (threadIdx.x == 0 && blockIdx.x == 0) g_flag_cnt = 0;
}

// exact h rows for flagged slots (serial fp32, ascending k — reference-class)
__global__ __launch_bounds__(256) void h_fix_kernel(
    const float* __restrict__ x, const float* __restrict__ W1,
    const float* __restrict__ b1)
{
    __shared__ float xs[IN_DIM];
    const int tid = threadIdx.x;
    const int nf = g_flag_cnt;
    for (int slot = blockIdx.x; slot < nf; slot += gridDim.x) {
        const int row = g_flag_rows[slot];
        for (int k = tid; k < IN_DIM; k += 256)
            xs[k] = x[(size_t)row * IN_DIM + k];
        __syncthreads();
#pragma unroll
        for (int jj = 0; jj < 4; jj++) {
            int j = tid + jj * 256;
            const float* w = W1 + (size_t)j * IN_DIM;
            float acc = 0.0f;
            for (int k = 0; k < IN_DIM; k++)
                acc = fmaf(xs[k], w[k], acc);
            g_hfix[(size_t)slot * INTER + j] = fmaxf(acc + b1[j], 0.0f);
        }
        __syncthreads();
    }
}

// exact c rows for flagged slots (reads g_hfix by slot)
__global__ __launch_bounds__(256) void fixup_exact_kernel(
    const float* __restrict__ W2, const float* __restrict__ b2, float* __restrict__ c)
{
    __shared__ float hs[8][INTER];
    const int tid = threadIdx.x;
    const int nf = g_flag_cnt;

    for (int base = blockIdx.x * 8; base < nf; base += gridDim.x * 8) {
        int nrows = nf - base; if (nrows > 8) nrows = 8;
        for (int r = 0; r < nrows; r++) {
            for (int k = tid; k < INTER; k += 256)
                hs[r][k] = g_hfix[(size_t)(base + r) * INTER + k];
        }
        __syncthreads();
#pragma unroll 1
        for (int jj = 0; jj < 8; jj++) {
            int j = tid + jj * 256;
            const float* w = W2 + (size_t)j * INTER;
            float acc[8];
#pragma unroll
            for (int r = 0; r < 8; r++) acc[r] = 0.0f;
            for (int k = 0; k < INTER; k += 4) {
                float4 w4 = *(const float4*)(w + k);
#pragma unroll
                for (int r = 0; r < 8; r++) {
                    acc[r] = fmaf(hs[r][k + 0], w4.x, acc[r]);
                    acc[r] = fmaf(hs[r][k + 1], w4.y, acc[r]);
                    acc[r] = fmaf(hs[r][k + 2], w4.z, acc[r]);
                    acc[r] = fmaf(hs[r][k + 3], w4.w, acc[r]);
                }
            }
            float bj = b2[j];
            for (int r = 0; r < nrows; r++) {
                int row = g_flag_rows[base + r];
                c[(size_t)row * CODE + j] = fmaxf(acc[r] + bj, 0.0f);
            }
        }
        __syncthreads();
    }
}

__global__ __launch_bounds__(256) void fixup_topk_kernel(const float* __restrict__ C)
{
    __shared__ TopkSmem S;
    const int nf = g_flag_cnt;
    for (int i = blockIdx.x; i < nf; i += gridDim.x) {
        topk_body(S, C, g_flag_rows[i], false);
        __syncthreads();
    }
}

// ---------------------------------------------------------------------------
// L3: sparse row-gather GEMV fp32 -> d bf16 pair (validated R9)
// ---------------------------------------------------------------------------
__global__ __launch_bounds__(256) void l3_gather(
    const float* __restrict__ W3T, const float* __restrict__ b3,
    bf16* __restrict__ D0, bf16* __restrict__ D1)
{
    __shared__ float sval[KNEUR];
    __shared__ int   sidx[KNEUR];
    const int row = blockIdx.x, tid = threadIdx.x;
    const int cnt = g_cnt[row];
    if (tid < KNEUR && tid < cnt) {
        sidx[tid] = g_idx[row * KNEUR + tid];
        sval[tid] = g_val[row * KNEUR + tid];
    }
    __syncthreads();

    const int n = tid * 4;
    float4 acc = *(const float4*)(b3 + n);
    int j = 0;
    for (; j + 4 <= cnt; j += 4) {
        const float4 w0 = *(const float4*)(W3T + (size_t)sidx[j + 0] * INTER + n);
        const float4 w1 = *(const float4*)(W3T + (size_t)sidx[j + 1] * INTER + n);
        const float4 w2 = *(const float4*)(W3T + (size_t)sidx[j + 2] * INTER + n);
        const float4 w3 = *(const float4*)(W3T + (size_t)sidx[j + 3] * INTER + n);
        const float v0 = sval[j], v1 = sval[j + 1], v2 = sval[j + 2], v3 = sval[j + 3];
        acc.x = fmaf(v0, w0.x, acc.x); acc.y = fmaf(v0, w0.y, acc.y);
        acc.z = fmaf(v0, w0.z, acc.z); acc.w = fmaf(v0, w0.w, acc.w);
        acc.x = fmaf(v1, w1.x, acc.x); acc.y = fmaf(v1, w1.y, acc.y);
        acc.z = fmaf(v1, w1.z, acc.z); acc.w = fmaf(v1, w1.w, acc.w);
        acc.x = fmaf(v2, w2.x, acc.x); acc.y = fmaf(v2, w2.y, acc.y);
        acc.z = fmaf(v2, w2.z, acc.z); acc.w = fmaf(v2, w2.w, acc.w);
        acc.x = fmaf(v3, w3.x, acc.x); acc.y = fmaf(v3, w3.y, acc.y);
        acc.z = fmaf(v3, w3.z, acc.z); acc.w = fmaf(v3, w3.w, acc.w);
    }
    for (; j < cnt; j++) {
        const float4 w0 = *(const float4*)(W3T + (size_t)sidx[j] * INTER + n);
        const float v0 = sval[j];
        acc.x = fmaf(v0, w0.x, acc.x); acc.y = fmaf(v0, w0.y, acc.y);
        acc.z = fmaf(v0, w0.z, acc.z); acc.w = fmaf(v0, w0.w, acc.w);
    }

    acc.x = fmaxf(acc.x, 0.0f); acc.y = fmaxf(acc.y, 0.0f);
    acc.z = fmaxf(acc.z, 0.0f); acc.w = fmaxf(acc.w, 0.0f);

    __nv_bfloat162 p0a, p0b, p1a, p1b;
    p0a.x = __float2bfloat16(acc.x); p0a.y = __float2bfloat16(acc.y);
    p0b.x = __float2bfloat16(acc.z); p0b.y = __float2bfloat16(acc.w);
    p1a.x = __float2bfloat16(acc.x - __bfloat162float(p0a.x));
    p1a.y = __float2bfloat16(acc.y - __bfloat162float(p0a.y));
    p1b.x = __float2bfloat16(acc.z - __bfloat162float(p0b.x));
    p1b.y = __float2bfloat16(acc.w - __bfloat162float(p0b.y));
    *(__nv_bfloat162*)(D0 + (size_t)row * INTER + n)     = p0a;
    *(__nv_bfloat162*)(D0 + (size_t)row * INTER + n + 2) = p0b;
    *(__nv_bfloat162*)(D1 + (size_t)row * INTER + n)     = p1a;
    *(__nv_bfloat162*)(D1 + (size_t)row * INTER + n + 2) = p1b;
}

// ---------------------------------------------------------------------------
extern "C" void kernel_launch(void* const* d_in, const int* in_sizes, int n_in,
                              void* d_out, int out_size)
{
    const float* x  = (const float*)d_in[0];
    const float* W1 = (const float*)d_in[1];
    const float* b1 = (const float*)d_in[2];
    const float* W2 = (const float*)d_in[3];
    const float* b2 = (const float*)d_in[4];
    const float* W3 = (const float*)d_in[5];
    const float* b3 = (const float*)d_in[6];
    const float* W4 = (const float*)d_in[7];
    const float* b4 = (const float*)d_in[8];
    float* out = (float*)d_out;

    float *c, *w3t;
    __half *x0, *x1, *w1h, *w1l, *hh16, *hl16, *w2h16, *w2l16;
    bf16 *d0, *d1, *w40, *w41;
    cudaGetSymbolAddress((void**)&c, g_c);
    cudaGetSymbolAddress((void**)&w3t, g_w3t);
    cudaGetSymbolAddress((void**)&x0, g_x0);       cudaGetSymbolAddress((void**)&x1, g_x1);
    cudaGetSymbolAddress((void**)&w1h, g_w1h);     cudaGetSymbolAddress((void**)&w1l, g_w1l);
    cudaGetSymbolAddress((void**)&hh16, g_hh16);   cudaGetSymbolAddress((void**)&hl16, g_hl16);
    cudaGetSymbolAddress((void**)&w2h16, g_w2h16); cudaGetSymbolAddress((void**)&w2l16, g_w2l16);
    cudaGetSymbolAddress((void**)&d0, g_d0);       cudaGetSymbolAddress((void**)&d1, g_d1);
    cudaGetSymbolAddress((void**)&w40, g_w4_0);    cudaGetSymbolAddress((void**)&w41, g_w4_1);

    cudaFuncSetAttribute(gemm_f16<0>, cudaFuncAttributeMaxDynamicSharedMemorySize, SMEM_HMMA);
    cudaFuncSetAttribute(gemm_f16<1>, cudaFuncAttributeMaxDynamicSharedMemorySize, SMEM_HMMA);
    cudaFuncSetAttribute(gemm_split2_f, cudaFuncAttributeMaxDynamicSharedMemorySize, SMEM_HMMA);

    auto gs = [](size_t n) { return (unsigned)((n + 255) / 256); };

    // prep: splits + transpose
    split16_pad<<<gs((size_t)BATCH * K1P), 256>>>(x,  x0,  x1,  BATCH, IN_DIM, BATCH, K1P);
    split16_pad<<<gs((size_t)INTER * K1P), 256>>>(W1, w1h, w1l, INTER, IN_DIM, INTER, K1P);
    split16_pad<<<gs((size_t)CODE * INTER), 256>>>(W2, w2h16, w2l16, CODE, INTER, CODE, INTER);
    split_pad2<<<gs((size_t)N4P * INTER), 256>>>(W4, w40, w41, IN_DIM, INTER, N4P, INTER);
    transpose_w3<<<dim3(CODE / 32, INTER / 32), dim3(32, 8)>>>(W3, w3t);

    // L1: fp16-split HMMA -> h pair direct
    gemm_f16<1><<<dim3(INTER / 128, BATCH / 128), 256, SMEM_HMMA>>>(
        x0, x1, w1h, w1l, b1, nullptr, hh16, hl16, K1P, INTER, INTER);

    // L2: fp16-split HMMA -> c fp32
    gemm_f16<0><<<dim3(CODE / 128, BATCH / 128), 256, SMEM_HMMA>>>(
        hh16, hl16, w2h16, w2l16, b2, c, nullptr, nullptr, INTER, CODE, CODE);

    // topk with margins; flagged rows get reference-class exact chain
    reset_cnt_kernel<<<1, 32>>>();
    topk_flag_kernel<<<BATCH, 256>>>(c);
    h_fix_kernel<<<512, 256>>>(x, W1, b1);
    fixup_exact_kernel<<<256, 256>>>(W2, b2, c);
    fixup_topk_kernel<<<512, 256>>>(c);

    // L3 sparse gather -> d pair
    l3_gather<<<BATCH, 256>>>(w3t, b3, d0, d1);

    // L4 HMMA split -> out
    gemm_split2_f<<<dim3(N4P / 128, BATCH / 128), 256, SMEM_HMMA>>>(
        d0, d1, w40, w41, b4, out, INTER, IN_DIM, IN_DIM);
}

// round 12
// speedup vs baseline: 1.8129x; 1.8129x over previous
#include <cuda_runtime.h>
#include <cuda_bf16.h>
#include <cuda_fp16.h>
#include <cstdint>

// ---------------------------------------------------------------------------
// Net_46368466928157 — round 12 (resubmit of R11; infra failure last round):
//   L1: fp16 scaled 2-part split HMMA (K 784->800), writes h fp16-pair direct
//   L2: fp16 scaled 2-part split HMMA, c fp32
//   topk: margins (tau1=2.5e-5) + flagged rows: exact fp32 recompute chain
//         h_fix (warp-GEMV) -> c_fix (warp-GEMV) -> re-topk
//   L3: sparse row-gather GEMV fp32
//   L4: bf16 2-part split HMMA
// ---------------------------------------------------------------------------

#define BATCH   16384
#define IN_DIM  784
#define K1P     800
#define INTER   1024
#define CODE    2048
#define N4P     896
#define NSTRIPE 32
#define KNEUR   64
#define KSTRIPE 4

#define TAU1 2.5e-5f
#define TAU2 2e-3f

typedef __nv_bfloat16 bf16;

// ---- scratch --------------------------------------------------------------
__device__ __half g_x0[(size_t)BATCH * K1P],  g_x1[(size_t)BATCH * K1P];
__device__ __half g_w1h[(size_t)INTER * K1P], g_w1l[(size_t)INTER * K1P];
__device__ __half g_hh16[(size_t)BATCH * INTER], g_hl16[(size_t)BATCH * INTER];
__device__ __half g_w2h16[(size_t)CODE * INTER], g_w2l16[(size_t)CODE * INTER];
__device__ float  g_c[(size_t)BATCH * CODE];
__device__ float  g_w3t[(size_t)CODE * INTER];
__device__ bf16   g_d0[(size_t)BATCH * INTER],  g_d1[(size_t)BATCH * INTER];
__device__ bf16   g_w4_0[(size_t)N4P * INTER],  g_w4_1[(size_t)N4P * INTER];
__device__ int    g_flag_cnt;
__device__ int    g_flag_rows[BATCH];
__device__ float  g_hfix[(size_t)BATCH * INTER];
__device__ int    g_cnt[BATCH];
__device__ int    g_idx[(size_t)BATCH * KNEUR];
__device__ float  g_val[(size_t)BATCH * KNEUR];

// ===========================================================================
// PTX helpers
// ===========================================================================
__device__ __forceinline__ uint32_t smem_u32(const void* p) {
    uint32_t a;
    asm("{ .reg .u64 t; cvta.to.shared.u64 t, %1; cvt.u32.u64 %0, t; }" : "=r"(a) : "l"(p));
    return a;
}
#define CP_ASYNC16(dst, src) \
    asm volatile("cp.async.cg.shared.global [%0], [%1], 16;" :: "r"(dst), "l"(src) : "memory")
#define CP_COMMIT()  asm volatile("cp.async.commit_group;" ::: "memory")
#define CP_WAIT(n)   asm volatile("cp.async.wait_group %0;" :: "n"(n) : "memory")

__device__ __forceinline__ void ldsm_x4(uint32_t& r0, uint32_t& r1, uint32_t& r2,
                                        uint32_t& r3, uint32_t addr) {
    asm volatile("ldmatrix.sync.aligned.m8n8.x4.shared.b16 {%0,%1,%2,%3}, [%4];"
        : "=r"(r0), "=r"(r1), "=r"(r2), "=r"(r3) : "r"(addr));
}
__device__ __forceinline__ void mma_bf(float* c, const uint32_t* a, const uint32_t* b) {
    asm volatile("mma.sync.aligned.m16n8k16.row.col.f32.bf16.bf16.f32 "
        "{%0,%1,%2,%3}, {%4,%5,%6,%7}, {%8,%9}, {%0,%1,%2,%3};"
        : "+f"(c[0]), "+f"(c[1]), "+f"(c[2]), "+f"(c[3])
        : "r"(a[0]), "r"(a[1]), "r"(a[2]), "r"(a[3]), "r"(b[0]), "r"(b[1]));
}
__device__ __forceinline__ void mma_fp16(float* c, const uint32_t* a, const uint32_t* b) {
    asm volatile("mma.sync.aligned.m16n8k16.row.col.f32.f16.f16.f32 "
        "{%0,%1,%2,%3}, {%4,%5,%6,%7}, {%8,%9}, {%0,%1,%2,%3};"
        : "+f"(c[0]), "+f"(c[1]), "+f"(c[2]), "+f"(c[3])
        : "r"(a[0]), "r"(a[1]), "r"(a[2]), "r"(a[3]), "r"(b[0]), "r"(b[1]));
}

#define ROWB   80
#define TILE_B (128 * ROWB)
#define SM_TILES 1024
#define SMEM_HMMA (SM_TILES + 2 * 4 * TILE_B)

// ===========================================================================
// fp16 scaled-split GEMM (validated): C = relu(bias + A@B^T).
// OUTMODE 0: fp32 out. OUTMODE 1: fp16 pair out.
// ===========================================================================
template<int OUTMODE>
__global__ __launch_bounds__(256, 1) void gemm_f16(
    const __half* __restrict__ A0, const __half* __restrict__ A1,
    const __half* __restrict__ B0, const __half* __restrict__ B1,
    const float* __restrict__ bias, float* __restrict__ Cf,
    __half* __restrict__ H0, __half* __restrict__ H1,
    int Kp, int Nvalid, int outStride)
{
    extern __shared__ char smem[];
    const uint32_t sbase = smem_u32(smem) + SM_TILES;
    const int tid  = threadIdx.x;
    const int warp = tid >> 5, lane = tid & 31;
    const int wm = (warp >> 2) * 64;
    const int wn = (warp & 3) * 32;
    const int m0 = blockIdx.y * 128;
    const int n0 = blockIdx.x * 128;

    if (tid < 128) {
        int n = n0 + tid;
        ((float*)smem)[tid] = (n < Nvalid) ? bias[n] : 0.0f;
    }

    float acc1[4][4][4], acc2[4][4][4];
#pragma unroll
    for (int i = 0; i < 4; i++)
#pragma unroll
        for (int j = 0; j < 4; j++)
#pragma unroll
            for (int q = 0; q < 4; q++) { acc1[i][j][q] = 0.0f; acc2[i][j][q] = 0.0f; }

    const __half* Ap[2] = { A0, A1 };
    const __half* Bp[2] = { B0, B1 };
    const int nk = Kp / 32;

    auto load_stage = [&](int kc, int s) {
        const int k0 = kc * 32;
        const uint32_t stb = sbase + s * 4 * TILE_B;
#pragma unroll
        for (int t = 0; t < 4; t++) {
            const __half* base = (t < 2) ? (Ap[t] + (size_t)m0 * Kp)
                                         : (Bp[t - 2] + (size_t)n0 * Kp);
#pragma unroll
            for (int i = 0; i < 2; i++) {
                int f = tid + i * 256;
                int row = f >> 2, c = f & 3;
                uint32_t dst = stb + t * TILE_B + row * ROWB + c * 16;
                CP_ASYNC16(dst, base + (size_t)row * Kp + k0 + c * 8);
            }
        }
        CP_COMMIT();
    };

    auto compute_stage = [&](int s) {
        const uint32_t stb = sbase + s * 4 * TILE_B;
#pragma unroll
        for (int ks = 0; ks < 2; ks++) {
            uint32_t afr[2][4][4];
#pragma unroll
            for (int p = 0; p < 2; p++) {
                const uint32_t Ab = stb + p * TILE_B;
#pragma unroll
                for (int mf = 0; mf < 4; mf++) {
                    int row = wm + mf * 16 + (lane & 15);
                    uint32_t off = row * ROWB + ks * 32 + (lane >> 4) * 16;
                    ldsm_x4(afr[p][mf][0], afr[p][mf][1], afr[p][mf][2], afr[p][mf][3], Ab + off);
                }
            }
#pragma unroll
            for (int j = 0; j < 2; j++) {
                const uint32_t Bb = stb + (2 + j) * TILE_B;
                uint32_t bfr[4][2];
#pragma unroll
                for (int p = 0; p < 2; p++) {
                    int g = lane >> 3, ri = lane & 7;
                    int row = wn + p * 16 + ((g >> 1) << 3) + ri;
                    uint32_t off = row * ROWB + (2 * ks + (g & 1)) * 16;
                    uint32_t t0, t1, t2, t3;
                    ldsm_x4(t0, t1, t2, t3, Bb + off);
                    bfr[p*2][0] = t0; bfr[p*2][1] = t1;
                    bfr[p*2+1][0] = t2; bfr[p*2+1][1] = t3;
                }
                if (j == 0) {
#pragma unroll
                    for (int mf = 0; mf < 4; mf++)
#pragma unroll
                        for (int nf = 0; nf < 4; nf++) {
                            mma_fp16(acc1[mf][nf], afr[0][mf], bfr[nf]);
                            mma_fp16(acc2[mf][nf], afr[1][mf], bfr[nf]);
                        }
                } else {
#pragma unroll
                    for (int mf = 0; mf < 4; mf++)
#pragma unroll
                        for (int nf = 0; nf < 4; nf++)
                            mma_fp16(acc2[mf][nf], afr[0][mf], bfr[nf]);
                }
            }
        }
    };

    load_stage(0, 0);
    for (int kc = 0; kc < nk; kc++) {
        if (kc + 1 < nk) { load_stage(kc + 1, (kc + 1) & 1); CP_WAIT(1); }
        else             { CP_WAIT(0); }
        __syncthreads();
        compute_stage(kc & 1);
        __syncthreads();
    }

    const float* bs = (const float*)smem;
    const float INV = 1.0f / 2048.0f;
    const int lr = lane >> 2;
    const int lc = (lane & 3) * 2;
#pragma unroll
    for (int mf = 0; mf < 4; mf++) {
#pragma unroll
        for (int nf = 0; nf < 4; nf++) {
            int nrel = wn + nf * 8 + lc;
            int n = n0 + nrel;
            float b0 = bs[nrel], b1 = bs[nrel + 1];
#pragma unroll
            for (int half = 0; half < 2; half++) {
                int m = m0 + wm + mf * 16 + lr + half * 8;
                float v0 = fmaxf(fmaf(acc2[mf][nf][half*2+0], INV, acc1[mf][nf][half*2+0]) + b0, 0.0f);
                float v1 = fmaxf(fmaf(acc2[mf][nf][half*2+1], INV, acc1[mf][nf][half*2+1]) + b1, 0.0f);
                if (OUTMODE == 0) {
                    if (n < Nvalid)
                        *(float2*)(Cf + (size_t)m * outStride + n) = make_float2(v0, v1);
                } else {
                    __half h0 = __float2half_rn(v0), h1 = __float2half_rn(v1);
                    __half2 hh = __halves2half2(h0, h1);
                    __half2 ll = __halves2half2(
                        __float2half_rn((v0 - __half2float(h0)) * 2048.0f),
                        __float2half_rn((v1 - __half2float(h1)) * 2048.0f));
                    *(__half2*)(H0 + (size_t)m * outStride + n) = hh;
                    *(__half2*)(H1 + (size_t)m * outStride + n) = ll;
                }
            }
        }
    }
}

// ===========================================================================
// L4 GEMM (bf16 2-part split — validated)
// ===========================================================================
__global__ __launch_bounds__(256, 1) void gemm_split2_f(
    const bf16* __restrict__ A0, const bf16* __restrict__ A1,
    const bf16* __restrict__ B0, const bf16* __restrict__ B1,
    const float* __restrict__ bias, float* __restrict__ Cf,
    int Kp, int Nvalid, int outStride)
{
    extern __shared__ char smem[];
    const uint32_t sbase = smem_u32(smem) + SM_TILES;
    const int tid  = threadIdx.x;
    const int warp = tid >> 5, lane = tid & 31;
    const int wm = (warp >> 2) * 64;
    const int wn = (warp & 3) * 32;
    const int m0 = blockIdx.y * 128;
    const int n0 = blockIdx.x * 128;

    if (tid < 128) {
        int n = n0 + tid;
        ((float*)smem)[tid] = (n < Nvalid) ? bias[n] : 0.0f;
    }

    float acc[4][4][4];
#pragma unroll
    for (int i = 0; i < 4; i++)
#pragma unroll
        for (int j = 0; j < 4; j++)
#pragma unroll
            for (int q = 0; q < 4; q++) acc[i][j][q] = 0.0f;

    const bf16* Ap[2] = { A0, A1 };
    const bf16* Bp[2] = { B0, B1 };
    const int nk = Kp / 32;

    auto load_stage = [&](int kc, int s) {
        const int k0 = kc * 32;
        const uint32_t stb = sbase + s * 4 * TILE_B;
#pragma unroll
        for (int t = 0; t < 4; t++) {
            const bf16* base = (t < 2) ? (Ap[t] + (size_t)m0 * Kp)
                                       : (Bp[t - 2] + (size_t)n0 * Kp);
#pragma unroll
            for (int i = 0; i < 2; i++) {
                int f = tid + i * 256;
                int row = f >> 2, c = f & 3;
                uint32_t dst = stb + t * TILE_B + row * ROWB + c * 16;
                CP_ASYNC16(dst, base + (size_t)row * Kp + k0 + c * 8);
            }
        }
        CP_COMMIT();
    };

    auto compute_stage = [&](int s) {
        const uint32_t stb = sbase + s * 4 * TILE_B;
#pragma unroll
        for (int ks = 0; ks < 2; ks++) {
            uint32_t afr[2][4][4];
#pragma unroll
            for (int p = 0; p < 2; p++) {
                const uint32_t Ab = stb + p * TILE_B;
#pragma unroll
                for (int mf = 0; mf < 4; mf++) {
                    int row = wm + mf * 16 + (lane & 15);
                    uint32_t off = row * ROWB + ks * 32 + (lane >> 4) * 16;
                    ldsm_x4(afr[p][mf][0], afr[p][mf][1], afr[p][mf][2], afr[p][mf][3], Ab + off);
                }
            }
#pragma unroll
            for (int j = 0; j < 2; j++) {
                const uint32_t Bb = stb + (2 + j) * TILE_B;
                uint32_t bfr[4][2];
#pragma unroll
                for (int p = 0; p < 2; p++) {
                    int g = lane >> 3, ri = lane & 7;
                    int row = wn + p * 16 + ((g >> 1) << 3) + ri;
                    uint32_t off = row * ROWB + (2 * ks + (g & 1)) * 16;
                    uint32_t t0, t1, t2, t3;
                    ldsm_x4(t0, t1, t2, t3, Bb + off);
                    bfr[p*2][0] = t0; bfr[p*2][1] = t1;
                    bfr[p*2+1][0] = t2; bfr[p*2+1][1] = t3;
                }
#pragma unroll
                for (int i = 0; i < 2 - j; i++)
#pragma unroll
                    for (int mf = 0; mf < 4; mf++)
#pragma unroll
                        for (int nf = 0; nf < 4; nf++)
                            mma_bf(acc[mf][nf], afr[i][mf], bfr[nf]);
            }
        }
    };

    load_stage(0, 0);
    for (int kc = 0; kc < nk; kc++) {
        if (kc + 1 < nk) { load_stage(kc + 1, (kc + 1) & 1); CP_WAIT(1); }
        else             { CP_WAIT(0); }
        __syncthreads();
        compute_stage(kc & 1);
        __syncthreads();
    }

    const float* bs = (const float*)smem;
    const int lr = lane >> 2;
    const int lc = (lane & 3) * 2;
#pragma unroll
    for (int mf = 0; mf < 4; mf++) {
#pragma unroll
        for (int nf = 0; nf < 4; nf++) {
            int nrel = wn + nf * 8 + lc;
            int n = n0 + nrel;
            float b0 = bs[nrel], b1 = bs[nrel + 1];
#pragma unroll
            for (int half = 0; half < 2; half++) {
                int m = m0 + wm + mf * 16 + lr + half * 8;
                float v0 = fmaxf(acc[mf][nf][half * 2 + 0] + b0, 0.0f);
                float v1 = fmaxf(acc[mf][nf][half * 2 + 1] + b1, 0.0f);
                if (n < Nvalid)
                    *(float2*)(Cf + (size_t)m * outStride + n) = make_float2(v0, v1);
            }
        }
    }
}

// ---------------------------------------------------------------------------
// prep kernels
// ---------------------------------------------------------------------------
__global__ __launch_bounds__(256) void split16_pad(
    const float* __restrict__ src, __half* __restrict__ H, __half* __restrict__ L,
    int srows, int scols, int orows, int ocols)
{
    size_t i = (size_t)blockIdx.x * blockDim.x + threadIdx.x;
    size_t tot = (size_t)orows * ocols;
    if (i >= tot) return;
    int r = (int)(i / ocols), c = (int)(i % ocols);
    float v = (r < srows && c < scols) ? src[(size_t)r * scols + c] : 0.0f;
    __half h = __float2half_rn(v);
    H[i] = h;
    L[i] = __float2half_rn((v - __half2float(h)) * 2048.0f);
}

__global__ __launch_bounds__(256) void split_pad2(
    const float* __restrict__ src, bf16* __restrict__ P0, bf16* __restrict__ P1,
    int srows, int scols, int orows, int ocols)
{
    size_t i = (size_t)blockIdx.x * blockDim.x + threadIdx.x;
    size_t tot = (size_t)orows * ocols;
    if (i >= tot) return;
    int r = (int)(i / ocols), c = (int)(i % ocols);
    float v = (r < srows && c < scols) ? src[(size_t)r * scols + c] : 0.0f;
    bf16 a = __float2bfloat16(v);
    P0[i] = a;
    P1[i] = __float2bfloat16(v - __bfloat162float(a));
}

__global__ void transpose_w3(const float* __restrict__ W3, float* __restrict__ W3T)
{
    __shared__ float t[32][33];
    int bx = blockIdx.x * 32;
    int by = blockIdx.y * 32;
    for (int i = threadIdx.y; i < 32; i += 8)
        t[i][threadIdx.x] = W3[(size_t)(by + i) * CODE + bx + threadIdx.x];
    __syncthreads();
    for (int i = threadIdx.y; i < 32; i += 8)
        W3T[(size_t)(bx + i) * INTER + by + threadIdx.x] = t[threadIdx.x][i];
}

// ---------------------------------------------------------------------------
// topk body — flags tight rows, emits compact (idx,val) lists (validated)
// ---------------------------------------------------------------------------
struct TopkSmem {
    unsigned int hist[256];
    unsigned int eqscan[256];
    float psum[256];
    float bmaxs[256];
    float ssum[NSTRIPE];
    float smask[NSTRIPE];
    unsigned int s_prefix, s_remk, s_total;
};

__device__ __forceinline__ void topk_body(
    TopkSmem& S, const float* __restrict__ C, int row, bool flagmode)
{
    const int tid = threadIdx.x;
    const float* crow = C + (size_t)row * CODE;

    float f[8];
    *(float4*)&f[0] = *(const float4*)(crow + tid * 8);
    *(float4*)&f[4] = *(const float4*)(crow + tid * 8 + 4);
    unsigned int u[8];
#pragma unroll
    for (int j = 0; j < 8; j++) u[j] = __float_as_uint(f[j]);

    if (tid == 0) { S.s_prefix = 0; S.s_remk = KNEUR; }
    __syncthreads();

#pragma unroll
    for (int pass = 0; pass < 4; pass++) {
        const int shift = 24 - pass * 8;
        const unsigned int pm = (pass == 0) ? 0u : (0xFFFFFFFFu << (shift + 8));
        S.hist[tid] = 0;
        __syncthreads();
        unsigned int pref = S.s_prefix;
#pragma unroll
        for (int j = 0; j < 8; j++)
            if ((u[j] & pm) == pref) atomicAdd(&S.hist[(u[j] >> shift) & 0xFF], 1u);
        __syncthreads();
        if (tid == 0) {
            unsigned int remk = S.s_remk, acc = 0;
            int b = 255;
            for (; b > 0; b--) { acc += S.hist[b]; if (acc >= remk) break; }
            if (acc < remk) acc += S.hist[0];
            S.s_prefix = pref | ((unsigned int)b << shift);
            S.s_remk = remk - (acc - S.hist[b]);
        }
        __syncthreads();
    }

    const unsigned int t = S.s_prefix;
    const unsigned int need_eq = S.s_remk;

    unsigned int cnt = 0;
    float bmax = 0.0f;
#pragma unroll
    for (int j = 0; j < 8; j++) {
        cnt += (u[j] == t);
        if (u[j] < t) bmax = fmaxf(bmax, f[j]);
    }
    S.eqscan[tid] = cnt;
    S.bmaxs[tid] = bmax;
    __syncthreads();
    if (tid == 0) {
        unsigned int run = 0;
        for (int i = 0; i < 256; i++) { unsigned int v = S.eqscan[i]; S.eqscan[i] = run; run += v; }
        S.s_total = run;
    }
#pragma unroll
    for (int off = 128; off > 0; off >>= 1) {
        __syncthreads();
        if (tid < off) S.bmaxs[tid] = fmaxf(S.bmaxs[tid], S.bmaxs[tid + off]);
    }
    __syncthreads();

    unsigned int rank = S.eqscan[tid];
    float part = 0.0f;
#pragma unroll
    for (int j = 0; j < 8; j++) {
        bool keep;
        if (u[j] > t) keep = true;
        else if (u[j] == t) { keep = (rank < need_eq); rank++; }
        else keep = false;
        if (!keep) f[j] = 0.0f;
        part += f[j];
    }
    S.psum[tid] = part;
    __syncthreads();

    if (tid < NSTRIPE) {
        float s = 0.0f;
#pragma unroll
        for (int i = 0; i < 8; i++) s += S.psum[tid * 8 + i];
        S.ssum[tid] = s;
    }
    __syncthreads();

    if (tid == 0) {
        bool sel[NSTRIPE];
#pragma unroll
        for (int s = 0; s < NSTRIPE; s++) sel[s] = false;
        float v4 = 0.0f, v5 = 0.0f;
        for (int it = 0; it < KSTRIPE + 1; it++) {
            int best = -1; float bv = -1.0f;
            for (int s = 0; s < NSTRIPE; s++)
                if (!sel[s] && S.ssum[s] > bv) { bv = S.ssum[s]; best = s; }
            if (it < KSTRIPE) { sel[best] = true; if (it == KSTRIPE - 1) v4 = bv; }
            else v5 = bv;
        }
#pragma unroll
        for (int s = 0; s < NSTRIPE; s++) S.smask[s] = sel[s] ? 1.0f : 0.0f;

        if (flagmode) {
            float gap_n = __uint_as_float(t) - S.bmaxs[0];
            if (need_eq < S.s_total) gap_n = 0.0f;
            float gap_s = v4 - v5;
            if (gap_n < TAU1 || gap_s < TAU2) {
                int ix = atomicAdd(&g_flag_cnt, 1);
                g_flag_rows[ix] = row;
            }
        }
    }
    __syncthreads();

    const float sm = S.smask[tid >> 3];
    float mv[8];
    unsigned int myc = 0;
#pragma unroll
    for (int j = 0; j < 8; j++) { mv[j] = f[j] * sm; myc += (mv[j] != 0.0f); }
    S.eqscan[tid] = myc;
    __syncthreads();
    if (tid == 0) {
        unsigned int run = 0;
        for (int i = 0; i < 256; i++) { unsigned int v = S.eqscan[i]; S.eqscan[i] = run; run += v; }
        g_cnt[row] = (int)run;
    }
    __syncthreads();
    int base = (int)S.eqscan[tid];
    const int gb = row * KNEUR;
#pragma unroll
    for (int j = 0; j < 8; j++) {
        if (mv[j] != 0.0f) {
            g_idx[gb + base] = tid * 8 + j;
            g_val[gb + base] = mv[j];
            base++;
        }
    }
}

__global__ __launch_bounds__(256) void topk_flag_kernel(const float* __restrict__ C)
{
    __shared__ TopkSmem S;
    topk_body(S, C, blockIdx.x, true);
}

__global__ __launch_bounds__(256) void reset_cnt_kernel()
{
    if (threadIdx.x == 0 && blockIdx.x == 0) g_flag_cnt = 0;
}

// ---------------------------------------------------------------------------
// h_fix: exact fp32 h rows for flagged slots. Warp-per-output GEMV:
// lanes stride k (coalesced W1 reads) + shfl reduce.
// ---------------------------------------------------------------------------
__global__ __launch_bounds__(256) void h_fix_kernel(
    const float* __restrict__ x, const float* __restrict__ W1,
    const float* __restrict__ b1)
{
    __shared__ float xs[IN_DIM];
    const int tid = threadIdx.x;
    const int lane = tid & 31, warp = tid >> 5;
    const int nf = g_flag_cnt;
    for (int slot = blockIdx.x; slot < nf; slot += gridDim.x) {
        const int row = g_flag_rows[slot];
        __syncthreads();
        for (int k = tid; k < IN_DIM; k += 256)
            xs[k] = x[(size_t)row * IN_DIM + k];
        __syncthreads();
        // 8 warps x 128 outputs each
        for (int jj = 0; jj < 128; jj++) {
            int j = warp * 128 + jj;
            const float* w = W1 + (size_t)j * IN_DIM;
            float acc = 0.0f;
            for (int k = lane; k < IN_DIM; k += 32)
                acc = fmaf(xs[k], w[k], acc);
#pragma unroll
            for (int o = 16; o > 0; o >>= 1)
                acc += __shfl_xor_sync(0xFFFFFFFFu, acc, o);
            if (lane == 0)
                g_hfix[(size_t)slot * INTER + j] = fmaxf(acc + b1[j], 0.0f);
        }
    }
}

// ---------------------------------------------------------------------------
// c_fix: exact fp32 c for flagged slots. Tasks = (slot, j-chunk of 256).
// Warp-per-output with coalesced W2 reads.
// ---------------------------------------------------------------------------
__global__ __launch_bounds__(256) void fixup_exact_kernel(
    const float* __restrict__ W2, const float* __restrict__ b2, float* __restrict__ c)
{
    __shared__ float hs[INTER];
    const int tid = threadIdx.x;
    const int lane = tid & 31, warp = tid >> 5;
    const int nf = g_flag_cnt;
    const int ntask = nf * 8;     // CODE / 256 = 8 chunks
    for (int task = blockIdx.x; task < ntask; task += gridDim.x) {
        const int slot = task >> 3, chunk = task & 7;
        const int row = g_flag_rows[slot];
        __syncthreads();
        for (int k = tid; k < INTER; k += 256)
            hs[k] = g_hfix[(size_t)slot * INTER + k];
        __syncthreads();
        // 8 warps x 32 outputs each = 256 outputs
        for (int jj = 0; jj < 32; jj++) {
            int j = chunk * 256 + warp * 32 + jj;
            const float* w = W2 + (size_t)j * INTER;
            float acc = 0.0f;
#pragma unroll 4
            for (int k = lane; k < INTER; k += 32)
                acc = fmaf(hs[k], w[k], acc);
#pragma unroll
            for (int o = 16; o > 0; o >>= 1)
                acc += __shfl_xor_sync(0xFFFFFFFFu, acc, o);
            if (lane == 0)
                c[(size_t)row * CODE + j] = fmaxf(acc + b2[j], 0.0f);
        }
    }
}

__global__ __launch_bounds__(256) void fixup_topk_kernel(const float* __restrict__ C)
{
    __shared__ TopkSmem S;
    const int nf = g_flag_cnt;
    for (int i = blockIdx.x; i < nf; i += gridDim.x) {
        topk_body(S, C, g_flag_rows[i], false);
        __syncthreads();
    }
}

// ---------------------------------------------------------------------------
// L3: sparse row-gather GEMV fp32 -> d bf16 pair (validated R9)
// ---------------------------------------------------------------------------
__global__ __launch_bounds__(256) void l3_gather(
    const float* __restrict__ W3T, const float* __restrict__ b3,
    bf16* __restrict__ D0, bf16* __restrict__ D1)
{
    __shared__ float sval[KNEUR];
    __shared__ int   sidx[KNEUR];
    const int row = blockIdx.x, tid = threadIdx.x;
    const int cnt = g_cnt[row];
    if (tid < KNEUR && tid < cnt) {
        sidx[tid] = g_idx[row * KNEUR + tid];
        sval[tid] = g_val[row * KNEUR + tid];
    }
    __syncthreads();

    const int n = tid * 4;
    float4 acc = *(const float4*)(b3 + n);
    int j = 0;
    for (; j + 4 <= cnt; j += 4) {
        const float4 w0 = *(const float4*)(W3T + (size_t)sidx[j + 0] * INTER + n);
        const float4 w1 = *(const float4*)(W3T + (size_t)sidx[j + 1] * INTER + n);
        const float4 w2 = *(const float4*)(W3T + (size_t)sidx[j + 2] * INTER + n);
        const float4 w3 = *(const float4*)(W3T + (size_t)sidx[j + 3] * INTER + n);
        const float v0 = sval[j], v1 = sval[j + 1], v2 = sval[j + 2], v3 = sval[j + 3];
        acc.x = fmaf(v0, w0.x, acc.x); acc.y = fmaf(v0, w0.y, acc.y);
        acc.z = fmaf(v0, w0.z, acc.z); acc.w = fmaf(v0, w0.w, acc.w);
        acc.x = fmaf(v1, w1.x, acc.x); acc.y = fmaf(v1, w1.y, acc.y);
        acc.z = fmaf(v1, w1.z, acc.z); acc.w = fmaf(v1, w1.w, acc.w);
        acc.x = fmaf(v2, w2.x, acc.x); acc.y = fmaf(v2, w2.y, acc.y);
        acc.z = fmaf(v2, w2.z, acc.z); acc.w = fmaf(v2, w2.w, acc.w);
        acc.x = fmaf(v3, w3.x, acc.x); acc.y = fmaf(v3, w3.y, acc.y);
        acc.z = fmaf(v3, w3.z, acc.z); acc.w = fmaf(v3, w3.w, acc.w);
    }
    for (; j < cnt; j++) {
        const float4 w0 = *(const float4*)(W3T + (size_t)sidx[j] * INTER + n);
        const float v0 = sval[j];
        acc.x = fmaf(v0, w0.x, acc.x); acc.y = fmaf(v0, w0.y, acc.y);
        acc.z = fmaf(v0, w0.z, acc.z); acc.w = fmaf(v0, w0.w, acc.w);
    }

    acc.x = fmaxf(acc.x, 0.0f); acc.y = fmaxf(acc.y, 0.0f);
    acc.z = fmaxf(acc.z, 0.0f); acc.w = fmaxf(acc.w, 0.0f);

    __nv_bfloat162 p0a, p0b, p1a, p1b;
    p0a.x = __float2bfloat16(acc.x); p0a.y = __float2bfloat16(acc.y);
    p0b.x = __float2bfloat16(acc.z); p0b.y = __float2bfloat16(acc.w);
    p1a.x = __float2bfloat16(acc.x - __bfloat162float(p0a.x));
    p1a.y = __float2bfloat16(acc.y - __bfloat162float(p0a.y));
    p1b.x = __float2bfloat16(acc.z - __bfloat162float(p0b.x));
    p1b.y = __float2bfloat16(acc.w - __bfloat162float(p0b.y));
    *(__nv_bfloat162*)(D0 + (size_t)row * INTER + n)     = p0a;
    *(__nv_bfloat162*)(D0 + (size_t)row * INTER + n + 2) = p0b;
    *(__nv_bfloat162*)(D1 + (size_t)row * INTER + n)     = p1a;
    *(__nv_bfloat162*)(D1 + (size_t)row * INTER + n + 2) = p1b;
}

// ---------------------------------------------------------------------------
extern "C" void kernel_launch(void* const* d_in, const int* in_sizes, int n_in,
                              void* d_out, int out_size)
{
    const float* x  = (const float*)d_in[0];
    const float* W1 = (const float*)d_in[1];
    const float* b1 = (const float*)d_in[2];
    const float* W2 = (const float*)d_in[3];
    const float* b2 = (const float*)d_in[4];
    const float* W3 = (const float*)d_in[5];
    const float* b3 = (const float*)d_in[6];
    const float* W4 = (const float*)d_in[7];
    const float* b4 = (const float*)d_in[8];
    float* out = (float*)d_out;

    float *c, *w3t;
    __half *x0, *x1, *w1h, *w1l, *hh16, *hl16, *w2h16, *w2l16;
    bf16 *d0, *d1, *w40, *w41;
    cudaGetSymbolAddress((void**)&c, g_c);
    cudaGetSymbolAddress((void**)&w3t, g_w3t);
    cudaGetSymbolAddress((void**)&x0, g_x0);       cudaGetSymbolAddress((void**)&x1, g_x1);
    cudaGetSymbolAddress((void**)&w1h, g_w1h);     cudaGetSymbolAddress((void**)&w1l, g_w1l);
    cudaGetSymbolAddress((void**)&hh16, g_hh16);   cudaGetSymbolAddress((void**)&hl16, g_hl16);
    cudaGetSymbolAddress((void**)&w2h16, g_w2h16); cudaGetSymbolAddress((void**)&w2l16, g_w2l16);
    cudaGetSymbolAddress((void**)&d0, g_d0);       cudaGetSymbolAddress((void**)&d1, g_d1);
    cudaGetSymbolAddress((void**)&w40, g_w4_0);    cudaGetSymbolAddress((void**)&w41, g_w4_1);

    cudaFuncSetAttribute(gemm_f16<0>, cudaFuncAttributeMaxDynamicSharedMemorySize, SMEM_HMMA);
    cudaFuncSetAttribute(gemm_f16<1>, cudaFuncAttributeMaxDynamicSharedMemorySize, SMEM_HMMA);
    cudaFuncSetAttribute(gemm_split2_f, cudaFuncAttributeMaxDynamicSharedMemorySize, SMEM_HMMA);

    auto gs = [](size_t n) { return (unsigned)((n + 255) / 256); };

    // prep: splits + transpose
    split16_pad<<<gs((size_t)BATCH * K1P), 256>>>(x,  x0,  x1,  BATCH, IN_DIM, BATCH, K1P);
    split16_pad<<<gs((size_t)INTER * K1P), 256>>>(W1, w1h, w1l, INTER, IN_DIM, INTER, K1P);
    split16_pad<<<gs((size_t)CODE * INTER), 256>>>(W2, w2h16, w2l16, CODE, INTER, CODE, INTER);
    split_pad2<<<gs((size_t)N4P * INTER), 256>>>(W4, w40, w41, IN_DIM, INTER, N4P, INTER);
    transpose_w3<<<dim3(CODE / 32, INTER / 32), dim3(32, 8)>>>(W3, w3t);

    // L1: fp16-split HMMA -> h pair direct
    gemm_f16<1><<<dim3(INTER / 128, BATCH / 128), 256, SMEM_HMMA>>>(
        x0, x1, w1h, w1l, b1, nullptr, hh16, hl16, K1P, INTER, INTER);

    // L2: fp16-split HMMA -> c fp32
    gemm_f16<0><<<dim3(CODE / 128, BATCH / 128), 256, SMEM_HMMA>>>(
        hh16, hl16, w2h16, w2l16, b2, c, nullptr, nullptr, INTER, CODE, CODE);

    // topk with margins; flagged rows: exact fp32 chain (fast warp-GEMV)
    reset_cnt_kernel<<<1, 32>>>();
    topk_flag_kernel<<<BATCH, 256>>>(c);
    h_fix_kernel<<<1024, 256>>>(x, W1, b1);
    fixup_exact_kernel<<<4096, 256>>>(W2, b2, c);
    fixup_topk_kernel<<<1024, 256>>>(c);

    // L3 sparse gather -> d pair
    l3_gather<<<BATCH, 256>>>(w3t, b3, d0, d1);

    // L4 HMMA split -> out
    gemm_split2_f<<<dim3(N4P / 128, BATCH / 128), 256, SMEM_HMMA>>>(
        d0, d1, w40, w41, b4, out, INTER, IN_DIM, IN_DIM);
}

// round 13
// speedup vs baseline: 2.0957x; 1.1560x over previous
#include <cuda_runtime.h>
#include <cuda_bf16.h>
#include <cuda_fp16.h>
#include <cstdint>

// ---------------------------------------------------------------------------
// Net_46368466928157 — round 13:
//   Same structure as R12; h_fix / c_fix rebuilt as BATCHED GEMVs
//   (16 flagged rows share each weight read; warp computes 4 outputs).
// ---------------------------------------------------------------------------

#define BATCH   16384
#define IN_DIM  784
#define K1P     800
#define INTER   1024
#define CODE    2048
#define N4P     896
#define NSTRIPE 32
#define KNEUR   64
#define KSTRIPE 4

#define TAU1 2.5e-5f
#define TAU2 2e-3f

typedef __nv_bfloat16 bf16;

// ---- scratch --------------------------------------------------------------
__device__ __half g_x0[(size_t)BATCH * K1P],  g_x1[(size_t)BATCH * K1P];
__device__ __half g_w1h[(size_t)INTER * K1P], g_w1l[(size_t)INTER * K1P];
__device__ __half g_hh16[(size_t)BATCH * INTER], g_hl16[(size_t)BATCH * INTER];
__device__ __half g_w2h16[(size_t)CODE * INTER], g_w2l16[(size_t)CODE * INTER];
__device__ float  g_c[(size_t)BATCH * CODE];
__device__ float  g_w3t[(size_t)CODE * INTER];
__device__ bf16   g_d0[(size_t)BATCH * INTER],  g_d1[(size_t)BATCH * INTER];
__device__ bf16   g_w4_0[(size_t)N4P * INTER],  g_w4_1[(size_t)N4P * INTER];
__device__ int    g_flag_cnt;
__device__ int    g_flag_rows[BATCH];
__device__ float  g_hfix[(size_t)BATCH * INTER];
__device__ int    g_cnt[BATCH];
__device__ int    g_idx[(size_t)BATCH * KNEUR];
__device__ float  g_val[(size_t)BATCH * KNEUR];

// ===========================================================================
// PTX helpers
// ===========================================================================
__device__ __forceinline__ uint32_t smem_u32(const void* p) {
    uint32_t a;
    asm("{ .reg .u64 t; cvta.to.shared.u64 t, %1; cvt.u32.u64 %0, t; }" : "=r"(a) : "l"(p));
    return a;
}
#define CP_ASYNC16(dst, src) \
    asm volatile("cp.async.cg.shared.global [%0], [%1], 16;" :: "r"(dst), "l"(src) : "memory")
#define CP_COMMIT()  asm volatile("cp.async.commit_group;" ::: "memory")
#define CP_WAIT(n)   asm volatile("cp.async.wait_group %0;" :: "n"(n) : "memory")

__device__ __forceinline__ void ldsm_x4(uint32_t& r0, uint32_t& r1, uint32_t& r2,
                                        uint32_t& r3, uint32_t addr) {
    asm volatile("ldmatrix.sync.aligned.m8n8.x4.shared.b16 {%0,%1,%2,%3}, [%4];"
        : "=r"(r0), "=r"(r1), "=r"(r2), "=r"(r3) : "r"(addr));
}
__device__ __forceinline__ void mma_bf(float* c, const uint32_t* a, const uint32_t* b) {
    asm volatile("mma.sync.aligned.m16n8k16.row.col.f32.bf16.bf16.f32 "
        "{%0,%1,%2,%3}, {%4,%5,%6,%7}, {%8,%9}, {%0,%1,%2,%3};"
        : "+f"(c[0]), "+f"(c[1]), "+f"(c[2]), "+f"(c[3])
        : "r"(a[0]), "r"(a[1]), "r"(a[2]), "r"(a[3]), "r"(b[0]), "r"(b[1]));
}
__device__ __forceinline__ void mma_fp16(float* c, const uint32_t* a, const uint32_t* b) {
    asm volatile("mma.sync.aligned.m16n8k16.row.col.f32.f16.f16.f32 "
        "{%0,%1,%2,%3}, {%4,%5,%6,%7}, {%8,%9}, {%0,%1,%2,%3};"
        : "+f"(c[0]), "+f"(c[1]), "+f"(c[2]), "+f"(c[3])
        : "r"(a[0]), "r"(a[1]), "r"(a[2]), "r"(a[3]), "r"(b[0]), "r"(b[1]));
}

#define ROWB   80
#define TILE_B (128 * ROWB)
#define SM_TILES 1024
#define SMEM_HMMA (SM_TILES + 2 * 4 * TILE_B)

// ===========================================================================
// fp16 scaled-split GEMM (validated): C = relu(bias + A@B^T).
// OUTMODE 0: fp32 out. OUTMODE 1: fp16 pair out.
// ===========================================================================
template<int OUTMODE>
__global__ __launch_bounds__(256, 1) void gemm_f16(
    const __half* __restrict__ A0, const __half* __restrict__ A1,
    const __half* __restrict__ B0, const __half* __restrict__ B1,
    const float* __restrict__ bias, float* __restrict__ Cf,
    __half* __restrict__ H0, __half* __restrict__ H1,
    int Kp, int Nvalid, int outStride)
{
    extern __shared__ char smem[];
    const uint32_t sbase = smem_u32(smem) + SM_TILES;
    const int tid  = threadIdx.x;
    const int warp = tid >> 5, lane = tid & 31;
    const int wm = (warp >> 2) * 64;
    const int wn = (warp & 3) * 32;
    const int m0 = blockIdx.y * 128;
    const int n0 = blockIdx.x * 128;

    if (tid < 128) {
        int n = n0 + tid;
        ((float*)smem)[tid] = (n < Nvalid) ? bias[n] : 0.0f;
    }

    float acc1[4][4][4], acc2[4][4][4];
#pragma unroll
    for (int i = 0; i < 4; i++)
#pragma unroll
        for (int j = 0; j < 4; j++)
#pragma unroll
            for (int q = 0; q < 4; q++) { acc1[i][j][q] = 0.0f; acc2[i][j][q] = 0.0f; }

    const __half* Ap[2] = { A0, A1 };
    const __half* Bp[2] = { B0, B1 };
    const int nk = Kp / 32;

    auto load_stage = [&](int kc, int s) {
        const int k0 = kc * 32;
        const uint32_t stb = sbase + s * 4 * TILE_B;
#pragma unroll
        for (int t = 0; t < 4; t++) {
            const __half* base = (t < 2) ? (Ap[t] + (size_t)m0 * Kp)
                                         : (Bp[t - 2] + (size_t)n0 * Kp);
#pragma unroll
            for (int i = 0; i < 2; i++) {
                int f = tid + i * 256;
                int row = f >> 2, c = f & 3;
                uint32_t dst = stb + t * TILE_B + row * ROWB + c * 16;
                CP_ASYNC16(dst, base + (size_t)row * Kp + k0 + c * 8);
            }
        }
        CP_COMMIT();
    };

    auto compute_stage = [&](int s) {
        const uint32_t stb = sbase + s * 4 * TILE_B;
#pragma unroll
        for (int ks = 0; ks < 2; ks++) {
            uint32_t afr[2][4][4];
#pragma unroll
            for (int p = 0; p < 2; p++) {
                const uint32_t Ab = stb + p * TILE_B;
#pragma unroll
                for (int mf = 0; mf < 4; mf++) {
                    int row = wm + mf * 16 + (lane & 15);
                    uint32_t off = row * ROWB + ks * 32 + (lane >> 4) * 16;
                    ldsm_x4(afr[p][mf][0], afr[p][mf][1], afr[p][mf][2], afr[p][mf][3], Ab + off);
                }
            }
#pragma unroll
            for (int j = 0; j < 2; j++) {
                const uint32_t Bb = stb + (2 + j) * TILE_B;
                uint32_t bfr[4][2];
#pragma unroll
                for (int p = 0; p < 2; p++) {
                    int g = lane >> 3, ri = lane & 7;
                    int row = wn + p * 16 + ((g >> 1) << 3) + ri;
                    uint32_t off = row * ROWB + (2 * ks + (g & 1)) * 16;
                    uint32_t t0, t1, t2, t3;
                    ldsm_x4(t0, t1, t2, t3, Bb + off);
                    bfr[p*2][0] = t0; bfr[p*2][1] = t1;
                    bfr[p*2+1][0] = t2; bfr[p*2+1][1] = t3;
                }
                if (j == 0) {
#pragma unroll
                    for (int mf = 0; mf < 4; mf++)
#pragma unroll
                        for (int nf = 0; nf < 4; nf++) {
                            mma_fp16(acc1[mf][nf], afr[0][mf], bfr[nf]);
                            mma_fp16(acc2[mf][nf], afr[1][mf], bfr[nf]);
                        }
                } else {
#pragma unroll
                    for (int mf = 0; mf < 4; mf++)
#pragma unroll
                        for (int nf = 0; nf < 4; nf++)
                            mma_fp16(acc2[mf][nf], afr[0][mf], bfr[nf]);
                }
            }
        }
    };

    load_stage(0, 0);
    for (int kc = 0; kc < nk; kc++) {
        if (kc + 1 < nk) { load_stage(kc + 1, (kc + 1) & 1); CP_WAIT(1); }
        else             { CP_WAIT(0); }
        __syncthreads();
        compute_stage(kc & 1);
        __syncthreads();
    }

    const float* bs = (const float*)smem;
    const float INV = 1.0f / 2048.0f;
    const int lr = lane >> 2;
    const int lc = (lane & 3) * 2;
#pragma unroll
    for (int mf = 0; mf < 4; mf++) {
#pragma unroll
        for (int nf = 0; nf < 4; nf++) {
            int nrel = wn + nf * 8 + lc;
            int n = n0 + nrel;
            float b0 = bs[nrel], b1 = bs[nrel + 1];
#pragma unroll
            for (int half = 0; half < 2; half++) {
                int m = m0 + wm + mf * 16 + lr + half * 8;
                float v0 = fmaxf(fmaf(acc2[mf][nf][half*2+0], INV, acc1[mf][nf][half*2+0]) + b0, 0.0f);
                float v1 = fmaxf(fmaf(acc2[mf][nf][half*2+1], INV, acc1[mf][nf][half*2+1]) + b1, 0.0f);
                if (OUTMODE == 0) {
                    if (n < Nvalid)
                        *(float2*)(Cf + (size_t)m * outStride + n) = make_float2(v0, v1);
                } else {
                    __half h0 = __float2half_rn(v0), h1 = __float2half_rn(v1);
                    __half2 hh = __halves2half2(h0, h1);
                    __half2 ll = __halves2half2(
                        __float2half_rn((v0 - __half2float(h0)) * 2048.0f),
                        __float2half_rn((v1 - __half2float(h1)) * 2048.0f));
                    *(__half2*)(H0 + (size_t)m * outStride + n) = hh;
                    *(__half2*)(H1 + (size_t)m * outStride + n) = ll;
                }
            }
        }
    }
}

// ===========================================================================
// L4 GEMM (bf16 2-part split — validated)
// ===========================================================================
__global__ __launch_bounds__(256, 1) void gemm_split2_f(
    const bf16* __restrict__ A0, const bf16* __restrict__ A1,
    const bf16* __restrict__ B0, const bf16* __restrict__ B1,
    const float* __restrict__ bias, float* __restrict__ Cf,
    int Kp, int Nvalid, int outStride)
{
    extern __shared__ char smem[];
    const uint32_t sbase = smem_u32(smem) + SM_TILES;
    const int tid  = threadIdx.x;
    const int warp = tid >> 5, lane = tid & 31;
    const int wm = (warp >> 2) * 64;
    const int wn = (warp & 3) * 32;
    const int m0 = blockIdx.y * 128;
    const int n0 = blockIdx.x * 128;

    if (tid < 128) {
        int n = n0 + tid;
        ((float*)smem)[tid] = (n < Nvalid) ? bias[n] : 0.0f;
    }

    float acc[4][4][4];
#pragma unroll
    for (int i = 0; i < 4; i++)
#pragma unroll
        for (int j = 0; j < 4; j++)
#pragma unroll
            for (int q = 0; q < 4; q++) acc[i][j][q] = 0.0f;

    const bf16* Ap[2] = { A0, A1 };
    const bf16* Bp[2] = { B0, B1 };
    const int nk = Kp / 32;

    auto load_stage = [&](int kc, int s) {
        const int k0 = kc * 32;
        const uint32_t stb = sbase + s * 4 * TILE_B;
#pragma unroll
        for (int t = 0; t < 4; t++) {
            const bf16* base = (t < 2) ? (Ap[t] + (size_t)m0 * Kp)
                                       : (Bp[t - 2] + (size_t)n0 * Kp);
#pragma unroll
            for (int i = 0; i < 2; i++) {
                int f = tid + i * 256;
                int row = f >> 2, c = f & 3;
                uint32_t dst = stb + t * TILE_B + row * ROWB + c * 16;
                CP_ASYNC16(dst, base + (size_t)row * Kp + k0 + c * 8);
            }
        }
        CP_COMMIT();
    };

    auto compute_stage = [&](int s) {
        const uint32_t stb = sbase + s * 4 * TILE_B;
#pragma unroll
        for (int ks = 0; ks < 2; ks++) {
            uint32_t afr[2][4][4];
#pragma unroll
            for (int p = 0; p < 2; p++) {
                const uint32_t Ab = stb + p * TILE_B;
#pragma unroll
                for (int mf = 0; mf < 4; mf++) {
                    int row = wm + mf * 16 + (lane & 15);
                    uint32_t off = row * ROWB + ks * 32 + (lane >> 4) * 16;
                    ldsm_x4(afr[p][mf][0], afr[p][mf][1], afr[p][mf][2], afr[p][mf][3], Ab + off);
                }
            }
#pragma unroll
            for (int j = 0; j < 2; j++) {
                const uint32_t Bb = stb + (2 + j) * TILE_B;
                uint32_t bfr[4][2];
#pragma unroll
                for (int p = 0; p < 2; p++) {
                    int g = lane >> 3, ri = lane & 7;
                    int row = wn + p * 16 + ((g >> 1) << 3) + ri;
                    uint32_t off = row * ROWB + (2 * ks + (g & 1)) * 16;
                    uint32_t t0, t1, t2, t3;
                    ldsm_x4(t0, t1, t2, t3, Bb + off);
                    bfr[p*2][0] = t0; bfr[p*2][1] = t1;
                    bfr[p*2+1][0] = t2; bfr[p*2+1][1] = t3;
                }
#pragma unroll
                for (int i = 0; i < 2 - j; i++)
#pragma unroll
                    for (int mf = 0; mf < 4; mf++)
#pragma unroll
                        for (int nf = 0; nf < 4; nf++)
                            mma_bf(acc[mf][nf], afr[i][mf], bfr[nf]);
            }
        }
    };

    load_stage(0, 0);
    for (int kc = 0; kc < nk; kc++) {
        if (kc + 1 < nk) { load_stage(kc + 1, (kc + 1) & 1); CP_WAIT(1); }
        else             { CP_WAIT(0); }
        __syncthreads();
        compute_stage(kc & 1);
        __syncthreads();
    }

    const float* bs = (const float*)smem;
    const int lr = lane >> 2;
    const int lc = (lane & 3) * 2;
#pragma unroll
    for (int mf = 0; mf < 4; mf++) {
#pragma unroll
        for (int nf = 0; nf < 4; nf++) {
            int nrel = wn + nf * 8 + lc;
            int n = n0 + nrel;
            float b0 = bs[nrel], b1 = bs[nrel + 1];
#pragma unroll
            for (int half = 0; half < 2; half++) {
                int m = m0 + wm + mf * 16 + lr + half * 8;
                float v0 = fmaxf(acc[mf][nf][half * 2 + 0] + b0, 0.0f);
                float v1 = fmaxf(acc[mf][nf][half * 2 + 1] + b1, 0.0f);
                if (n < Nvalid)
                    *(float2*)(Cf + (size_t)m * outStride + n) = make_float2(v0, v1);
            }
        }
    }
}

// ---------------------------------------------------------------------------
// prep kernels
// ---------------------------------------------------------------------------
__global__ __launch_bounds__(256) void split16_pad(
    const float* __restrict__ src, __half* __restrict__ H, __half* __restrict__ L,
    int srows, int scols, int orows, int ocols)
{
    size_t i = (size_t)blockIdx.x * blockDim.x + threadIdx.x;
    size_t tot = (size_t)orows * ocols;
    if (i >= tot) return;
    int r = (int)(i / ocols), c = (int)(i % ocols);
    float v = (r < srows && c < scols) ? src[(size_t)r * scols + c] : 0.0f;
    __half h = __float2half_rn(v);
    H[i] = h;
    L[i] = __float2half_rn((v - __half2float(h)) * 2048.0f);
}

__global__ __launch_bounds__(256) void split_pad2(
    const float* __restrict__ src, bf16* __restrict__ P0, bf16* __restrict__ P1,
    int srows, int scols, int orows, int ocols)
{
    size_t i = (size_t)blockIdx.x * blockDim.x + threadIdx.x;
    size_t tot = (size_t)orows * ocols;
    if (i >= tot) return;
    int r = (int)(i / ocols), c = (int)(i % ocols);
    float v = (r < srows && c < scols) ? src[(size_t)r * scols + c] : 0.0f;
    bf16 a = __float2bfloat16(v);
    P0[i] = a;
    P1[i] = __float2bfloat16(v - __bfloat162float(a));
}

__global__ void transpose_w3(const float* __restrict__ W3, float* __restrict__ W3T)
{
    __shared__ float t[32][33];
    int bx = blockIdx.x * 32;
    int by = blockIdx.y * 32;
    for (int i = threadIdx.y; i < 32; i += 8)
        t[i][threadIdx.x] = W3[(size_t)(by + i) * CODE + bx + threadIdx.x];
    __syncthreads();
    for (int i = threadIdx.y; i < 32; i += 8)
        W3T[(size_t)(bx + i) * INTER + by + threadIdx.x] = t[threadIdx.x][i];
}

// ---------------------------------------------------------------------------
// topk body — flags tight rows, emits compact (idx,val) lists (validated)
// ---------------------------------------------------------------------------
struct TopkSmem {
    unsigned int hist[256];
    unsigned int eqscan[256];
    float psum[256];
    float bmaxs[256];
    float ssum[NSTRIPE];
    float smask[NSTRIPE];
    unsigned int s_prefix, s_remk, s_total;
};

__device__ __forceinline__ void topk_body(
    TopkSmem& S, const float* __restrict__ C, int row, bool flagmode)
{
    const int tid = threadIdx.x;
    const float* crow = C + (size_t)row * CODE;

    float f[8];
    *(float4*)&f[0] = *(const float4*)(crow + tid * 8);
    *(float4*)&f[4] = *(const float4*)(crow + tid * 8 + 4);
    unsigned int u[8];
#pragma unroll
    for (int j = 0; j < 8; j++) u[j] = __float_as_uint(f[j]);

    if (tid == 0) { S.s_prefix = 0; S.s_remk = KNEUR; }
    __syncthreads();

#pragma unroll
    for (int pass = 0; pass < 4; pass++) {
        const int shift = 24 - pass * 8;
        const unsigned int pm = (pass == 0) ? 0u : (0xFFFFFFFFu << (shift + 8));
        S.hist[tid] = 0;
        __syncthreads();
        unsigned int pref = S.s_prefix;
#pragma unroll
        for (int j = 0; j < 8; j++)
            if ((u[j] & pm) == pref) atomicAdd(&S.hist[(u[j] >> shift) & 0xFF], 1u);
        __syncthreads();
        if (tid == 0) {
            unsigned int remk = S.s_remk, acc = 0;
            int b = 255;
            for (; b > 0; b--) { acc += S.hist[b]; if (acc >= remk) break; }
            if (acc < remk) acc += S.hist[0];
            S.s_prefix = pref | ((unsigned int)b << shift);
            S.s_remk = remk - (acc - S.hist[b]);
        }
        __syncthreads();
    }

    const unsigned int t = S.s_prefix;
    const unsigned int need_eq = S.s_remk;

    unsigned int cnt = 0;
    float bmax = 0.0f;
#pragma unroll
    for (int j = 0; j < 8; j++) {
        cnt += (u[j] == t);
        if (u[j] < t) bmax = fmaxf(bmax, f[j]);
    }
    S.eqscan[tid] = cnt;
    S.bmaxs[tid] = bmax;
    __syncthreads();
    if (tid == 0) {
        unsigned int run = 0;
        for (int i = 0; i < 256; i++) { unsigned int v = S.eqscan[i]; S.eqscan[i] = run; run += v; }
        S.s_total = run;
    }
#pragma unroll
    for (int off = 128; off > 0; off >>= 1) {
        __syncthreads();
        if (tid < off) S.bmaxs[tid] = fmaxf(S.bmaxs[tid], S.bmaxs[tid + off]);
    }
    __syncthreads();

    unsigned int rank = S.eqscan[tid];
    float part = 0.0f;
#pragma unroll
    for (int j = 0; j < 8; j++) {
        bool keep;
        if (u[j] > t) keep = true;
        else if (u[j] == t) { keep = (rank < need_eq); rank++; }
        else keep = false;
        if (!keep) f[j] = 0.0f;
        part += f[j];
    }
    S.psum[tid] = part;
    __syncthreads();

    if (tid < NSTRIPE) {
        float s = 0.0f;
#pragma unroll
        for (int i = 0; i < 8; i++) s += S.psum[tid * 8 + i];
        S.ssum[tid] = s;
    }
    __syncthreads();

    if (tid == 0) {
        bool sel[NSTRIPE];
#pragma unroll
        for (int s = 0; s < NSTRIPE; s++) sel[s] = false;
        float v4 = 0.0f, v5 = 0.0f;
        for (int it = 0; it < KSTRIPE + 1; it++) {
            int best = -1; float bv = -1.0f;
            for (int s = 0; s < NSTRIPE; s++)
                if (!sel[s] && S.ssum[s] > bv) { bv = S.ssum[s]; best = s; }
            if (it < KSTRIPE) { sel[best] = true; if (it == KSTRIPE - 1) v4 = bv; }
            else v5 = bv;
        }
#pragma unroll
        for (int s = 0; s < NSTRIPE; s++) S.smask[s] = sel[s] ? 1.0f : 0.0f;

        if (flagmode) {
            float gap_n = __uint_as_float(t) - S.bmaxs[0];
            if (need_eq < S.s_total) gap_n = 0.0f;
            float gap_s = v4 - v5;
            if (gap_n < TAU1 || gap_s < TAU2) {
                int ix = atomicAdd(&g_flag_cnt, 1);
                g_flag_rows[ix] = row;
            }
        }
    }
    __syncthreads();

    const float sm = S.smask[tid >> 3];
    float mv[8];
    unsigned int myc = 0;
#pragma unroll
    for (int j = 0; j < 8; j++) { mv[j] = f[j] * sm; myc += (mv[j] != 0.0f); }
    S.eqscan[tid] = myc;
    __syncthreads();
    if (tid == 0) {
        unsigned int run = 0;
        for (int i = 0; i < 256; i++) { unsigned int v = S.eqscan[i]; S.eqscan[i] = run; run += v; }
        g_cnt[row] = (int)run;
    }
    __syncthreads();
    int base = (int)S.eqscan[tid];
    const int gb = row * KNEUR;
#pragma unroll
    for (int j = 0; j < 8; j++) {
        if (mv[j] != 0.0f) {
            g_idx[gb + base] = tid * 8 + j;
            g_val[gb + base] = mv[j];
            base++;
        }
    }
}

__global__ __launch_bounds__(256) void topk_flag_kernel(const float* __restrict__ C)
{
    __shared__ TopkSmem S;
    topk_body(S, C, blockIdx.x, true);
}

__global__ __launch_bounds__(256) void reset_cnt_kernel()
{
    if (threadIdx.x == 0 && blockIdx.x == 0) g_flag_cnt = 0;
}

// ---------------------------------------------------------------------------
// Batched fix GEMVs: 16 flagged rows per block share each weight read.
// Warp computes 4 outputs (j) at once, lanes stride K in float4.
// ---------------------------------------------------------------------------
#define FGROUP 16

// h_fix: A = x rows (K=784, float4 count 196), out g_hfix[slot][INTER]
__global__ __launch_bounds__(256) void h_fix_kernel(
    const float* __restrict__ x, const float* __restrict__ W1,
    const float* __restrict__ b1)
{
    extern __shared__ float xs[];            // [FGROUP][IN_DIM]
    const int tid = threadIdx.x;
    const int lane = tid & 31, warp = tid >> 5;
    const int nf = g_flag_cnt;
    const int ngroup = (nf + FGROUP - 1) / FGROUP;
    const int ntask = ngroup * 2;            // 2 halves of INTER (512 j each)

    for (int task = blockIdx.x; task < ntask; task += gridDim.x) {
        const int grp = task >> 1, half = task & 1;
        const int base = grp * FGROUP;
        const int nrows = min(FGROUP, nf - base);
        __syncthreads();
        for (int r = 0; r < nrows; r++) {
            int row = g_flag_rows[base + r];
            for (int k = tid; k < IN_DIM; k += 256)
                xs[r * IN_DIM + k] = x[(size_t)row * IN_DIM + k];
        }
        __syncthreads();

        // 8 warps x 64 j each = 512 j per half; groups of 4 j
        for (int jg = 0; jg < 16; jg++) {
            const int j0 = half * 512 + warp * 64 + jg * 4;
            const float4* w0 = (const float4*)(W1 + (size_t)(j0 + 0) * IN_DIM);
            const float4* w1 = (const float4*)(W1 + (size_t)(j0 + 1) * IN_DIM);
            const float4* w2 = (const float4*)(W1 + (size_t)(j0 + 2) * IN_DIM);
            const float4* w3 = (const float4*)(W1 + (size_t)(j0 + 3) * IN_DIM);
            float acc[FGROUP][4];
#pragma unroll
            for (int r = 0; r < FGROUP; r++)
#pragma unroll
                for (int q = 0; q < 4; q++) acc[r][q] = 0.0f;

            for (int kk = lane; kk < IN_DIM / 4; kk += 32) {
                float4 a = w0[kk], b = w1[kk], c = w2[kk], d = w3[kk];
#pragma unroll
                for (int r = 0; r < FGROUP; r++) {
                    float4 xv = ((const float4*)(xs + r * IN_DIM))[kk];
                    acc[r][0] = fmaf(xv.x, a.x, fmaf(xv.y, a.y, fmaf(xv.z, a.z, fmaf(xv.w, a.w, acc[r][0]))));
                    acc[r][1] = fmaf(xv.x, b.x, fmaf(xv.y, b.y, fmaf(xv.z, b.z, fmaf(xv.w, b.w, acc[r][1]))));
                    acc[r][2] = fmaf(xv.x, c.x, fmaf(xv.y, c.y, fmaf(xv.z, c.z, fmaf(xv.w, c.w, acc[r][2]))));
                    acc[r][3] = fmaf(xv.x, d.x, fmaf(xv.y, d.y, fmaf(xv.z, d.z, fmaf(xv.w, d.w, acc[r][3]))));
                }
            }
#pragma unroll
            for (int r = 0; r < FGROUP; r++)
#pragma unroll
                for (int q = 0; q < 4; q++) {
                    float a = acc[r][q];
#pragma unroll
                    for (int o = 16; o > 0; o >>= 1)
                        a += __shfl_xor_sync(0xFFFFFFFFu, a, o);
                    if (lane == 0 && r < nrows)
                        g_hfix[(size_t)(base + r) * INTER + j0 + q] =
                            fmaxf(a + b1[j0 + q], 0.0f);
                }
        }
    }
}

// c_fix: A = g_hfix slot rows (K=1024), out scattered to c[row][CODE]
__global__ __launch_bounds__(256) void fixup_exact_kernel(
    const float* __restrict__ W2, const float* __restrict__ b2, float* __restrict__ c)
{
    extern __shared__ float hs[];            // [FGROUP][INTER]
    const int tid = threadIdx.x;
    const int lane = tid & 31, warp = tid >> 5;
    const int nf = g_flag_cnt;
    const int ngroup = (nf + FGROUP - 1) / FGROUP;
    const int ntask = ngroup * 4;            // 4 quarters of CODE (512 j each)

    for (int task = blockIdx.x; task < ntask; task += gridDim.x) {
        const int grp = task >> 2, quart = task & 3;
        const int base = grp * FGROUP;
        const int nrows = min(FGROUP, nf - base);
        __syncthreads();
        for (int r = 0; r < nrows; r++) {
            for (int k = tid; k < INTER; k += 256)
                hs[r * INTER + k] = g_hfix[(size_t)(base + r) * INTER + k];
        }
        __syncthreads();

        for (int jg = 0; jg < 16; jg++) {
            const int j0 = quart * 512 + warp * 64 + jg * 4;
            const float4* w0 = (const float4*)(W2 + (size_t)(j0 + 0) * INTER);
            const float4* w1 = (const float4*)(W2 + (size_t)(j0 + 1) * INTER);
            const float4* w2 = (const float4*)(W2 + (size_t)(j0 + 2) * INTER);
            const float4* w3 = (const float4*)(W2 + (size_t)(j0 + 3) * INTER);
            float acc[FGROUP][4];
#pragma unroll
            for (int r = 0; r < FGROUP; r++)
#pragma unroll
                for (int q = 0; q < 4; q++) acc[r][q] = 0.0f;

            for (int kk = lane; kk < INTER / 4; kk += 32) {
                float4 a = w0[kk], b = w1[kk], cc = w2[kk], d = w3[kk];
#pragma unroll
                for (int r = 0; r < FGROUP; r++) {
                    float4 hv = ((const float4*)(hs + r * INTER))[kk];
                    acc[r][0] = fmaf(hv.x, a.x, fmaf(hv.y, a.y, fmaf(hv.z, a.z, fmaf(hv.w, a.w, acc[r][0]))));
                    acc[r][1] = fmaf(hv.x, b.x, fmaf(hv.y, b.y, fmaf(hv.z, b.z, fmaf(hv.w, b.w, acc[r][1]))));
                    acc[r][2] = fmaf(hv.x, cc.x, fmaf(hv.y, cc.y, fmaf(hv.z, cc.z, fmaf(hv.w, cc.w, acc[r][2]))));
                    acc[r][3] = fmaf(hv.x, d.x, fmaf(hv.y, d.y, fmaf(hv.z, d.z, fmaf(hv.w, d.w, acc[r][3]))));
                }
            }
#pragma unroll
            for (int r = 0; r < FGROUP; r++)
#pragma unroll
                for (int q = 0; q < 4; q++) {
                    float a = acc[r][q];
#pragma unroll
                    for (int o = 16; o > 0; o >>= 1)
                        a += __shfl_xor_sync(0xFFFFFFFFu, a, o);
                    if (lane == 0 && r < nrows) {
                        int row = g_flag_rows[base + r];
                        c[(size_t)row * CODE + j0 + q] = fmaxf(a + b2[j0 + q], 0.0f);
                    }
                }
        }
    }
}

__global__ __launch_bounds__(256) void fixup_topk_kernel(const float* __restrict__ C)
{
    __shared__ TopkSmem S;
    const int nf = g_flag_cnt;
    for (int i = blockIdx.x; i < nf; i += gridDim.x) {
        topk_body(S, C, g_flag_rows[i], false);
        __syncthreads();
    }
}

// ---------------------------------------------------------------------------
// L3: sparse row-gather GEMV fp32 -> d bf16 pair (validated R9)
// ---------------------------------------------------------------------------
__global__ __launch_bounds__(256) void l3_gather(
    const float* __restrict__ W3T, const float* __restrict__ b3,
    bf16* __restrict__ D0, bf16* __restrict__ D1)
{
    __shared__ float sval[KNEUR];
    __shared__ int   sidx[KNEUR];
    const int row = blockIdx.x, tid = threadIdx.x;
    const int cnt = g_cnt[row];
    if (tid < KNEUR && tid < cnt) {
        sidx[tid] = g_idx[row * KNEUR + tid];
        sval[tid] = g_val[row * KNEUR + tid];
    }
    __syncthreads();

    const int n = tid * 4;
    float4 acc = *(const float4*)(b3 + n);
    int j = 0;
    for (; j + 4 <= cnt; j += 4) {
        const float4 w0 = *(const float4*)(W3T + (size_t)sidx[j + 0] * INTER + n);
        const float4 w1 = *(const float4*)(W3T + (size_t)sidx[j + 1] * INTER + n);
        const float4 w2 = *(const float4*)(W3T + (size_t)sidx[j + 2] * INTER + n);
        const float4 w3 = *(const float4*)(W3T + (size_t)sidx[j + 3] * INTER + n);
        const float v0 = sval[j], v1 = sval[j + 1], v2 = sval[j + 2], v3 = sval[j + 3];
        acc.x = fmaf(v0, w0.x, acc.x); acc.y = fmaf(v0, w0.y, acc.y);
        acc.z = fmaf(v0, w0.z, acc.z); acc.w = fmaf(v0, w0.w, acc.w);
        acc.x = fmaf(v1, w1.x, acc.x); acc.y = fmaf(v1, w1.y, acc.y);
        acc.z = fmaf(v1, w1.z, acc.z); acc.w = fmaf(v1, w1.w, acc.w);
        acc.x = fmaf(v2, w2.x, acc.x); acc.y = fmaf(v2, w2.y, acc.y);
        acc.z = fmaf(v2, w2.z, acc.z); acc.w = fmaf(v2, w2.w, acc.w);
        acc.x = fmaf(v3, w3.x, acc.x); acc.y = fmaf(v3, w3.y, acc.y);
        acc.z = fmaf(v3, w3.z, acc.z); acc.w = fmaf(v3, w3.w, acc.w);
    }
    for (; j < cnt; j++) {
        const float4 w0 = *(const float4*)(W3T + (size_t)sidx[j] * INTER + n);
        const float v0 = sval[j];
        acc.x = fmaf(v0, w0.x, acc.x); acc.y = fmaf(v0, w0.y, acc.y);
        acc.z = fmaf(v0, w0.z, acc.z); acc.w = fmaf(v0, w0.w, acc.w);
    }

    acc.x = fmaxf(acc.x, 0.0f); acc.y = fmaxf(acc.y, 0.0f);
    acc.z = fmaxf(acc.z, 0.0f); acc.w = fmaxf(acc.w, 0.0f);

    __nv_bfloat162 p0a, p0b, p1a, p1b;
    p0a.x = __float2bfloat16(acc.x); p0a.y = __float2bfloat16(acc.y);
    p0b.x = __float2bfloat16(acc.z); p0b.y = __float2bfloat16(acc.w);
    p1a.x = __float2bfloat16(acc.x - __bfloat162float(p0a.x));
    p1a.y = __float2bfloat16(acc.y - __bfloat162float(p0a.y));
    p1b.x = __float2bfloat16(acc.z - __bfloat162float(p0b.x));
    p1b.y = __float2bfloat16(acc.w - __bfloat162float(p0b.y));
    *(__nv_bfloat162*)(D0 + (size_t)row * INTER + n)     = p0a;
    *(__nv_bfloat162*)(D0 + (size_t)row * INTER + n + 2) = p0b;
    *(__nv_bfloat162*)(D1 + (size_t)row * INTER + n)     = p1a;
    *(__nv_bfloat162*)(D1 + (size_t)row * INTER + n + 2) = p1b;
}

// ---------------------------------------------------------------------------
extern "C" void kernel_launch(void* const* d_in, const int* in_sizes, int n_in,
                              void* d_out, int out_size)
{
    const float* x  = (const float*)d_in[0];
    const float* W1 = (const float*)d_in[1];
    const float* b1 = (const float*)d_in[2];
    const float* W2 = (const float*)d_in[3];
    const float* b2 = (const float*)d_in[4];
    const float* W3 = (const float*)d_in[5];
    const float* b3 = (const float*)d_in[6];
    const float* W4 = (const float*)d_in[7];
    const float* b4 = (const float*)d_in[8];
    float* out = (float*)d_out;

    float *c, *w3t;
    __half *x0, *x1, *w1h, *w1l, *hh16, *hl16, *w2h16, *w2l16;
    bf16 *d0, *d1, *w40, *w41;
    cudaGetSymbolAddress((void**)&c, g_c);
    cudaGetSymbolAddress((void**)&w3t, g_w3t);
    cudaGetSymbolAddress((void**)&x0, g_x0);       cudaGetSymbolAddress((void**)&x1, g_x1);
    cudaGetSymbolAddress((void**)&w1h, g_w1h);     cudaGetSymbolAddress((void**)&w1l, g_w1l);
    cudaGetSymbolAddress((void**)&hh16, g_hh16);   cudaGetSymbolAddress((void**)&hl16, g_hl16);
    cudaGetSymbolAddress((void**)&w2h16, g_w2h16); cudaGetSymbolAddress((void**)&w2l16, g_w2l16);
    cudaGetSymbolAddress((void**)&d0, g_d0);       cudaGetSymbolAddress((void**)&d1, g_d1);
    cudaGetSymbolAddress((void**)&w40, g_w4_0);    cudaGetSymbolAddress((void**)&w41, g_w4_1);

    cudaFuncSetAttribute(gemm_f16<0>, cudaFuncAttributeMaxDynamicSharedMemorySize, SMEM_HMMA);
    cudaFuncSetAttribute(gemm_f16<1>, cudaFuncAttributeMaxDynamicSharedMemorySize, SMEM_HMMA);
    cudaFuncSetAttribute(gemm_split2_f, cudaFuncAttributeMaxDynamicSharedMemorySize, SMEM_HMMA);
    cudaFuncSetAttribute(h_fix_kernel, cudaFuncAttributeMaxDynamicSharedMemorySize,
                         FGROUP * IN_DIM * (int)sizeof(float));
    cudaFuncSetAttribute(fixup_exact_kernel, cudaFuncAttributeMaxDynamicSharedMemorySize,
                         FGROUP * INTER * (int)sizeof(float));

    auto gs = [](size_t n) { return (unsigned)((n + 255) / 256); };

    // prep: splits + transpose
    split16_pad<<<gs((size_t)BATCH * K1P), 256>>>(x,  x0,  x1,  BATCH, IN_DIM, BATCH, K1P);
    split16_pad<<<gs((size_t)INTER * K1P), 256>>>(W1, w1h, w1l, INTER, IN_DIM, INTER, K1P);
    split16_pad<<<gs((size_t)CODE * INTER), 256>>>(W2, w2h16, w2l16, CODE, INTER, CODE, INTER);
    split_pad2<<<gs((size_t)N4P * INTER), 256>>>(W4, w40, w41, IN_DIM, INTER, N4P, INTER);
    transpose_w3<<<dim3(CODE / 32, INTER / 32), dim3(32, 8)>>>(W3, w3t);

    // L1: fp16-split HMMA -> h pair direct
    gemm_f16<1><<<dim3(INTER / 128, BATCH / 128), 256, SMEM_HMMA>>>(
        x0, x1, w1h, w1l, b1, nullptr, hh16, hl16, K1P, INTER, INTER);

    // L2: fp16-split HMMA -> c fp32
    gemm_f16<0><<<dim3(CODE / 128, BATCH / 128), 256, SMEM_HMMA>>>(
        hh16, hl16, w2h16, w2l16, b2, c, nullptr, nullptr, INTER, CODE, CODE);

    // topk with margins; flagged rows: batched exact fp32 chain
    reset_cnt_kernel<<<1, 32>>>();
    topk_flag_kernel<<<BATCH, 256>>>(c);
    h_fix_kernel<<<512, 256, FGROUP * IN_DIM * sizeof(float)>>>(x, W1, b1);
    fixup_exact_kernel<<<1024, 256, FGROUP * INTER * sizeof(float)>>>(W2, b2, c);
    fixup_topk_kernel<<<1024, 256>>>(c);

    // L3 sparse gather -> d pair
    l3_gather<<<BATCH, 256>>>(w3t, b3, d0, d1);

    // L4 HMMA split -> out
    gemm_split2_f<<<dim3(N4P / 128, BATCH / 128), 256, SMEM_HMMA>>>(
        d0, d1, w40, w41, b4, out, INTER, IN_DIM, IN_DIM);
}

// round 14
// speedup vs baseline: 2.1732x; 1.0370x over previous
#include <cuda_runtime.h>
#include <cuda_bf16.h>
#include <cuda_fp16.h>
#include <cstdint>

// ---------------------------------------------------------------------------
// Net_46368466928157 — round 14:
//   L1: fp16 scaled 2-part split HMMA (3 terms) -> h pair
//   L2: fp16 scaled 2-part split HMMA (3 terms) -> c fp32
//   topk: margins + batched exact fixup (validated R13)
//   L3: sparse row-gather GEMV, W3^T in fp16, fp32 accum -> d fp16 pair
//   L4: fp16 HMMA, 2 terms (A pair x single-fp16 W4)
// ---------------------------------------------------------------------------

#define BATCH   16384
#define IN_DIM  784
#define K1P     800
#define INTER   1024
#define CODE    2048
#define N4P     896
#define NSTRIPE 32
#define KNEUR   64
#define KSTRIPE 4

#define TAU1 2.5e-5f
#define TAU2 2e-3f

// ---- scratch --------------------------------------------------------------
__device__ __half g_x0[(size_t)BATCH * K1P],  g_x1[(size_t)BATCH * K1P];
__device__ __half g_w1h[(size_t)INTER * K1P], g_w1l[(size_t)INTER * K1P];
__device__ __half g_hh16[(size_t)BATCH * INTER], g_hl16[(size_t)BATCH * INTER];
__device__ __half g_w2h16[(size_t)CODE * INTER], g_w2l16[(size_t)CODE * INTER];
__device__ float  g_c[(size_t)BATCH * CODE];
__device__ __half g_w3t16[(size_t)CODE * INTER];        // W3^T fp16 [2048,1024]
__device__ __half g_dh16[(size_t)BATCH * INTER], g_dl16[(size_t)BATCH * INTER];
__device__ __half g_w4h16[(size_t)N4P * INTER];         // W4 fp16 single, padded
__device__ int    g_flag_cnt;
__device__ int    g_flag_rows[BATCH];
__device__ float  g_hfix[(size_t)BATCH * INTER];
__device__ int    g_cnt[BATCH];
__device__ int    g_idx[(size_t)BATCH * KNEUR];
__device__ float  g_val[(size_t)BATCH * KNEUR];

// ===========================================================================
// PTX helpers
// ===========================================================================
__device__ __forceinline__ uint32_t smem_u32(const void* p) {
    uint32_t a;
    asm("{ .reg .u64 t; cvta.to.shared.u64 t, %1; cvt.u32.u64 %0, t; }" : "=r"(a) : "l"(p));
    return a;
}
#define CP_ASYNC16(dst, src) \
    asm volatile("cp.async.cg.shared.global [%0], [%1], 16;" :: "r"(dst), "l"(src) : "memory")
#define CP_COMMIT()  asm volatile("cp.async.commit_group;" ::: "memory")
#define CP_WAIT(n)   asm volatile("cp.async.wait_group %0;" :: "n"(n) : "memory")

__device__ __forceinline__ void ldsm_x4(uint32_t& r0, uint32_t& r1, uint32_t& r2,
                                        uint32_t& r3, uint32_t addr) {
    asm volatile("ldmatrix.sync.aligned.m8n8.x4.shared.b16 {%0,%1,%2,%3}, [%4];"
        : "=r"(r0), "=r"(r1), "=r"(r2), "=r"(r3) : "r"(addr));
}
__device__ __forceinline__ void mma_fp16(float* c, const uint32_t* a, const uint32_t* b) {
    asm volatile("mma.sync.aligned.m16n8k16.row.col.f32.f16.f16.f32 "
        "{%0,%1,%2,%3}, {%4,%5,%6,%7}, {%8,%9}, {%0,%1,%2,%3};"
        : "+f"(c[0]), "+f"(c[1]), "+f"(c[2]), "+f"(c[3])
        : "r"(a[0]), "r"(a[1]), "r"(a[2]), "r"(a[3]), "r"(b[0]), "r"(b[1]));
}

#define ROWB   80
#define TILE_B (128 * ROWB)
#define SM_TILES 1024
#define SMEM_HMMA3 (SM_TILES + 2 * 4 * TILE_B)   // 3-term: 4 tiles/stage
#define SMEM_HMMA2 (SM_TILES + 2 * 3 * TILE_B)   // 2-term: 3 tiles/stage

// ===========================================================================
// fp16 scaled-split GEMM: C = relu(bias + A@B^T). A1 = Alo*2048, B1 = Blo*2048.
// TERMS=3: acc1=AhBh, acc2=AlBh+AhBl. TERMS=2: acc1=AhBh, acc2=AlBh (B single).
// OUTMODE 0: fp32 out (guard n<Nvalid). OUTMODE 1: fp16 pair out.
// ===========================================================================
template<int OUTMODE, int TERMS>
__global__ __launch_bounds__(256, 1) void gemm_f16(
    const __half* __restrict__ A0, const __half* __restrict__ A1,
    const __half* __restrict__ B0, const __half* __restrict__ B1,
    const float* __restrict__ bias, float* __restrict__ Cf,
    __half* __restrict__ H0, __half* __restrict__ H1,
    int Kp, int Nvalid, int outStride)
{
    extern __shared__ char smem[];
    const int NT = (TERMS == 3) ? 4 : 3;     // tiles per stage
    const uint32_t sbase = smem_u32(smem) + SM_TILES;
    const int tid  = threadIdx.x;
    const int warp = tid >> 5, lane = tid & 31;
    const int wm = (warp >> 2) * 64;
    const int wn = (warp & 3) * 32;
    const int m0 = blockIdx.y * 128;
    const int n0 = blockIdx.x * 128;

    if (tid < 128) {
        int n = n0 + tid;
        ((float*)smem)[tid] = (n < Nvalid) ? bias[n] : 0.0f;
    }

    float acc1[4][4][4], acc2[4][4][4];
#pragma unroll
    for (int i = 0; i < 4; i++)
#pragma unroll
        for (int j = 0; j < 4; j++)
#pragma unroll
            for (int q = 0; q < 4; q++) { acc1[i][j][q] = 0.0f; acc2[i][j][q] = 0.0f; }

    const int nk = Kp / 32;

    auto load_stage = [&](int kc, int s) {
        const int k0 = kc * 32;
        const uint32_t stb = sbase + s * NT * TILE_B;
#pragma unroll
        for (int t = 0; t < NT; t++) {
            const __half* base =
                (t == 0) ? (A0 + (size_t)m0 * Kp) :
                (t == 1) ? (A1 + (size_t)m0 * Kp) :
                (t == 2) ? (B0 + (size_t)n0 * Kp) :
                           (B1 + (size_t)n0 * Kp);
#pragma unroll
            for (int i = 0; i < 2; i++) {
                int f = tid + i * 256;
                int row = f >> 2, c = f & 3;
                uint32_t dst = stb + t * TILE_B + row * ROWB + c * 16;
                CP_ASYNC16(dst, base + (size_t)row * Kp + k0 + c * 8);
            }
        }
        CP_COMMIT();
    };

    auto compute_stage = [&](int s) {
        const uint32_t stb = sbase + s * NT * TILE_B;
#pragma unroll
        for (int ks = 0; ks < 2; ks++) {
            uint32_t afr[2][4][4];
#pragma unroll
            for (int p = 0; p < 2; p++) {
                const uint32_t Ab = stb + p * TILE_B;
#pragma unroll
                for (int mf = 0; mf < 4; mf++) {
                    int row = wm + mf * 16 + (lane & 15);
                    uint32_t off = row * ROWB + ks * 32 + (lane >> 4) * 16;
                    ldsm_x4(afr[p][mf][0], afr[p][mf][1], afr[p][mf][2], afr[p][mf][3], Ab + off);
                }
            }
            const int NB = (TERMS == 3) ? 2 : 1;
#pragma unroll
            for (int j = 0; j < NB; j++) {
                const uint32_t Bb = stb + (2 + j) * TILE_B;
                uint32_t bfr[4][2];
#pragma unroll
                for (int p = 0; p < 2; p++) {
                    int g = lane >> 3, ri = lane & 7;
                    int row = wn + p * 16 + ((g >> 1) << 3) + ri;
                    uint32_t off = row * ROWB + (2 * ks + (g & 1)) * 16;
                    uint32_t t0, t1, t2, t3;
                    ldsm_x4(t0, t1, t2, t3, Bb + off);
                    bfr[p*2][0] = t0; bfr[p*2][1] = t1;
                    bfr[p*2+1][0] = t2; bfr[p*2+1][1] = t3;
                }
                if (j == 0) {
#pragma unroll
                    for (int mf = 0; mf < 4; mf++)
#pragma unroll
                        for (int nf = 0; nf < 4; nf++) {
                            mma_fp16(acc1[mf][nf], afr[0][mf], bfr[nf]);   // Ah*Bh
                            mma_fp16(acc2[mf][nf], afr[1][mf], bfr[nf]);   // Al*Bh
                        }
                } else {
#pragma unroll
                    for (int mf = 0; mf < 4; mf++)
#pragma unroll
                        for (int nf = 0; nf < 4; nf++)
                            mma_fp16(acc2[mf][nf], afr[0][mf], bfr[nf]);   // Ah*Bl
                }
            }
        }
    };

    load_stage(0, 0);
    for (int kc = 0; kc < nk; kc++) {
        if (kc + 1 < nk) { load_stage(kc + 1, (kc + 1) & 1); CP_WAIT(1); }
        else             { CP_WAIT(0); }
        __syncthreads();
        compute_stage(kc & 1);
        __syncthreads();
    }

    const float* bs = (const float*)smem;
    const float INV = 1.0f / 2048.0f;
    const int lr = lane >> 2;
    const int lc = (lane & 3) * 2;
#pragma unroll
    for (int mf = 0; mf < 4; mf++) {
#pragma unroll
        for (int nf = 0; nf < 4; nf++) {
            int nrel = wn + nf * 8 + lc;
            int n = n0 + nrel;
            float b0 = bs[nrel], b1 = bs[nrel + 1];
#pragma unroll
            for (int half = 0; half < 2; half++) {
                int m = m0 + wm + mf * 16 + lr + half * 8;
                float v0 = fmaxf(fmaf(acc2[mf][nf][half*2+0], INV, acc1[mf][nf][half*2+0]) + b0, 0.0f);
                float v1 = fmaxf(fmaf(acc2[mf][nf][half*2+1], INV, acc1[mf][nf][half*2+1]) + b1, 0.0f);
                if (OUTMODE == 0) {
                    if (n < Nvalid)
                        *(float2*)(Cf + (size_t)m * outStride + n) = make_float2(v0, v1);
                } else {
                    __half h0 = __float2half_rn(v0), h1 = __float2half_rn(v1);
                    __half2 hh = __halves2half2(h0, h1);
                    __half2 ll = __halves2half2(
                        __float2half_rn((v0 - __half2float(h0)) * 2048.0f),
                        __float2half_rn((v1 - __half2float(h1)) * 2048.0f));
                    *(__half2*)(H0 + (size_t)m * outStride + n) = hh;
                    *(__half2*)(H1 + (size_t)m * outStride + n) = ll;
                }
            }
        }
    }
}

// ---------------------------------------------------------------------------
// prep kernels
// ---------------------------------------------------------------------------
__global__ __launch_bounds__(256) void split16_pad(
    const float* __restrict__ src, __half* __restrict__ H, __half* __restrict__ L,
    int srows, int scols, int orows, int ocols)
{
    size_t i = (size_t)blockIdx.x * blockDim.x + threadIdx.x;
    size_t tot = (size_t)orows * ocols;
    if (i >= tot) return;
    int r = (int)(i / ocols), c = (int)(i % ocols);
    float v = (r < srows && c < scols) ? src[(size_t)r * scols + c] : 0.0f;
    __half h = __float2half_rn(v);
    H[i] = h;
    L[i] = __float2half_rn((v - __half2float(h)) * 2048.0f);
}

// single fp16, zero-padded
__global__ __launch_bounds__(256) void convert16_pad(
    const float* __restrict__ src, __half* __restrict__ H,
    int srows, int scols, int orows, int ocols)
{
    size_t i = (size_t)blockIdx.x * blockDim.x + threadIdx.x;
    size_t tot = (size_t)orows * ocols;
    if (i >= tot) return;
    int r = (int)(i / ocols), c = (int)(i % ocols);
    float v = (r < srows && c < scols) ? src[(size_t)r * scols + c] : 0.0f;
    H[i] = __float2half_rn(v);
}

// W3 [INTER,CODE] fp32 -> W3T [CODE,INTER] fp16
__global__ void transpose_w3(const float* __restrict__ W3, __half* __restrict__ W3T)
{
    __shared__ float t[32][33];
    int bx = blockIdx.x * 32;
    int by = blockIdx.y * 32;
    for (int i = threadIdx.y; i < 32; i += 8)
        t[i][threadIdx.x] = W3[(size_t)(by + i) * CODE + bx + threadIdx.x];
    __syncthreads();
    for (int i = threadIdx.y; i < 32; i += 8)
        W3T[(size_t)(bx + i) * INTER + by + threadIdx.x] = __float2half_rn(t[threadIdx.x][i]);
}

// ---------------------------------------------------------------------------
// topk body — flags tight rows, emits compact (idx,val) lists (validated)
// ---------------------------------------------------------------------------
struct TopkSmem {
    unsigned int hist[256];
    unsigned int eqscan[256];
    float psum[256];
    float bmaxs[256];
    float ssum[NSTRIPE];
    float smask[NSTRIPE];
    unsigned int s_prefix, s_remk, s_total;
};

__device__ __forceinline__ void topk_body(
    TopkSmem& S, const float* __restrict__ C, int row, bool flagmode)
{
    const int tid = threadIdx.x;
    const float* crow = C + (size_t)row * CODE;

    float f[8];
    *(float4*)&f[0] = *(const float4*)(crow + tid * 8);
    *(float4*)&f[4] = *(const float4*)(crow + tid * 8 + 4);
    unsigned int u[8];
#pragma unroll
    for (int j = 0; j < 8; j++) u[j] = __float_as_uint(f[j]);

    if (tid == 0) { S.s_prefix = 0; S.s_remk = KNEUR; }
    __syncthreads();

#pragma unroll
    for (int pass = 0; pass < 4; pass++) {
        const int shift = 24 - pass * 8;
        const unsigned int pm = (pass == 0) ? 0u : (0xFFFFFFFFu << (shift + 8));
        S.hist[tid] = 0;
        __syncthreads();
        unsigned int pref = S.s_prefix;
#pragma unroll
        for (int j = 0; j < 8; j++)
            if ((u[j] & pm) == pref) atomicAdd(&S.hist[(u[j] >> shift) & 0xFF], 1u);
        __syncthreads();
        if (tid == 0) {
            unsigned int remk = S.s_remk, acc = 0;
            int b = 255;
            for (; b > 0; b--) { acc += S.hist[b]; if (acc >= remk) break; }
            if (acc < remk) acc += S.hist[0];
            S.s_prefix = pref | ((unsigned int)b << shift);
            S.s_remk = remk - (acc - S.hist[b]);
        }
        __syncthreads();
    }

    const unsigned int t = S.s_prefix;
    const unsigned int need_eq = S.s_remk;

    unsigned int cnt = 0;
    float bmax = 0.0f;
#pragma unroll
    for (int j = 0; j < 8; j++) {
        cnt += (u[j] == t);
        if (u[j] < t) bmax = fmaxf(bmax, f[j]);
    }
    S.eqscan[tid] = cnt;
    S.bmaxs[tid] = bmax;
    __syncthreads();
    if (tid == 0) {
        unsigned int run = 0;
        for (int i = 0; i < 256; i++) { unsigned int v = S.eqscan[i]; S.eqscan[i] = run; run += v; }
        S.s_total = run;
    }
#pragma unroll
    for (int off = 128; off > 0; off >>= 1) {
        __syncthreads();
        if (tid < off) S.bmaxs[tid] = fmaxf(S.bmaxs[tid], S.bmaxs[tid + off]);
    }
    __syncthreads();

    unsigned int rank = S.eqscan[tid];
    float part = 0.0f;
#pragma unroll
    for (int j = 0; j < 8; j++) {
        bool keep;
        if (u[j] > t) keep = true;
        else if (u[j] == t) { keep = (rank < need_eq); rank++; }
        else keep = false;
        if (!keep) f[j] = 0.0f;
        part += f[j];
    }
    S.psum[tid] = part;
    __syncthreads();

    if (tid < NSTRIPE) {
        float s = 0.0f;
#pragma unroll
        for (int i = 0; i < 8; i++) s += S.psum[tid * 8 + i];
        S.ssum[tid] = s;
    }
    __syncthreads();

    if (tid == 0) {
        bool sel[NSTRIPE];
#pragma unroll
        for (int s = 0; s < NSTRIPE; s++) sel[s] = false;
        float v4 = 0.0f, v5 = 0.0f;
        for (int it = 0; it < KSTRIPE + 1; it++) {
            int best = -1; float bv = -1.0f;
            for (int s = 0; s < NSTRIPE; s++)
                if (!sel[s] && S.ssum[s] > bv) { bv = S.ssum[s]; best = s; }
            if (it < KSTRIPE) { sel[best] = true; if (it == KSTRIPE - 1) v4 = bv; }
            else v5 = bv;
        }
#pragma unroll
        for (int s = 0; s < NSTRIPE; s++) S.smask[s] = sel[s] ? 1.0f : 0.0f;

        if (flagmode) {
            float gap_n = __uint_as_float(t) - S.bmaxs[0];
            if (need_eq < S.s_total) gap_n = 0.0f;
            float gap_s = v4 - v5;
            if (gap_n < TAU1 || gap_s < TAU2) {
                int ix = atomicAdd(&g_flag_cnt, 1);
                g_flag_rows[ix] = row;
            }
        }
    }
    __syncthreads();

    const float sm = S.smask[tid >> 3];
    float mv[8];
    unsigned int myc = 0;
#pragma unroll
    for (int j = 0; j < 8; j++) { mv[j] = f[j] * sm; myc += (mv[j] != 0.0f); }
    S.eqscan[tid] = myc;
    __syncthreads();
    if (tid == 0) {
        unsigned int run = 0;
        for (int i = 0; i < 256; i++) { unsigned int v = S.eqscan[i]; S.eqscan[i] = run; run += v; }
        g_cnt[row] = (int)run;
    }
    __syncthreads();
    int base = (int)S.eqscan[tid];
    const int gb = row * KNEUR;
#pragma unroll
    for (int j = 0; j < 8; j++) {
        if (mv[j] != 0.0f) {
            g_idx[gb + base] = tid * 8 + j;
            g_val[gb + base] = mv[j];
            base++;
        }
    }
}

__global__ __launch_bounds__(256) void topk_flag_kernel(const float* __restrict__ C)
{
    __shared__ TopkSmem S;
    topk_body(S, C, blockIdx.x, true);
}

__global__ __launch_bounds__(256) void reset_cnt_kernel()
{
    if (threadIdx.x == 0 && blockIdx.x == 0) g_flag_cnt = 0;
}

// ---------------------------------------------------------------------------
// Batched fix GEMVs (validated R13): FGROUP flagged rows share weight reads.
// ---------------------------------------------------------------------------
#define FGROUP 16

__global__ __launch_bounds__(256) void h_fix_kernel(
    const float* __restrict__ x, const float* __restrict__ W1,
    const float* __restrict__ b1)
{
    extern __shared__ float xs[];            // [FGROUP][IN_DIM]
    const int tid = threadIdx.x;
    const int lane = tid & 31, warp = tid >> 5;
    const int nf = g_flag_cnt;
    const int ngroup = (nf + FGROUP - 1) / FGROUP;
    const int ntask = ngroup * 2;

    for (int task = blockIdx.x; task < ntask; task += gridDim.x) {
        const int grp = task >> 1, half = task & 1;
        const int base = grp * FGROUP;
        const int nrows = min(FGROUP, nf - base);
        __syncthreads();
        for (int r = 0; r < nrows; r++) {
            int row = g_flag_rows[base + r];
            for (int k = tid; k < IN_DIM; k += 256)
                xs[r * IN_DIM + k] = x[(size_t)row * IN_DIM + k];
        }
        __syncthreads();

        for (int jg = 0; jg < 16; jg++) {
            const int j0 = half * 512 + warp * 64 + jg * 4;
            const float4* w0 = (const float4*)(W1 + (size_t)(j0 + 0) * IN_DIM);
            const float4* w1 = (const float4*)(W1 + (size_t)(j0 + 1) * IN_DIM);
            const float4* w2 = (const float4*)(W1 + (size_t)(j0 + 2) * IN_DIM);
            const float4* w3 = (const float4*)(W1 + (size_t)(j0 + 3) * IN_DIM);
            float acc[FGROUP][4];
#pragma unroll
            for (int r = 0; r < FGROUP; r++)
#pragma unroll
                for (int q = 0; q < 4; q++) acc[r][q] = 0.0f;

            for (int kk = lane; kk < IN_DIM / 4; kk += 32) {
                float4 a = w0[kk], b = w1[kk], c = w2[kk], d = w3[kk];
#pragma unroll
                for (int r = 0; r < FGROUP; r++) {
                    float4 xv = ((const float4*)(xs + r * IN_DIM))[kk];
                    acc[r][0] = fmaf(xv.x, a.x, fmaf(xv.y, a.y, fmaf(xv.z, a.z, fmaf(xv.w, a.w, acc[r][0]))));
                    acc[r][1] = fmaf(xv.x, b.x, fmaf(xv.y, b.y, fmaf(xv.z, b.z, fmaf(xv.w, b.w, acc[r][1]))));
                    acc[r][2] = fmaf(xv.x, c.x, fmaf(xv.y, c.y, fmaf(xv.z, c.z, fmaf(xv.w, c.w, acc[r][2]))));
                    acc[r][3] = fmaf(xv.x, d.x, fmaf(xv.y, d.y, fmaf(xv.z, d.z, fmaf(xv.w, d.w, acc[r][3]))));
                }
            }
#pragma unroll
            for (int r = 0; r < FGROUP; r++)
#pragma unroll
                for (int q = 0; q < 4; q++) {
                    float a = acc[r][q];
#pragma unroll
                    for (int o = 16; o > 0; o >>= 1)
                        a += __shfl_xor_sync(0xFFFFFFFFu, a, o);
                    if (lane == 0 && r < nrows)
                        g_hfix[(size_t)(base + r) * INTER + j0 + q] =
                            fmaxf(a + b1[j0 + q], 0.0f);
                }
        }
    }
}

__global__ __launch_bounds__(256) void fixup_exact_kernel(
    const float* __restrict__ W2, const float* __restrict__ b2, float* __restrict__ c)
{
    extern __shared__ float hs[];            // [FGROUP][INTER]
    const int tid = threadIdx.x;
    const int lane = tid & 31, warp = tid >> 5;
    const int nf = g_flag_cnt;
    const int ngroup = (nf + FGROUP - 1) / FGROUP;
    const int ntask = ngroup * 4;

    for (int task = blockIdx.x; task < ntask; task += gridDim.x) {
        const int grp = task >> 2, quart = task & 3;
        const int base = grp * FGROUP;
        const int nrows = min(FGROUP, nf - base);
        __syncthreads();
        for (int r = 0; r < nrows; r++) {
            for (int k = tid; k < INTER; k += 256)
                hs[r * INTER + k] = g_hfix[(size_t)(base + r) * INTER + k];
        }
        __syncthreads();

        for (int jg = 0; jg < 16; jg++) {
            const int j0 = quart * 512 + warp * 64 + jg * 4;
            const float4* w0 = (const float4*)(W2 + (size_t)(j0 + 0) * INTER);
            const float4* w1 = (const float4*)(W2 + (size_t)(j0 + 1) * INTER);
            const float4* w2 = (const float4*)(W2 + (size_t)(j0 + 2) * INTER);
            const float4* w3 = (const float4*)(W2 + (size_t)(j0 + 3) * INTER);
            float acc[FGROUP][4];
#pragma unroll
            for (int r = 0; r < FGROUP; r++)
#pragma unroll
                for (int q = 0; q < 4; q++) acc[r][q] = 0.0f;

            for (int kk = lane; kk < INTER / 4; kk += 32) {
                float4 a = w0[kk], b = w1[kk], cc = w2[kk], d = w3[kk];
#pragma unroll
                for (int r = 0; r < FGROUP; r++) {
                    float4 hv = ((const float4*)(hs + r * INTER))[kk];
                    acc[r][0] = fmaf(hv.x, a.x, fmaf(hv.y, a.y, fmaf(hv.z, a.z, fmaf(hv.w, a.w, acc[r][0]))));
                    acc[r][1] = fmaf(hv.x, b.x, fmaf(hv.y, b.y, fmaf(hv.z, b.z, fmaf(hv.w, b.w, acc[r][1]))));
                    acc[r][2] = fmaf(hv.x, cc.x, fmaf(hv.y, cc.y, fmaf(hv.z, cc.z, fmaf(hv.w, cc.w, acc[r][2]))));
                    acc[r][3] = fmaf(hv.x, d.x, fmaf(hv.y, d.y, fmaf(hv.z, d.z, fmaf(hv.w, d.w, acc[r][3]))));
                }
            }
#pragma unroll
            for (int r = 0; r < FGROUP; r++)
#pragma unroll
                for (int q = 0; q < 4; q++) {
                    float a = acc[r][q];
#pragma unroll
                    for (int o = 16; o > 0; o >>= 1)
                        a += __shfl_xor_sync(0xFFFFFFFFu, a, o);
                    if (lane == 0 && r < nrows) {
                        int row = g_flag_rows[base + r];
                        c[(size_t)row * CODE + j0 + q] = fmaxf(a + b2[j0 + q], 0.0f);
                    }
                }
        }
    }
}

__global__ __launch_bounds__(256) void fixup_topk_kernel(const float* __restrict__ C)
{
    __shared__ TopkSmem S;
    const int nf = g_flag_cnt;
    for (int i = blockIdx.x; i < nf; i += gridDim.x) {
        topk_body(S, C, g_flag_rows[i], false);
        __syncthreads();
    }
}

// ---------------------------------------------------------------------------
// L3: sparse row-gather GEMV, W3^T fp16, fp32 accum -> d fp16 pair.
// one block per row; thread owns 4 contiguous outputs (8B fp16 per idx).
// ---------------------------------------------------------------------------
__global__ __launch_bounds__(256) void l3_gather(
    const __half* __restrict__ W3T, const float* __restrict__ b3,
    __half* __restrict__ D0, __half* __restrict__ D1)
{
    __shared__ float sval[KNEUR];
    __shared__ int   sidx[KNEUR];
    const int row = blockIdx.x, tid = threadIdx.x;
    const int cnt = g_cnt[row];
    if (tid < KNEUR && tid < cnt) {
        sidx[tid] = g_idx[row * KNEUR + tid];
        sval[tid] = g_val[row * KNEUR + tid];
    }
    __syncthreads();

    const int n = tid * 4;
    float4 acc = *(const float4*)(b3 + n);
    int j = 0;
    for (; j + 4 <= cnt; j += 4) {
#pragma unroll
        for (int q = 0; q < 4; q++) {
            const __half2* wp = (const __half2*)(W3T + (size_t)sidx[j + q] * INTER + n);
            float2 lo = __half22float2(wp[0]);
            float2 hi = __half22float2(wp[1]);
            const float v = sval[j + q];
            acc.x = fmaf(v, lo.x, acc.x); acc.y = fmaf(v, lo.y, acc.y);
            acc.z = fmaf(v, hi.x, acc.z); acc.w = fmaf(v, hi.y, acc.w);
        }
    }
    for (; j < cnt; j++) {
        const __half2* wp = (const __half2*)(W3T + (size_t)sidx[j] * INTER + n);
        float2 lo = __half22float2(wp[0]);
        float2 hi = __half22float2(wp[1]);
        const float v = sval[j];
        acc.x = fmaf(v, lo.x, acc.x); acc.y = fmaf(v, lo.y, acc.y);
        acc.z = fmaf(v, hi.x, acc.z); acc.w = fmaf(v, hi.y, acc.w);
    }

    acc.x = fmaxf(acc.x, 0.0f); acc.y = fmaxf(acc.y, 0.0f);
    acc.z = fmaxf(acc.z, 0.0f); acc.w = fmaxf(acc.w, 0.0f);

    __half h0 = __float2half_rn(acc.x), h1 = __float2half_rn(acc.y);
    __half h2 = __float2half_rn(acc.z), h3 = __float2half_rn(acc.w);
    __half2 hh0 = __halves2half2(h0, h1), hh1 = __halves2half2(h2, h3);
    __half2 ll0 = __halves2half2(
        __float2half_rn((acc.x - __half2float(h0)) * 2048.0f),
        __float2half_rn((acc.y - __half2float(h1)) * 2048.0f));
    __half2 ll1 = __halves2half2(
        __float2half_rn((acc.z - __half2float(h2)) * 2048.0f),
        __float2half_rn((acc.w - __half2float(h3)) * 2048.0f));
    *(__half2*)(D0 + (size_t)row * INTER + n)     = hh0;
    *(__half2*)(D0 + (size_t)row * INTER + n + 2) = hh1;
    *(__half2*)(D1 + (size_t)row * INTER + n)     = ll0;
    *(__half2*)(D1 + (size_t)row * INTER + n + 2) = ll1;
}

// ---------------------------------------------------------------------------
extern "C" void kernel_launch(void* const* d_in, const int* in_sizes, int n_in,
                              void* d_out, int out_size)
{
    const float* x  = (const float*)d_in[0];
    const float* W1 = (const float*)d_in[1];
    const float* b1 = (const float*)d_in[2];
    const float* W2 = (const float*)d_in[3];
    const float* b2 = (const float*)d_in[4];
    const float* W3 = (const float*)d_in[5];
    const float* b3 = (const float*)d_in[6];
    const float* W4 = (const float*)d_in[7];
    const float* b4 = (const float*)d_in[8];
    float* out = (float*)d_out;

    float* c;
    __half *x0, *x1, *w1h, *w1l, *hh16, *hl16, *w2h16, *w2l16;
    __half *w3t16, *dh16, *dl16, *w4h16;
    cudaGetSymbolAddress((void**)&c, g_c);
    cudaGetSymbolAddress((void**)&x0, g_x0);       cudaGetSymbolAddress((void**)&x1, g_x1);
    cudaGetSymbolAddress((void**)&w1h, g_w1h);     cudaGetSymbolAddress((void**)&w1l, g_w1l);
    cudaGetSymbolAddress((void**)&hh16, g_hh16);   cudaGetSymbolAddress((void**)&hl16, g_hl16);
    cudaGetSymbolAddress((void**)&w2h16, g_w2h16); cudaGetSymbolAddress((void**)&w2l16, g_w2l16);
    cudaGetSymbolAddress((void**)&w3t16, g_w3t16);
    cudaGetSymbolAddress((void**)&dh16, g_dh16);   cudaGetSymbolAddress((void**)&dl16, g_dl16);
    cudaGetSymbolAddress((void**)&w4h16, g_w4h16);

    cudaFuncSetAttribute(gemm_f16<0,3>, cudaFuncAttributeMaxDynamicSharedMemorySize, SMEM_HMMA3);
    cudaFuncSetAttribute(gemm_f16<1,3>, cudaFuncAttributeMaxDynamicSharedMemorySize, SMEM_HMMA3);
    cudaFuncSetAttribute(gemm_f16<0,2>, cudaFuncAttributeMaxDynamicSharedMemorySize, SMEM_HMMA2);
    cudaFuncSetAttribute(h_fix_kernel, cudaFuncAttributeMaxDynamicSharedMemorySize,
                         FGROUP * IN_DIM * (int)sizeof(float));
    cudaFuncSetAttribute(fixup_exact_kernel, cudaFuncAttributeMaxDynamicSharedMemorySize,
                         FGROUP * INTER * (int)sizeof(float));

    auto gs = [](size_t n) { return (unsigned)((n + 255) / 256); };

    // prep: splits + transpose + W4 fp16
    split16_pad<<<gs((size_t)BATCH * K1P), 256>>>(x,  x0,  x1,  BATCH, IN_DIM, BATCH, K1P);
    split16_pad<<<gs((size_t)INTER * K1P), 256>>>(W1, w1h, w1l, INTER, IN_DIM, INTER, K1P);
    split16_pad<<<gs((size_t)CODE * INTER), 256>>>(W2, w2h16, w2l16, CODE, INTER, CODE, INTER);
    convert16_pad<<<gs((size_t)N4P * INTER), 256>>>(W4, w4h16, IN_DIM, INTER, N4P, INTER);
    transpose_w3<<<dim3(CODE / 32, INTER / 32), dim3(32, 8)>>>(W3, w3t16);

    // L1: fp16-split HMMA (3 terms) -> h pair direct
    gemm_f16<1,3><<<dim3(INTER / 128, BATCH / 128), 256, SMEM_HMMA3>>>(
        x0, x1, w1h, w1l, b1, nullptr, hh16, hl16, K1P, INTER, INTER);

    // L2: fp16-split HMMA (3 terms) -> c fp32
    gemm_f16<0,3><<<dim3(CODE / 128, BATCH / 128), 256, SMEM_HMMA3>>>(
        hh16, hl16, w2h16, w2l16, b2, c, nullptr, nullptr, INTER, CODE, CODE);

    // topk with margins; flagged rows: batched exact fp32 chain
    reset_cnt_kernel<<<1, 32>>>();
    topk_flag_kernel<<<BATCH, 256>>>(c);
    h_fix_kernel<<<512, 256, FGROUP * IN_DIM * sizeof(float)>>>(x, W1, b1);
    fixup_exact_kernel<<<1024, 256, FGROUP * INTER * sizeof(float)>>>(W2, b2, c);
    fixup_topk_kernel<<<1024, 256>>>(c);

    // L3 sparse gather (fp16 weights, fp32 accum) -> d fp16 pair
    l3_gather<<<BATCH, 256>>>(w3t16, b3, dh16, dl16);

    // L4: fp16 HMMA, 2 terms (d pair x W4 fp16) -> out fp32
    gemm_f16<0,2><<<dim3(N4P / 128, BATCH / 128), 256, SMEM_HMMA2>>>(
        dh16, dl16, w4h16, nullptr, b4, out, nullptr, nullptr, INTER, IN_DIM, IN_DIM);
}

// round 15
// speedup vs baseline: 2.2172x; 1.0202x over previous
#include <cuda_runtime.h>
#include <cuda_bf16.h>
#include <cuda_fp16.h>
#include <cstdint>

// ---------------------------------------------------------------------------
// Net_46368466928157 — round 15:
//   GEMMs re-tiled 128x64 (2 CTAs/SM, latency hiding) — L1/L2/L4.
//   Rest identical to R14 (validated): topk margins + batched exact fixup,
//   sparse fp16 gather L3, fp16 scaled-split arithmetic.
// ---------------------------------------------------------------------------

#define BATCH   16384
#define IN_DIM  784
#define K1P     800
#define INTER   1024
#define CODE    2048
#define N4P     896
#define NSTRIPE 32
#define KNEUR   64
#define KSTRIPE 4

#define TAU1 2.5e-5f
#define TAU2 2e-3f

// ---- scratch --------------------------------------------------------------
__device__ __half g_x0[(size_t)BATCH * K1P],  g_x1[(size_t)BATCH * K1P];
__device__ __half g_w1h[(size_t)INTER * K1P], g_w1l[(size_t)INTER * K1P];
__device__ __half g_hh16[(size_t)BATCH * INTER], g_hl16[(size_t)BATCH * INTER];
__device__ __half g_w2h16[(size_t)CODE * INTER], g_w2l16[(size_t)CODE * INTER];
__device__ float  g_c[(size_t)BATCH * CODE];
__device__ __half g_w3t16[(size_t)CODE * INTER];
__device__ __half g_dh16[(size_t)BATCH * INTER], g_dl16[(size_t)BATCH * INTER];
__device__ __half g_w4h16[(size_t)N4P * INTER];
__device__ int    g_flag_cnt;
__device__ int    g_flag_rows[BATCH];
__device__ float  g_hfix[(size_t)BATCH * INTER];
__device__ int    g_cnt[BATCH];
__device__ int    g_idx[(size_t)BATCH * KNEUR];
__device__ float  g_val[(size_t)BATCH * KNEUR];

// ===========================================================================
// PTX helpers
// ===========================================================================
__device__ __forceinline__ uint32_t smem_u32(const void* p) {
    uint32_t a;
    asm("{ .reg .u64 t; cvta.to.shared.u64 t, %1; cvt.u32.u64 %0, t; }" : "=r"(a) : "l"(p));
    return a;
}
#define CP_ASYNC16(dst, src) \
    asm volatile("cp.async.cg.shared.global [%0], [%1], 16;" :: "r"(dst), "l"(src) : "memory")
#define CP_COMMIT()  asm volatile("cp.async.commit_group;" ::: "memory")
#define CP_WAIT(n)   asm volatile("cp.async.wait_group %0;" :: "n"(n) : "memory")

__device__ __forceinline__ void ldsm_x4(uint32_t& r0, uint32_t& r1, uint32_t& r2,
                                        uint32_t& r3, uint32_t addr) {
    asm volatile("ldmatrix.sync.aligned.m8n8.x4.shared.b16 {%0,%1,%2,%3}, [%4];"
        : "=r"(r0), "=r"(r1), "=r"(r2), "=r"(r3) : "r"(addr));
}
__device__ __forceinline__ void mma_fp16(float* c, const uint32_t* a, const uint32_t* b) {
    asm volatile("mma.sync.aligned.m16n8k16.row.col.f32.f16.f16.f32 "
        "{%0,%1,%2,%3}, {%4,%5,%6,%7}, {%8,%9}, {%0,%1,%2,%3};"
        : "+f"(c[0]), "+f"(c[1]), "+f"(c[2]), "+f"(c[3])
        : "r"(a[0]), "r"(a[1]), "r"(a[2]), "r"(a[3]), "r"(b[0]), "r"(b[1]));
}

#define ROWB    80
#define TILE_A  (128 * ROWB)     // A tile: 128 rows x 32 k
#define TILE_Bb (64 * ROWB)      // B tile: 64 rows x 32 k
#define SM_TILES 1024
// stage bytes: TERMS==3 -> 2A+2B, TERMS==2 -> 2A+1B
#define STAGE3 (2 * TILE_A + 2 * TILE_Bb)
#define STAGE2 (2 * TILE_A + 1 * TILE_Bb)
#define SMEM_HMMA3 (SM_TILES + 2 * STAGE3)
#define SMEM_HMMA2 (SM_TILES + 2 * STAGE2)

// ===========================================================================
// fp16 scaled-split GEMM, CTA tile 128x64, 2 CTAs/SM.
// Warp layout: 8 warps = 4(M) x 2(N); warp tile 32x32 (mf=2 x nf=4).
// TERMS=3: acc1=AhBh, acc2=AlBh+AhBl. TERMS=2: acc1=AhBh, acc2=AlBh.
// OUTMODE 0: fp32 out (guard n<Nvalid). OUTMODE 1: fp16 pair out.
// ===========================================================================
template<int OUTMODE, int TERMS>
__global__ __launch_bounds__(256, 2) void gemm_f16(
    const __half* __restrict__ A0, const __half* __restrict__ A1,
    const __half* __restrict__ B0, const __half* __restrict__ B1,
    const float* __restrict__ bias, float* __restrict__ Cf,
    __half* __restrict__ H0, __half* __restrict__ H1,
    int Kp, int Nvalid, int outStride)
{
    extern __shared__ char smem[];
    const int STAGE = (TERMS == 3) ? STAGE3 : STAGE2;
    const int NB = (TERMS == 3) ? 2 : 1;     // B tiles per stage
    const uint32_t sbase = smem_u32(smem) + SM_TILES;
    const int tid  = threadIdx.x;
    const int warp = tid >> 5, lane = tid & 31;
    const int wm = (warp >> 1) * 32;         // warp M offset (0,32,64,96)
    const int wn = (warp & 1) * 32;          // warp N offset (0,32)
    const int m0 = blockIdx.y * 128;
    const int n0 = blockIdx.x * 64;

    if (tid < 64) {
        int n = n0 + tid;
        ((float*)smem)[tid] = (n < Nvalid) ? bias[n] : 0.0f;
    }

    float acc1[2][4][4], acc2[2][4][4];
#pragma unroll
    for (int i = 0; i < 2; i++)
#pragma unroll
        for (int j = 0; j < 4; j++)
#pragma unroll
            for (int q = 0; q < 4; q++) { acc1[i][j][q] = 0.0f; acc2[i][j][q] = 0.0f; }

    const int nk = Kp / 32;

    auto load_stage = [&](int kc, int s) {
        const int k0 = kc * 32;
        const uint32_t stb = sbase + s * STAGE;
        // A tiles: 128 rows, 512 x 16B chunks each -> 2 per thread
#pragma unroll
        for (int t = 0; t < 2; t++) {
            const __half* base = (t == 0 ? A0 : A1) + (size_t)m0 * Kp;
#pragma unroll
            for (int i = 0; i < 2; i++) {
                int f = tid + i * 256;
                int row = f >> 2, c = f & 3;
                uint32_t dst = stb + t * TILE_A + row * ROWB + c * 16;
                CP_ASYNC16(dst, base + (size_t)row * Kp + k0 + c * 8);
            }
        }
        // B tiles: 64 rows, 256 x 16B chunks each -> 1 per thread
#pragma unroll
        for (int t = 0; t < NB; t++) {
            const __half* base = (t == 0 ? B0 : B1) + (size_t)n0 * Kp;
            int row = tid >> 2, c = tid & 3;
            uint32_t dst = stb + 2 * TILE_A + t * TILE_Bb + row * ROWB + c * 16;
            CP_ASYNC16(dst, base + (size_t)row * Kp + k0 + c * 8);
        }
        CP_COMMIT();
    };

    auto compute_stage = [&](int s) {
        const uint32_t stb = sbase + s * STAGE;
#pragma unroll
        for (int ks = 0; ks < 2; ks++) {
            uint32_t afr[2][2][4];
#pragma unroll
            for (int p = 0; p < 2; p++) {
                const uint32_t Ab = stb + p * TILE_A;
#pragma unroll
                for (int mf = 0; mf < 2; mf++) {
                    int row = wm + mf * 16 + (lane & 15);
                    uint32_t off = row * ROWB + ks * 32 + (lane >> 4) * 16;
                    ldsm_x4(afr[p][mf][0], afr[p][mf][1], afr[p][mf][2], afr[p][mf][3], Ab + off);
                }
            }
#pragma unroll
            for (int j = 0; j < NB; j++) {
                const uint32_t Bb = stb + 2 * TILE_A + j * TILE_Bb;
                uint32_t bfr[4][2];
#pragma unroll
                for (int p = 0; p < 2; p++) {
                    int g = lane >> 3, ri = lane & 7;
                    int row = wn + p * 16 + ((g >> 1) << 3) + ri;
                    uint32_t off = row * ROWB + (2 * ks + (g & 1)) * 16;
                    uint32_t t0, t1, t2, t3;
                    ldsm_x4(t0, t1, t2, t3, Bb + off);
                    bfr[p*2][0] = t0; bfr[p*2][1] = t1;
                    bfr[p*2+1][0] = t2; bfr[p*2+1][1] = t3;
                }
                if (j == 0) {
#pragma unroll
                    for (int mf = 0; mf < 2; mf++)
#pragma unroll
                        for (int nf = 0; nf < 4; nf++) {
                            mma_fp16(acc1[mf][nf], afr[0][mf], bfr[nf]);   // Ah*Bh
                            mma_fp16(acc2[mf][nf], afr[1][mf], bfr[nf]);   // Al*Bh
                        }
                } else {
#pragma unroll
                    for (int mf = 0; mf < 2; mf++)
#pragma unroll
                        for (int nf = 0; nf < 4; nf++)
                            mma_fp16(acc2[mf][nf], afr[0][mf], bfr[nf]);   // Ah*Bl
                }
            }
        }
    };

    load_stage(0, 0);
    for (int kc = 0; kc < nk; kc++) {
        if (kc + 1 < nk) { load_stage(kc + 1, (kc + 1) & 1); CP_WAIT(1); }
        else             { CP_WAIT(0); }
        __syncthreads();
        compute_stage(kc & 1);
        __syncthreads();
    }

    const float* bs = (const float*)smem;
    const float INV = 1.0f / 2048.0f;
    const int lr = lane >> 2;
    const int lc = (lane & 3) * 2;
#pragma unroll
    for (int mf = 0; mf < 2; mf++) {
#pragma unroll
        for (int nf = 0; nf < 4; nf++) {
            int nrel = wn + nf * 8 + lc;
            int n = n0 + nrel;
            float b0 = bs[nrel], b1 = bs[nrel + 1];
#pragma unroll
            for (int half = 0; half < 2; half++) {
                int m = m0 + wm + mf * 16 + lr + half * 8;
                float v0 = fmaxf(fmaf(acc2[mf][nf][half*2+0], INV, acc1[mf][nf][half*2+0]) + b0, 0.0f);
                float v1 = fmaxf(fmaf(acc2[mf][nf][half*2+1], INV, acc1[mf][nf][half*2+1]) + b1, 0.0f);
                if (OUTMODE == 0) {
                    if (n < Nvalid)
                        *(float2*)(Cf + (size_t)m * outStride + n) = make_float2(v0, v1);
                } else {
                    __half h0 = __float2half_rn(v0), h1 = __float2half_rn(v1);
                    __half2 hh = __halves2half2(h0, h1);
                    __half2 ll = __halves2half2(
                        __float2half_rn((v0 - __half2float(h0)) * 2048.0f),
                        __float2half_rn((v1 - __half2float(h1)) * 2048.0f));
                    *(__half2*)(H0 + (size_t)m * outStride + n) = hh;
                    *(__half2*)(H1 + (size_t)m * outStride + n) = ll;
                }
            }
        }
    }
}

// ---------------------------------------------------------------------------
// prep kernels
// ---------------------------------------------------------------------------
__global__ __launch_bounds__(256) void split16_pad(
    const float* __restrict__ src, __half* __restrict__ H, __half* __restrict__ L,
    int srows, int scols, int orows, int ocols)
{
    size_t i = (size_t)blockIdx.x * blockDim.x + threadIdx.x;
    size_t tot = (size_t)orows * ocols;
    if (i >= tot) return;
    int r = (int)(i / ocols), c = (int)(i % ocols);
    float v = (r < srows && c < scols) ? src[(size_t)r * scols + c] : 0.0f;
    __half h = __float2half_rn(v);
    H[i] = h;
    L[i] = __float2half_rn((v - __half2float(h)) * 2048.0f);
}

__global__ __launch_bounds__(256) void convert16_pad(
    const float* __restrict__ src, __half* __restrict__ H,
    int srows, int scols, int orows, int ocols)
{
    size_t i = (size_t)blockIdx.x * blockDim.x + threadIdx.x;
    size_t tot = (size_t)orows * ocols;
    if (i >= tot) return;
    int r = (int)(i / ocols), c = (int)(i % ocols);
    float v = (r < srows && c < scols) ? src[(size_t)r * scols + c] : 0.0f;
    H[i] = __float2half_rn(v);
}

__global__ void transpose_w3(const float* __restrict__ W3, __half* __restrict__ W3T)
{
    __shared__ float t[32][33];
    int bx = blockIdx.x * 32;
    int by = blockIdx.y * 32;
    for (int i = threadIdx.y; i < 32; i += 8)
        t[i][threadIdx.x] = W3[(size_t)(by + i) * CODE + bx + threadIdx.x];
    __syncthreads();
    for (int i = threadIdx.y; i < 32; i += 8)
        W3T[(size_t)(bx + i) * INTER + by + threadIdx.x] = __float2half_rn(t[threadIdx.x][i]);
}

// ---------------------------------------------------------------------------
// topk body (validated)
// ---------------------------------------------------------------------------
struct TopkSmem {
    unsigned int hist[256];
    unsigned int eqscan[256];
    float psum[256];
    float bmaxs[256];
    float ssum[NSTRIPE];
    float smask[NSTRIPE];
    unsigned int s_prefix, s_remk, s_total;
};

__device__ __forceinline__ void topk_body(
    TopkSmem& S, const float* __restrict__ C, int row, bool flagmode)
{
    const int tid = threadIdx.x;
    const float* crow = C + (size_t)row * CODE;

    float f[8];
    *(float4*)&f[0] = *(const float4*)(crow + tid * 8);
    *(float4*)&f[4] = *(const float4*)(crow + tid * 8 + 4);
    unsigned int u[8];
#pragma unroll
    for (int j = 0; j < 8; j++) u[j] = __float_as_uint(f[j]);

    if (tid == 0) { S.s_prefix = 0; S.s_remk = KNEUR; }
    __syncthreads();

#pragma unroll
    for (int pass = 0; pass < 4; pass++) {
        const int shift = 24 - pass * 8;
        const unsigned int pm = (pass == 0) ? 0u : (0xFFFFFFFFu << (shift + 8));
        S.hist[tid] = 0;
        __syncthreads();
        unsigned int pref = S.s_prefix;
#pragma unroll
        for (int j = 0; j < 8; j++)
            if ((u[j] & pm) == pref) atomicAdd(&S.hist[(u[j] >> shift) & 0xFF], 1u);
        __syncthreads();
        if (tid == 0) {
            unsigned int remk = S.s_remk, acc = 0;
            int b = 255;
            for (; b > 0; b--) { acc += S.hist[b]; if (acc >= remk) break; }
            if (acc < remk) acc += S.hist[0];
            S.s_prefix = pref | ((unsigned int)b << shift);
            S.s_remk = remk - (acc - S.hist[b]);
        }
        __syncthreads();
    }

    const unsigned int t = S.s_prefix;
    const unsigned int need_eq = S.s_remk;

    unsigned int cnt = 0;
    float bmax = 0.0f;
#pragma unroll
    for (int j = 0; j < 8; j++) {
        cnt += (u[j] == t);
        if (u[j] < t) bmax = fmaxf(bmax, f[j]);
    }
    S.eqscan[tid] = cnt;
    S.bmaxs[tid] = bmax;
    __syncthreads();
    if (tid == 0) {
        unsigned int run = 0;
        for (int i = 0; i < 256; i++) { unsigned int v = S.eqscan[i]; S.eqscan[i] = run; run += v; }
        S.s_total = run;
    }
#pragma unroll
    for (int off = 128; off > 0; off >>= 1) {
        __syncthreads();
        if (tid < off) S.bmaxs[tid] = fmaxf(S.bmaxs[tid], S.bmaxs[tid + off]);
    }
    __syncthreads();

    unsigned int rank = S.eqscan[tid];
    float part = 0.0f;
#pragma unroll
    for (int j = 0; j < 8; j++) {
        bool keep;
        if (u[j] > t) keep = true;
        else if (u[j] == t) { keep = (rank < need_eq); rank++; }
        else keep = false;
        if (!keep) f[j] = 0.0f;
        part += f[j];
    }
    S.psum[tid] = part;
    __syncthreads();

    if (tid < NSTRIPE) {
        float s = 0.0f;
#pragma unroll
        for (int i = 0; i < 8; i++) s += S.psum[tid * 8 + i];
        S.ssum[tid] = s;
    }
    __syncthreads();

    if (tid == 0) {
        bool sel[NSTRIPE];
#pragma unroll
        for (int s = 0; s < NSTRIPE; s++) sel[s] = false;
        float v4 = 0.0f, v5 = 0.0f;
        for (int it = 0; it < KSTRIPE + 1; it++) {
            int best = -1; float bv = -1.0f;
            for (int s = 0; s < NSTRIPE; s++)
                if (!sel[s] && S.ssum[s] > bv) { bv = S.ssum[s]; best = s; }
            if (it < KSTRIPE) { sel[best] = true; if (it == KSTRIPE - 1) v4 = bv; }
            else v5 = bv;
        }
#pragma unroll
        for (int s = 0; s < NSTRIPE; s++) S.smask[s] = sel[s] ? 1.0f : 0.0f;

        if (flagmode) {
            float gap_n = __uint_as_float(t) - S.bmaxs[0];
            if (need_eq < S.s_total) gap_n = 0.0f;
            float gap_s = v4 - v5;
            if (gap_n < TAU1 || gap_s < TAU2) {
                int ix = atomicAdd(&g_flag_cnt, 1);
                g_flag_rows[ix] = row;
            }
        }
    }
    __syncthreads();

    const float sm = S.smask[tid >> 3];
    float mv[8];
    unsigned int myc = 0;
#pragma unroll
    for (int j = 0; j < 8; j++) { mv[j] = f[j] * sm; myc += (mv[j] != 0.0f); }
    S.eqscan[tid] = myc;
    __syncthreads();
    if (tid == 0) {
        unsigned int run = 0;
        for (int i = 0; i < 256; i++) { unsigned int v = S.eqscan[i]; S.eqscan[i] = run; run += v; }
        g_cnt[row] = (int)run;
    }
    __syncthreads();
    int base = (int)S.eqscan[tid];
    const int gb = row * KNEUR;
#pragma unroll
    for (int j = 0; j < 8; j++) {
        if (mv[j] != 0.0f) {
            g_idx[gb + base] = tid * 8 + j;
            g_val[gb + base] = mv[j];
            base++;
        }
    }
}

__global__ __launch_bounds__(256) void topk_flag_kernel(const float* __restrict__ C)
{
    __shared__ TopkSmem S;
    topk_body(S, C, blockIdx.x, true);
}

__global__ __launch_bounds__(256) void reset_cnt_kernel()
{
    if (threadIdx.x == 0 && blockIdx.x == 0) g_flag_cnt = 0;
}

// ---------------------------------------------------------------------------
// Batched fix GEMVs (validated R13)
// ---------------------------------------------------------------------------
#define FGROUP 16

__global__ __launch_bounds__(256) void h_fix_kernel(
    const float* __restrict__ x, const float* __restrict__ W1,
    const float* __restrict__ b1)
{
    extern __shared__ float xs[];
    const int tid = threadIdx.x;
    const int lane = tid & 31, warp = tid >> 5;
    const int nf = g_flag_cnt;
    const int ngroup = (nf + FGROUP - 1) / FGROUP;
    const int ntask = ngroup * 2;

    for (int task = blockIdx.x; task < ntask; task += gridDim.x) {
        const int grp = task >> 1, half = task & 1;
        const int base = grp * FGROUP;
        const int nrows = min(FGROUP, nf - base);
        __syncthreads();
        for (int r = 0; r < nrows; r++) {
            int row = g_flag_rows[base + r];
            for (int k = tid; k < IN_DIM; k += 256)
                xs[r * IN_DIM + k] = x[(size_t)row * IN_DIM + k];
        }
        __syncthreads();

        for (int jg = 0; jg < 16; jg++) {
            const int j0 = half * 512 + warp * 64 + jg * 4;
            const float4* w0 = (const float4*)(W1 + (size_t)(j0 + 0) * IN_DIM);
            const float4* w1 = (const float4*)(W1 + (size_t)(j0 + 1) * IN_DIM);
            const float4* w2 = (const float4*)(W1 + (size_t)(j0 + 2) * IN_DIM);
            const float4* w3 = (const float4*)(W1 + (size_t)(j0 + 3) * IN_DIM);
            float acc[FGROUP][4];
#pragma unroll
            for (int r = 0; r < FGROUP; r++)
#pragma unroll
                for (int q = 0; q < 4; q++) acc[r][q] = 0.0f;

            for (int kk = lane; kk < IN_DIM / 4; kk += 32) {
                float4 a = w0[kk], b = w1[kk], c = w2[kk], d = w3[kk];
#pragma unroll
                for (int r = 0; r < FGROUP; r++) {
                    float4 xv = ((const float4*)(xs + r * IN_DIM))[kk];
                    acc[r][0] = fmaf(xv.x, a.x, fmaf(xv.y, a.y, fmaf(xv.z, a.z, fmaf(xv.w, a.w, acc[r][0]))));
                    acc[r][1] = fmaf(xv.x, b.x, fmaf(xv.y, b.y, fmaf(xv.z, b.z, fmaf(xv.w, b.w, acc[r][1]))));
                    acc[r][2] = fmaf(xv.x, c.x, fmaf(xv.y, c.y, fmaf(xv.z, c.z, fmaf(xv.w, c.w, acc[r][2]))));
                    acc[r][3] = fmaf(xv.x, d.x, fmaf(xv.y, d.y, fmaf(xv.z, d.z, fmaf(xv.w, d.w, acc[r][3]))));
                }
            }
#pragma unroll
            for (int r = 0; r < FGROUP; r++)
#pragma unroll
                for (int q = 0; q < 4; q++) {
                    float a = acc[r][q];
#pragma unroll
                    for (int o = 16; o > 0; o >>= 1)
                        a += __shfl_xor_sync(0xFFFFFFFFu, a, o);
                    if (lane == 0 && r < nrows)
                        g_hfix[(size_t)(base + r) * INTER + j0 + q] =
                            fmaxf(a + b1[j0 + q], 0.0f);
                }
        }
    }
}

__global__ __launch_bounds__(256) void fixup_exact_kernel(
    const float* __restrict__ W2, const float* __restrict__ b2, float* __restrict__ c)
{
    extern __shared__ float hs[];
    const int tid = threadIdx.x;
    const int lane = tid & 31, warp = tid >> 5;
    const int nf = g_flag_cnt;
    const int ngroup = (nf + FGROUP - 1) / FGROUP;
    const int ntask = ngroup * 4;

    for (int task = blockIdx.x; task < ntask; task += gridDim.x) {
        const int grp = task >> 2, quart = task & 3;
        const int base = grp * FGROUP;
        const int nrows = min(FGROUP, nf - base);
        __syncthreads();
        for (int r = 0; r < nrows; r++) {
            for (int k = tid; k < INTER; k += 256)
                hs[r * INTER + k] = g_hfix[(size_t)(base + r) * INTER + k];
        }
        __syncthreads();

        for (int jg = 0; jg < 16; jg++) {
            const int j0 = quart * 512 + warp * 64 + jg * 4;
            const float4* w0 = (const float4*)(W2 + (size_t)(j0 + 0) * INTER);
            const float4* w1 = (const float4*)(W2 + (size_t)(j0 + 1) * INTER);
            const float4* w2 = (const float4*)(W2 + (size_t)(j0 + 2) * INTER);
            const float4* w3 = (const float4*)(W2 + (size_t)(j0 + 3) * INTER);
            float acc[FGROUP][4];
#pragma unroll
            for (int r = 0; r < FGROUP; r++)
#pragma unroll
                for (int q = 0; q < 4; q++) acc[r][q] = 0.0f;

            for (int kk = lane; kk < INTER / 4; kk += 32) {
                float4 a = w0[kk], b = w1[kk], cc = w2[kk], d = w3[kk];
#pragma unroll
                for (int r = 0; r < FGROUP; r++) {
                    float4 hv = ((const float4*)(hs + r * INTER))[kk];
                    acc[r][0] = fmaf(hv.x, a.x, fmaf(hv.y, a.y, fmaf(hv.z, a.z, fmaf(hv.w, a.w, acc[r][0]))));
                    acc[r][1] = fmaf(hv.x, b.x, fmaf(hv.y, b.y, fmaf(hv.z, b.z, fmaf(hv.w, b.w, acc[r][1]))));
                    acc[r][2] = fmaf(hv.x, cc.x, fmaf(hv.y, cc.y, fmaf(hv.z, cc.z, fmaf(hv.w, cc.w, acc[r][2]))));
                    acc[r][3] = fmaf(hv.x, d.x, fmaf(hv.y, d.y, fmaf(hv.z, d.z, fmaf(hv.w, d.w, acc[r][3]))));
                }
            }
#pragma unroll
            for (int r = 0; r < FGROUP; r++)
#pragma unroll
                for (int q = 0; q < 4; q++) {
                    float a = acc[r][q];
#pragma unroll
                    for (int o = 16; o > 0; o >>= 1)
                        a += __shfl_xor_sync(0xFFFFFFFFu, a, o);
                    if (lane == 0 && r < nrows) {
                        int row = g_flag_rows[base + r];
                        c[(size_t)row * CODE + j0 + q] = fmaxf(a + b2[j0 + q], 0.0f);
                    }
                }
        }
    }
}

__global__ __launch_bounds__(256) void fixup_topk_kernel(const float* __restrict__ C)
{
    __shared__ TopkSmem S;
    const int nf = g_flag_cnt;
    for (int i = blockIdx.x; i < nf; i += gridDim.x) {
        topk_body(S, C, g_flag_rows[i], false);
        __syncthreads();
    }
}

// ---------------------------------------------------------------------------
// L3: sparse row-gather GEMV, fp16 weights, fp32 accum -> d fp16 pair
// ---------------------------------------------------------------------------
__global__ __launch_bounds__(256) void l3_gather(
    const __half* __restrict__ W3T, const float* __restrict__ b3,
    __half* __restrict__ D0, __half* __restrict__ D1)
{
    __shared__ float sval[KNEUR];
    __shared__ int   sidx[KNEUR];
    const int row = blockIdx.x, tid = threadIdx.x;
    const int cnt = g_cnt[row];
    if (tid < KNEUR && tid < cnt) {
        sidx[tid] = g_idx[row * KNEUR + tid];
        sval[tid] = g_val[row * KNEUR + tid];
    }
    __syncthreads();

    const int n = tid * 4;
    float4 acc = *(const float4*)(b3 + n);
    int j = 0;
    for (; j + 4 <= cnt; j += 4) {
#pragma unroll
        for (int q = 0; q < 4; q++) {
            const __half2* wp = (const __half2*)(W3T + (size_t)sidx[j + q] * INTER + n);
            float2 lo = __half22float2(wp[0]);
            float2 hi = __half22float2(wp[1]);
            const float v = sval[j + q];
            acc.x = fmaf(v, lo.x, acc.x); acc.y = fmaf(v, lo.y, acc.y);
            acc.z = fmaf(v, hi.x, acc.z); acc.w = fmaf(v, hi.y, acc.w);
        }
    }
    for (; j < cnt; j++) {
        const __half2* wp = (const __half2*)(W3T + (size_t)sidx[j] * INTER + n);
        float2 lo = __half22float2(wp[0]);
        float2 hi = __half22float2(wp[1]);
        const float v = sval[j];
        acc.x = fmaf(v, lo.x, acc.x); acc.y = fmaf(v, lo.y, acc.y);
        acc.z = fmaf(v, hi.x, acc.z); acc.w = fmaf(v, hi.y, acc.w);
    }

    acc.x = fmaxf(acc.x, 0.0f); acc.y = fmaxf(acc.y, 0.0f);
    acc.z = fmaxf(acc.z, 0.0f); acc.w = fmaxf(acc.w, 0.0f);

    __half h0 = __float2half_rn(acc.x), h1 = __float2half_rn(acc.y);
    __half h2 = __float2half_rn(acc.z), h3 = __float2half_rn(acc.w);
    __half2 hh0 = __halves2half2(h0, h1), hh1 = __halves2half2(h2, h3);
    __half2 ll0 = __halves2half2(
        __float2half_rn((acc.x - __half2float(h0)) * 2048.0f),
        __float2half_rn((acc.y - __half2float(h1)) * 2048.0f));
    __half2 ll1 = __halves2half2(
        __float2half_rn((acc.z - __half2float(h2)) * 2048.0f),
        __float2half_rn((acc.w - __half2float(h3)) * 2048.0f));
    *(__half2*)(D0 + (size_t)row * INTER + n)     = hh0;
    *(__half2*)(D0 + (size_t)row * INTER + n + 2) = hh1;
    *(__half2*)(D1 + (size_t)row * INTER + n)     = ll0;
    *(__half2*)(D1 + (size_t)row * INTER + n + 2) = ll1;
}

// ---------------------------------------------------------------------------
extern "C" void kernel_launch(void* const* d_in, const int* in_sizes, int n_in,
                              void* d_out, int out_size)
{
    const float* x  = (const float*)d_in[0];
    const float* W1 = (const float*)d_in[1];
    const float* b1 = (const float*)d_in[2];
    const float* W2 = (const float*)d_in[3];
    const float* b2 = (const float*)d_in[4];
    const float* W3 = (const float*)d_in[5];
    const float* b3 = (const float*)d_in[6];
    const float* W4 = (const float*)d_in[7];
    const float* b4 = (const float*)d_in[8];
    float* out = (float*)d_out;

    float* c;
    __half *x0, *x1, *w1h, *w1l, *hh16, *hl16, *w2h16, *w2l16;
    __half *w3t16, *dh16, *dl16, *w4h16;
    cudaGetSymbolAddress((void**)&c, g_c);
    cudaGetSymbolAddress((void**)&x0, g_x0);       cudaGetSymbolAddress((void**)&x1, g_x1);
    cudaGetSymbolAddress((void**)&w1h, g_w1h);     cudaGetSymbolAddress((void**)&w1l, g_w1l);
    cudaGetSymbolAddress((void**)&hh16, g_hh16);   cudaGetSymbolAddress((void**)&hl16, g_hl16);
    cudaGetSymbolAddress((void**)&w2h16, g_w2h16); cudaGetSymbolAddress((void**)&w2l16, g_w2l16);
    cudaGetSymbolAddress((void**)&w3t16, g_w3t16);
    cudaGetSymbolAddress((void**)&dh16, g_dh16);   cudaGetSymbolAddress((void**)&dl16, g_dl16);
    cudaGetSymbolAddress((void**)&w4h16, g_w4h16);

    cudaFuncSetAttribute(gemm_f16<0,3>, cudaFuncAttributeMaxDynamicSharedMemorySize, SMEM_HMMA3);
    cudaFuncSetAttribute(gemm_f16<1,3>, cudaFuncAttributeMaxDynamicSharedMemorySize, SMEM_HMMA3);
    cudaFuncSetAttribute(gemm_f16<0,2>, cudaFuncAttributeMaxDynamicSharedMemorySize, SMEM_HMMA2);
    cudaFuncSetAttribute(h_fix_kernel, cudaFuncAttributeMaxDynamicSharedMemorySize,
                         FGROUP * IN_DIM * (int)sizeof(float));
    cudaFuncSetAttribute(fixup_exact_kernel, cudaFuncAttributeMaxDynamicSharedMemorySize,
                         FGROUP * INTER * (int)sizeof(float));

    auto gs = [](size_t n) { return (unsigned)((n + 255) / 256); };

    // prep
    split16_pad<<<gs((size_t)BATCH * K1P), 256>>>(x,  x0,  x1,  BATCH, IN_DIM, BATCH, K1P);
    split16_pad<<<gs((size_t)INTER * K1P), 256>>>(W1, w1h, w1l, INTER, IN_DIM, INTER, K1P);
    split16_pad<<<gs((size_t)CODE * INTER), 256>>>(W2, w2h16, w2l16, CODE, INTER, CODE, INTER);
    convert16_pad<<<gs((size_t)N4P * INTER), 256>>>(W4, w4h16, IN_DIM, INTER, N4P, INTER);
    transpose_w3<<<dim3(CODE / 32, INTER / 32), dim3(32, 8)>>>(W3, w3t16);

    // L1: 3-term fp16 HMMA -> h pair
    gemm_f16<1,3><<<dim3(INTER / 64, BATCH / 128), 256, SMEM_HMMA3>>>(
        x0, x1, w1h, w1l, b1, nullptr, hh16, hl16, K1P, INTER, INTER);

    // L2: 3-term fp16 HMMA -> c fp32
    gemm_f16<0,3><<<dim3(CODE / 64, BATCH / 128), 256, SMEM_HMMA3>>>(
        hh16, hl16, w2h16, w2l16, b2, c, nullptr, nullptr, INTER, CODE, CODE);

    // topk + margins + batched exact fixup
    reset_cnt_kernel<<<1, 32>>>();
    topk_flag_kernel<<<BATCH, 256>>>(c);
    h_fix_kernel<<<512, 256, FGROUP * IN_DIM * sizeof(float)>>>(x, W1, b1);
    fixup_exact_kernel<<<1024, 256, FGROUP * INTER * sizeof(float)>>>(W2, b2, c);
    fixup_topk_kernel<<<1024, 256>>>(c);

    // L3 sparse gather -> d fp16 pair
    l3_gather<<<BATCH, 256>>>(w3t16, b3, dh16, dl16);

    // L4: 2-term fp16 HMMA -> out fp32
    gemm_f16<0,2><<<dim3(N4P / 64, BATCH / 128), 256, SMEM_HMMA2>>>(
        dh16, dl16, w4h16, nullptr, b4, out, nullptr, nullptr, INTER, IN_DIM, IN_DIM);
}

// round 17
// speedup vs baseline: 2.7214x; 1.2274x over previous
#include <cuda_runtime.h>
#include <cuda_bf16.h>
#include <cuda_fp16.h>
#include <cstdint>

// ---------------------------------------------------------------------------
// Net_46368466928157 — round 16:
//   R15 structure; topk_body serial scans replaced with parallel
//   Hillis-Steele scans (integer-exact -> identical selections).
// ---------------------------------------------------------------------------

#define BATCH   16384
#define IN_DIM  784
#define K1P     800
#define INTER   1024
#define CODE    2048
#define N4P     896
#define NSTRIPE 32
#define KNEUR   64
#define KSTRIPE 4

#define TAU1 2.5e-5f
#define TAU2 2e-3f

// ---- scratch --------------------------------------------------------------
__device__ __half g_x0[(size_t)BATCH * K1P],  g_x1[(size_t)BATCH * K1P];
__device__ __half g_w1h[(size_t)INTER * K1P], g_w1l[(size_t)INTER * K1P];
__device__ __half g_hh16[(size_t)BATCH * INTER], g_hl16[(size_t)BATCH * INTER];
__device__ __half g_w2h16[(size_t)CODE * INTER], g_w2l16[(size_t)CODE * INTER];
__device__ float  g_c[(size_t)BATCH * CODE];
__device__ __half g_w3t16[(size_t)CODE * INTER];
__device__ __half g_dh16[(size_t)BATCH * INTER], g_dl16[(size_t)BATCH * INTER];
__device__ __half g_w4h16[(size_t)N4P * INTER];
__device__ int    g_flag_cnt;
__device__ int    g_flag_rows[BATCH];
__device__ float  g_hfix[(size_t)BATCH * INTER];
__device__ int    g_cnt[BATCH];
__device__ int    g_idx[(size_t)BATCH * KNEUR];
__device__ float  g_val[(size_t)BATCH * KNEUR];

// ===========================================================================
// PTX helpers
// ===========================================================================
__device__ __forceinline__ uint32_t smem_u32(const void* p) {
    uint32_t a;
    asm("{ .reg .u64 t; cvta.to.shared.u64 t, %1; cvt.u32.u64 %0, t; }" : "=r"(a) : "l"(p));
    return a;
}
#define CP_ASYNC16(dst, src) \
    asm volatile("cp.async.cg.shared.global [%0], [%1], 16;" :: "r"(dst), "l"(src) : "memory")
#define CP_COMMIT()  asm volatile("cp.async.commit_group;" ::: "memory")
#define CP_WAIT(n)   asm volatile("cp.async.wait_group %0;" :: "n"(n) : "memory")

__device__ __forceinline__ void ldsm_x4(uint32_t& r0, uint32_t& r1, uint32_t& r2,
                                        uint32_t& r3, uint32_t addr) {
    asm volatile("ldmatrix.sync.aligned.m8n8.x4.shared.b16 {%0,%1,%2,%3}, [%4];"
        : "=r"(r0), "=r"(r1), "=r"(r2), "=r"(r3) : "r"(addr));
}
__device__ __forceinline__ void mma_fp16(float* c, const uint32_t* a, const uint32_t* b) {
    asm volatile("mma.sync.aligned.m16n8k16.row.col.f32.f16.f16.f32 "
        "{%0,%1,%2,%3}, {%4,%5,%6,%7}, {%8,%9}, {%0,%1,%2,%3};"
        : "+f"(c[0]), "+f"(c[1]), "+f"(c[2]), "+f"(c[3])
        : "r"(a[0]), "r"(a[1]), "r"(a[2]), "r"(a[3]), "r"(b[0]), "r"(b[1]));
}

#define ROWB    80
#define TILE_A  (128 * ROWB)
#define TILE_Bb (64 * ROWB)
#define SM_TILES 1024
#define STAGE3 (2 * TILE_A + 2 * TILE_Bb)
#define STAGE2 (2 * TILE_A + 1 * TILE_Bb)
#define SMEM_HMMA3 (SM_TILES + 2 * STAGE3)
#define SMEM_HMMA2 (SM_TILES + 2 * STAGE2)

// ===========================================================================
// fp16 scaled-split GEMM, CTA tile 128x64, 2 CTAs/SM (validated R15).
// ===========================================================================
template<int OUTMODE, int TERMS>
__global__ __launch_bounds__(256, 2) void gemm_f16(
    const __half* __restrict__ A0, const __half* __restrict__ A1,
    const __half* __restrict__ B0, const __half* __restrict__ B1,
    const float* __restrict__ bias, float* __restrict__ Cf,
    __half* __restrict__ H0, __half* __restrict__ H1,
    int Kp, int Nvalid, int outStride)
{
    extern __shared__ char smem[];
    const int STAGE = (TERMS == 3) ? STAGE3 : STAGE2;
    const int NB = (TERMS == 3) ? 2 : 1;
    const uint32_t sbase = smem_u32(smem) + SM_TILES;
    const int tid  = threadIdx.x;
    const int warp = tid >> 5, lane = tid & 31;
    const int wm = (warp >> 1) * 32;
    const int wn = (warp & 1) * 32;
    const int m0 = blockIdx.y * 128;
    const int n0 = blockIdx.x * 64;

    if (tid < 64) {
        int n = n0 + tid;
        ((float*)smem)[tid] = (n < Nvalid) ? bias[n] : 0.0f;
    }

    float acc1[2][4][4], acc2[2][4][4];
#pragma unroll
    for (int i = 0; i < 2; i++)
#pragma unroll
        for (int j = 0; j < 4; j++)
#pragma unroll
            for (int q = 0; q < 4; q++) { acc1[i][j][q] = 0.0f; acc2[i][j][q] = 0.0f; }

    const int nk = Kp / 32;

    auto load_stage = [&](int kc, int s) {
        const int k0 = kc * 32;
        const uint32_t stb = sbase + s * STAGE;
#pragma unroll
        for (int t = 0; t < 2; t++) {
            const __half* base = (t == 0 ? A0 : A1) + (size_t)m0 * Kp;
#pragma unroll
            for (int i = 0; i < 2; i++) {
                int f = tid + i * 256;
                int row = f >> 2, c = f & 3;
                uint32_t dst = stb + t * TILE_A + row * ROWB + c * 16;
                CP_ASYNC16(dst, base + (size_t)row * Kp + k0 + c * 8);
            }
        }
#pragma unroll
        for (int t = 0; t < NB; t++) {
            const __half* base = (t == 0 ? B0 : B1) + (size_t)n0 * Kp;
            int row = tid >> 2, c = tid & 3;
            uint32_t dst = stb + 2 * TILE_A + t * TILE_Bb + row * ROWB + c * 16;
            CP_ASYNC16(dst, base + (size_t)row * Kp + k0 + c * 8);
        }
        CP_COMMIT();
    };

    auto compute_stage = [&](int s) {
        const uint32_t stb = sbase + s * STAGE;
#pragma unroll
        for (int ks = 0; ks < 2; ks++) {
            uint32_t afr[2][2][4];
#pragma unroll
            for (int p = 0; p < 2; p++) {
                const uint32_t Ab = stb + p * TILE_A;
#pragma unroll
                for (int mf = 0; mf < 2; mf++) {
                    int row = wm + mf * 16 + (lane & 15);
                    uint32_t off = row * ROWB + ks * 32 + (lane >> 4) * 16;
                    ldsm_x4(afr[p][mf][0], afr[p][mf][1], afr[p][mf][2], afr[p][mf][3], Ab + off);
                }
            }
#pragma unroll
            for (int j = 0; j < NB; j++) {
                const uint32_t Bb = stb + 2 * TILE_A + j * TILE_Bb;
                uint32_t bfr[4][2];
#pragma unroll
                for (int p = 0; p < 2; p++) {
                    int g = lane >> 3, ri = lane & 7;
                    int row = wn + p * 16 + ((g >> 1) << 3) + ri;
                    uint32_t off = row * ROWB + (2 * ks + (g & 1)) * 16;
                    uint32_t t0, t1, t2, t3;
                    ldsm_x4(t0, t1, t2, t3, Bb + off);
                    bfr[p*2][0] = t0; bfr[p*2][1] = t1;
                    bfr[p*2+1][0] = t2; bfr[p*2+1][1] = t3;
                }
                if (j == 0) {
#pragma unroll
                    for (int mf = 0; mf < 2; mf++)
#pragma unroll
                        for (int nf = 0; nf < 4; nf++) {
                            mma_fp16(acc1[mf][nf], afr[0][mf], bfr[nf]);
                            mma_fp16(acc2[mf][nf], afr[1][mf], bfr[nf]);
                        }
                } else {
#pragma unroll
                    for (int mf = 0; mf < 2; mf++)
#pragma unroll
                        for (int nf = 0; nf < 4; nf++)
                            mma_fp16(acc2[mf][nf], afr[0][mf], bfr[nf]);
                }
            }
        }
    };

    load_stage(0, 0);
    for (int kc = 0; kc < nk; kc++) {
        if (kc + 1 < nk) { load_stage(kc + 1, (kc + 1) & 1); CP_WAIT(1); }
        else             { CP_WAIT(0); }
        __syncthreads();
        compute_stage(kc & 1);
        __syncthreads();
    }

    const float* bs = (const float*)smem;
    const float INV = 1.0f / 2048.0f;
    const int lr = lane >> 2;
    const int lc = (lane & 3) * 2;
#pragma unroll
    for (int mf = 0; mf < 2; mf++) {
#pragma unroll
        for (int nf = 0; nf < 4; nf++) {
            int nrel = wn + nf * 8 + lc;
            int n = n0 + nrel;
            float b0 = bs[nrel], b1 = bs[nrel + 1];
#pragma unroll
            for (int half = 0; half < 2; half++) {
                int m = m0 + wm + mf * 16 + lr + half * 8;
                float v0 = fmaxf(fmaf(acc2[mf][nf][half*2+0], INV, acc1[mf][nf][half*2+0]) + b0, 0.0f);
                float v1 = fmaxf(fmaf(acc2[mf][nf][half*2+1], INV, acc1[mf][nf][half*2+1]) + b1, 0.0f);
                if (OUTMODE == 0) {
                    if (n < Nvalid)
                        *(float2*)(Cf + (size_t)m * outStride + n) = make_float2(v0, v1);
                } else {
                    __half h0 = __float2half_rn(v0), h1 = __float2half_rn(v1);
                    __half2 hh = __halves2half2(h0, h1);
                    __half2 ll = __halves2half2(
                        __float2half_rn((v0 - __half2float(h0)) * 2048.0f),
                        __float2half_rn((v1 - __half2float(h1)) * 2048.0f));
                    *(__half2*)(H0 + (size_t)m * outStride + n) = hh;
                    *(__half2*)(H1 + (size_t)m * outStride + n) = ll;
                }
            }
        }
    }
}

// ---------------------------------------------------------------------------
// prep kernels
// ---------------------------------------------------------------------------
__global__ __launch_bounds__(256) void split16_pad(
    const float* __restrict__ src, __half* __restrict__ H, __half* __restrict__ L,
    int srows, int scols, int orows, int ocols)
{
    size_t i = (size_t)blockIdx.x * blockDim.x + threadIdx.x;
    size_t tot = (size_t)orows * ocols;
    if (i >= tot) return;
    int r = (int)(i / ocols), c = (int)(i % ocols);
    float v = (r < srows && c < scols) ? src[(size_t)r * scols + c] : 0.0f;
    __half h = __float2half_rn(v);
    H[i] = h;
    L[i] = __float2half_rn((v - __half2float(h)) * 2048.0f);
}

__global__ __launch_bounds__(256) void convert16_pad(
    const float* __restrict__ src, __half* __restrict__ H,
    int srows, int scols, int orows, int ocols)
{
    size_t i = (size_t)blockIdx.x * blockDim.x + threadIdx.x;
    size_t tot = (size_t)orows * ocols;
    if (i >= tot) return;
    int r = (int)(i / ocols), c = (int)(i % ocols);
    float v = (r < srows && c < scols) ? src[(size_t)r * scols + c] : 0.0f;
    H[i] = __float2half_rn(v);
}

__global__ void transpose_w3(const float* __restrict__ W3, __half* __restrict__ W3T)
{
    __shared__ float t[32][33];
    int bx = blockIdx.x * 32;
    int by = blockIdx.y * 32;
    for (int i = threadIdx.y; i < 32; i += 8)
        t[i][threadIdx.x] = W3[(size_t)(by + i) * CODE + bx + threadIdx.x];
    __syncthreads();
    for (int i = threadIdx.y; i < 32; i += 8)
        W3T[(size_t)(bx + i) * INTER + by + threadIdx.x] = __float2half_rn(t[threadIdx.x][i]);
}

// ---------------------------------------------------------------------------
// topk body — parallel scans (integer-exact; selections identical to R15)
// ---------------------------------------------------------------------------
struct TopkSmem {
    unsigned int hist[256];
    unsigned int eqscan[256];
    float psum[256];
    float bmaxs[256];
    float ssum[NSTRIPE];
    float smask[NSTRIPE];
    unsigned int s_prefix, s_remk, s_total;
};

__device__ __forceinline__ void topk_body(
    TopkSmem& S, const float* __restrict__ C, int row, bool flagmode)
{
    const int tid = threadIdx.x;
    const float* crow = C + (size_t)row * CODE;

    float f[8];
    *(float4*)&f[0] = *(const float4*)(crow + tid * 8);
    *(float4*)&f[4] = *(const float4*)(crow + tid * 8 + 4);
    unsigned int u[8];
#pragma unroll
    for (int j = 0; j < 8; j++) u[j] = __float_as_uint(f[j]);

    if (tid == 0) { S.s_prefix = 0; S.s_remk = KNEUR; }
    __syncthreads();

    // ---- 4-pass radix select; bucket pick via parallel suffix scan ----
#pragma unroll
    for (int pass = 0; pass < 4; pass++) {
        const int shift = 24 - pass * 8;
        const unsigned int pm = (pass == 0) ? 0u : (0xFFFFFFFFu << (shift + 8));
        S.hist[tid] = 0;
        __syncthreads();
        unsigned int pref = S.s_prefix;
        unsigned int remk = S.s_remk;
#pragma unroll
        for (int j = 0; j < 8; j++)
            if ((u[j] & pm) == pref) atomicAdd(&S.hist[(u[j] >> shift) & 0xFF], 1u);
        __syncthreads();
        // inclusive SUFFIX scan of hist (Hillis-Steele)
#pragma unroll
        for (int off = 1; off < 256; off <<= 1) {
            unsigned int v = S.hist[tid];
            unsigned int a = (tid + off < 256) ? S.hist[tid + off] : 0u;
            __syncthreads();
            S.hist[tid] = v + a;
            __syncthreads();
        }
        // pick b = max bucket with S[b] >= remk; remk' = remk - S[b+1]
        unsigned int Sb  = S.hist[tid];
        unsigned int Sb1 = (tid < 255) ? S.hist[tid + 1] : 0u;
        if (Sb >= remk && (tid == 255 || Sb1 < remk)) {
            S.s_prefix = pref | ((unsigned int)tid << shift);
            S.s_remk = remk - Sb1;
        }
        __syncthreads();
    }

    const unsigned int t = S.s_prefix;
    const unsigned int need_eq = S.s_remk;

    unsigned int cnt = 0;
    float bmax = 0.0f;
#pragma unroll
    for (int j = 0; j < 8; j++) {
        cnt += (u[j] == t);
        if (u[j] < t) bmax = fmaxf(bmax, f[j]);
    }
    S.eqscan[tid] = cnt;
    S.bmaxs[tid] = bmax;
    __syncthreads();
    // inclusive forward scan of equal-counts
#pragma unroll
    for (int off = 1; off < 256; off <<= 1) {
        unsigned int v = S.eqscan[tid];
        unsigned int a = (tid >= off) ? S.eqscan[tid - off] : 0u;
        __syncthreads();
        S.eqscan[tid] = v + a;
        __syncthreads();
    }
    unsigned int rank = S.eqscan[tid] - cnt;      // exclusive prefix
    if (tid == 0) S.s_total = S.eqscan[255];
    // bmax tree reduction
#pragma unroll
    for (int off = 128; off > 0; off >>= 1) {
        __syncthreads();
        if (tid < off) S.bmaxs[tid] = fmaxf(S.bmaxs[tid], S.bmaxs[tid + off]);
    }
    __syncthreads();

    float part = 0.0f;
#pragma unroll
    for (int j = 0; j < 8; j++) {
        bool keep;
        if (u[j] > t) keep = true;
        else if (u[j] == t) { keep = (rank < need_eq); rank++; }
        else keep = false;
        if (!keep) f[j] = 0.0f;
        part += f[j];
    }
    S.psum[tid] = part;
    __syncthreads();

    if (tid < NSTRIPE) {
        float s = 0.0f;
#pragma unroll
        for (int i = 0; i < 8; i++) s += S.psum[tid * 8 + i];
        S.ssum[tid] = s;
    }
    __syncthreads();

    if (tid == 0) {
        bool sel[NSTRIPE];
#pragma unroll
        for (int s = 0; s < NSTRIPE; s++) sel[s] = false;
        float v4 = 0.0f, v5 = 0.0f;
        for (int it = 0; it < KSTRIPE + 1; it++) {
            int best = -1; float bv = -1.0f;
            for (int s = 0; s < NSTRIPE; s++)
                if (!sel[s] && S.ssum[s] > bv) { bv = S.ssum[s]; best = s; }
            if (it < KSTRIPE) { sel[best] = true; if (it == KSTRIPE - 1) v4 = bv; }
            else v5 = bv;
        }
#pragma unroll
        for (int s = 0; s < NSTRIPE; s++) S.smask[s] = sel[s] ? 1.0f : 0.0f;

        if (flagmode) {
            float gap_n = __uint_as_float(t) - S.bmaxs[0];
            if (need_eq < S.s_total) gap_n = 0.0f;
            float gap_s = v4 - v5;
            if (gap_n < TAU1 || gap_s < TAU2) {
                int ix = atomicAdd(&g_flag_cnt, 1);
                g_flag_rows[ix] = row;
            }
        }
    }
    __syncthreads();

    // ---- compact (idx,val) emit: parallel scan for bases ----
    const float sm = S.smask[tid >> 3];
    float mv[8];
    unsigned int myc = 0;
#pragma unroll
    for (int j = 0; j < 8; j++) { mv[j] = f[j] * sm; myc += (mv[j] != 0.0f); }
    S.eqscan[tid] = myc;
    __syncthreads();
#pragma unroll
    for (int off = 1; off < 256; off <<= 1) {
        unsigned int v = S.eqscan[tid];
        unsigned int a = (tid >= off) ? S.eqscan[tid - off] : 0u;
        __syncthreads();
        S.eqscan[tid] = v + a;
        __syncthreads();
    }
    int base = (int)(S.eqscan[tid] - myc);        // exclusive
    if (tid == 0) g_cnt[row] = (int)S.eqscan[255];
    const int gb = row * KNEUR;
#pragma unroll
    for (int j = 0; j < 8; j++) {
        if (mv[j] != 0.0f) {
            g_idx[gb + base] = tid * 8 + j;
            g_val[gb + base] = mv[j];
            base++;
        }
    }
}

__global__ __launch_bounds__(256) void topk_flag_kernel(const float* __restrict__ C)
{
    __shared__ TopkSmem S;
    topk_body(S, C, blockIdx.x, true);
}

__global__ __launch_bounds__(256) void reset_cnt_kernel()
{
    if (threadIdx.x == 0 && blockIdx.x == 0) g_flag_cnt = 0;
}

// ---------------------------------------------------------------------------
// Batched fix GEMVs (validated R13)
// ---------------------------------------------------------------------------
#define FGROUP 16

__global__ __launch_bounds__(256) void h_fix_kernel(
    const float* __restrict__ x, const float* __restrict__ W1,
    const float* __restrict__ b1)
{
    extern __shared__ float xs[];
    const int tid = threadIdx.x;
    const int lane = tid & 31, warp = tid >> 5;
    const int nf = g_flag_cnt;
    const int ngroup = (nf + FGROUP - 1) / FGROUP;
    const int ntask = ngroup * 2;

    for (int task = blockIdx.x; task < ntask; task += gridDim.x) {
        const int grp = task >> 1, half = task & 1;
        const int base = grp * FGROUP;
        const int nrows = min(FGROUP, nf - base);
        __syncthreads();
        for (int r = 0; r < nrows; r++) {
            int row = g_flag_rows[base + r];
            for (int k = tid; k < IN_DIM; k += 256)
                xs[r * IN_DIM + k] = x[(size_t)row * IN_DIM + k];
        }
        __syncthreads();

        for (int jg = 0; jg < 16; jg++) {
            const int j0 = half * 512 + warp * 64 + jg * 4;
            const float4* w0 = (const float4*)(W1 + (size_t)(j0 + 0) * IN_DIM);
            const float4* w1 = (const float4*)(W1 + (size_t)(j0 + 1) * IN_DIM);
            const float4* w2 = (const float4*)(W1 + (size_t)(j0 + 2) * IN_DIM);
            const float4* w3 = (const float4*)(W1 + (size_t)(j0 + 3) * IN_DIM);
            float acc[FGROUP][4];
#pragma unroll
            for (int r = 0; r < FGROUP; r++)
#pragma unroll
                for (int q = 0; q < 4; q++) acc[r][q] = 0.0f;

            for (int kk = lane; kk < IN_DIM / 4; kk += 32) {
                float4 a = w0[kk], b = w1[kk], c = w2[kk], d = w3[kk];
#pragma unroll
                for (int r = 0; r < FGROUP; r++) {
                    float4 xv = ((const float4*)(xs + r * IN_DIM))[kk];
                    acc[r][0] = fmaf(xv.x, a.x, fmaf(xv.y, a.y, fmaf(xv.z, a.z, fmaf(xv.w, a.w, acc[r][0]))));
                    acc[r][1] = fmaf(xv.x, b.x, fmaf(xv.y, b.y, fmaf(xv.z, b.z, fmaf(xv.w, b.w, acc[r][1]))));
                    acc[r][2] = fmaf(xv.x, c.x, fmaf(xv.y, c.y, fmaf(xv.z, c.z, fmaf(xv.w, c.w, acc[r][2]))));
                    acc[r][3] = fmaf(xv.x, d.x, fmaf(xv.y, d.y, fmaf(xv.z, d.z, fmaf(xv.w, d.w, acc[r][3]))));
                }
            }
#pragma unroll
            for (int r = 0; r < FGROUP; r++)
#pragma unroll
                for (int q = 0; q < 4; q++) {
                    float a = acc[r][q];
#pragma unroll
                    for (int o = 16; o > 0; o >>= 1)
                        a += __shfl_xor_sync(0xFFFFFFFFu, a, o);
                    if (lane == 0 && r < nrows)
                        g_hfix[(size_t)(base + r) * INTER + j0 + q] =
                            fmaxf(a + b1[j0 + q], 0.0f);
                }
        }
    }
}

__global__ __launch_bounds__(256) void fixup_exact_kernel(
    const float* __restrict__ W2, const float* __restrict__ b2, float* __restrict__ c)
{
    extern __shared__ float hs[];
    const int tid = threadIdx.x;
    const int lane = tid & 31, warp = tid >> 5;
    const int nf = g_flag_cnt;
    const int ngroup = (nf + FGROUP - 1) / FGROUP;
    const int ntask = ngroup * 4;

    for (int task = blockIdx.x; task < ntask; task += gridDim.x) {
        const int grp = task >> 2, quart = task & 3;
        const int base = grp * FGROUP;
        const int nrows = min(FGROUP, nf - base);
        __syncthreads();
        for (int r = 0; r < nrows; r++) {
            for (int k = tid; k < INTER; k += 256)
                hs[r * INTER + k] = g_hfix[(size_t)(base + r) * INTER + k];
        }
        __syncthreads();

        for (int jg = 0; jg < 16; jg++) {
            const int j0 = quart * 512 + warp * 64 + jg * 4;
            const float4* w0 = (const float4*)(W2 + (size_t)(j0 + 0) * INTER);
            const float4* w1 = (const float4*)(W2 + (size_t)(j0 + 1) * INTER);
            const float4* w2 = (const float4*)(W2 + (size_t)(j0 + 2) * INTER);
            const float4* w3 = (const float4*)(W2 + (size_t)(j0 + 3) * INTER);
            float acc[FGROUP][4];
#pragma unroll
            for (int r = 0; r < FGROUP; r++)
#pragma unroll
                for (int q = 0; q < 4; q++) acc[r][q] = 0.0f;

            for (int kk = lane; kk < INTER / 4; kk += 32) {
                float4 a = w0[kk], b = w1[kk], cc = w2[kk], d = w3[kk];
#pragma unroll
                for (int r = 0; r < FGROUP; r++) {
                    float4 hv = ((const float4*)(hs + r * INTER))[kk];
                    acc[r][0] = fmaf(hv.x, a.x, fmaf(hv.y, a.y, fmaf(hv.z, a.z, fmaf(hv.w, a.w, acc[r][0]))));
                    acc[r][1] = fmaf(hv.x, b.x, fmaf(hv.y, b.y, fmaf(hv.z, b.z, fmaf(hv.w, b.w, acc[r][1]))));
                    acc[r][2] = fmaf(hv.x, cc.x, fmaf(hv.y, cc.y, fmaf(hv.z, cc.z, fmaf(hv.w, cc.w, acc[r][2]))));
                    acc[r][3] = fmaf(hv.x, d.x, fmaf(hv.y, d.y, fmaf(hv.z, d.z, fmaf(hv.w, d.w, acc[r][3]))));
                }
            }
#pragma unroll
            for (int r = 0; r < FGROUP; r++)
#pragma unroll
                for (int q = 0; q < 4; q++) {
                    float a = acc[r][q];
#pragma unroll
                    for (int o = 16; o > 0; o >>= 1)
                        a += __shfl_xor_sync(0xFFFFFFFFu, a, o);
                    if (lane == 0 && r < nrows) {
                        int row = g_flag_rows[base + r];
                        c[(size_t)row * CODE + j0 + q] = fmaxf(a + b2[j0 + q], 0.0f);
                    }
                }
        }
    }
}

__global__ __launch_bounds__(256) void fixup_topk_kernel(const float* __restrict__ C)
{
    __shared__ TopkSmem S;
    const int nf = g_flag_cnt;
    for (int i = blockIdx.x; i < nf; i += gridDim.x) {
        topk_body(S, C, g_flag_rows[i], false);
        __syncthreads();
    }
}

// ---------------------------------------------------------------------------
// L3: sparse row-gather GEMV, fp16 weights, fp32 accum -> d fp16 pair
// ---------------------------------------------------------------------------
__global__ __launch_bounds__(256) void l3_gather(
    const __half* __restrict__ W3T, const float* __restrict__ b3,
    __half* __restrict__ D0, __half* __restrict__ D1)
{
    __shared__ float sval[KNEUR];
    __shared__ int   sidx[KNEUR];
    const int row = blockIdx.x, tid = threadIdx.x;
    const int cnt = g_cnt[row];
    if (tid < KNEUR && tid < cnt) {
        sidx[tid] = g_idx[row * KNEUR + tid];
        sval[tid] = g_val[row * KNEUR + tid];
    }
    __syncthreads();

    const int n = tid * 4;
    float4 acc = *(const float4*)(b3 + n);
    int j = 0;
    for (; j + 4 <= cnt; j += 4) {
#pragma unroll
        for (int q = 0; q < 4; q++) {
            const __half2* wp = (const __half2*)(W3T + (size_t)sidx[j + q] * INTER + n);
            float2 lo = __half22float2(wp[0]);
            float2 hi = __half22float2(wp[1]);
            const float v = sval[j + q];
            acc.x = fmaf(v, lo.x, acc.x); acc.y = fmaf(v, lo.y, acc.y);
            acc.z = fmaf(v, hi.x, acc.z); acc.w = fmaf(v, hi.y, acc.w);
        }
    }
    for (; j < cnt; j++) {
        const __half2* wp = (const __half2*)(W3T + (size_t)sidx[j] * INTER + n);
        float2 lo = __half22float2(wp[0]);
        float2 hi = __half22float2(wp[1]);
        const float v = sval[j];
        acc.x = fmaf(v, lo.x, acc.x); acc.y = fmaf(v, lo.y, acc.y);
        acc.z = fmaf(v, hi.x, acc.z); acc.w = fmaf(v, hi.y, acc.w);
    }

    acc.x = fmaxf(acc.x, 0.0f); acc.y = fmaxf(acc.y, 0.0f);
    acc.z = fmaxf(acc.z, 0.0f); acc.w = fmaxf(acc.w, 0.0f);

    __half h0 = __float2half_rn(acc.x), h1 = __float2half_rn(acc.y);
    __half h2 = __float2half_rn(acc.z), h3 = __float2half_rn(acc.w);
    __half2 hh0 = __halves2half2(h0, h1), hh1 = __halves2half2(h2, h3);
    __half2 ll0 = __halves2half2(
        __float2half_rn((acc.x - __half2float(h0)) * 2048.0f),
        __float2half_rn((acc.y - __half2float(h1)) * 2048.0f));
    __half2 ll1 = __halves2half2(
        __float2half_rn((acc.z - __half2float(h2)) * 2048.0f),
        __float2half_rn((acc.w - __half2float(h3)) * 2048.0f));
    *(__half2*)(D0 + (size_t)row * INTER + n)     = hh0;
    *(__half2*)(D0 + (size_t)row * INTER + n + 2) = hh1;
    *(__half2*)(D1 + (size_t)row * INTER + n)     = ll0;
    *(__half2*)(D1 + (size_t)row * INTER + n + 2) = ll1;
}

// ---------------------------------------------------------------------------
extern "C" void kernel_launch(void* const* d_in, const int* in_sizes, int n_in,
                              void* d_out, int out_size)
{
    const float* x  = (const float*)d_in[0];
    const float* W1 = (const float*)d_in[1];
    const float* b1 = (const float*)d_in[2];
    const float* W2 = (const float*)d_in[3];
    const float* b2 = (const float*)d_in[4];
    const float* W3 = (const float*)d_in[5];
    const float* b3 = (const float*)d_in[6];
    const float* W4 = (const float*)d_in[7];
    const float* b4 = (const float*)d_in[8];
    float* out = (float*)d_out;

    float* c;
    __half *x0, *x1, *w1h, *w1l, *hh16, *hl16, *w2h16, *w2l16;
    __half *w3t16, *dh16, *dl16, *w4h16;
    cudaGetSymbolAddress((void**)&c, g_c);
    cudaGetSymbolAddress((void**)&x0, g_x0);       cudaGetSymbolAddress((void**)&x1, g_x1);
    cudaGetSymbolAddress((void**)&w1h, g_w1h);     cudaGetSymbolAddress((void**)&w1l, g_w1l);
    cudaGetSymbolAddress((void**)&hh16, g_hh16);   cudaGetSymbolAddress((void**)&hl16, g_hl16);
    cudaGetSymbolAddress((void**)&w2h16, g_w2h16); cudaGetSymbolAddress((void**)&w2l16, g_w2l16);
    cudaGetSymbolAddress((void**)&w3t16, g_w3t16);
    cudaGetSymbolAddress((void**)&dh16, g_dh16);   cudaGetSymbolAddress((void**)&dl16, g_dl16);
    cudaGetSymbolAddress((void**)&w4h16, g_w4h16);

    cudaFuncSetAttribute(gemm_f16<0,3>, cudaFuncAttributeMaxDynamicSharedMemorySize, SMEM_HMMA3);
    cudaFuncSetAttribute(gemm_f16<1,3>, cudaFuncAttributeMaxDynamicSharedMemorySize, SMEM_HMMA3);
    cudaFuncSetAttribute(gemm_f16<0,2>, cudaFuncAttributeMaxDynamicSharedMemorySize, SMEM_HMMA2);
    cudaFuncSetAttribute(h_fix_kernel, cudaFuncAttributeMaxDynamicSharedMemorySize,
                         FGROUP * IN_DIM * (int)sizeof(float));
    cudaFuncSetAttribute(fixup_exact_kernel, cudaFuncAttributeMaxDynamicSharedMemorySize,
                         FGROUP * INTER * (int)sizeof(float));

    auto gs = [](size_t n) { return (unsigned)((n + 255) / 256); };

    // prep
    split16_pad<<<gs((size_t)BATCH * K1P), 256>>>(x,  x0,  x1,  BATCH, IN_DIM, BATCH, K1P);
    split16_pad<<<gs((size_t)INTER * K1P), 256>>>(W1, w1h, w1l, INTER, IN_DIM, INTER, K1P);
    split16_pad<<<gs((size_t)CODE * INTER), 256>>>(W2, w2h16, w2l16, CODE, INTER, CODE, INTER);
    convert16_pad<<<gs((size_t)N4P * INTER), 256>>>(W4, w4h16, IN_DIM, INTER, N4P, INTER);
    transpose_w3<<<dim3(CODE / 32, INTER / 32), dim3(32, 8)>>>(W3, w3t16);

    // L1: 3-term fp16 HMMA -> h pair
    gemm_f16<1,3><<<dim3(INTER / 64, BATCH / 128), 256, SMEM_HMMA3>>>(
        x0, x1, w1h, w1l, b1, nullptr, hh16, hl16, K1P, INTER, INTER);

    // L2: 3-term fp16 HMMA -> c fp32
    gemm_f16<0,3><<<dim3(CODE / 64, BATCH / 128), 256, SMEM_HMMA3>>>(
        hh16, hl16, w2h16, w2l16, b2, c, nullptr, nullptr, INTER, CODE, CODE);

    // topk + margins + batched exact fixup
    reset_cnt_kernel<<<1, 32>>>();
    topk_flag_kernel<<<BATCH, 256>>>(c);
    h_fix_kernel<<<512, 256, FGROUP * IN_DIM * sizeof(float)>>>(x, W1, b1);
    fixup_exact_kernel<<<1024, 256, FGROUP * INTER * sizeof(float)>>>(W2, b2, c);
    fixup_topk_kernel<<<1024, 256>>>(c);

    // L3 sparse gather -> d fp16 pair
    l3_gather<<<BATCH, 256>>>(w3t16, b3, dh16, dl16);

    // L4: 2-term fp16 HMMA -> out fp32
    gemm_f16<0,2><<<dim3(N4P / 64, BATCH / 128), 256, SMEM_HMMA2>>>(
        dh16, dl16, w4h16, nullptr, b4, out, nullptr, nullptr, INTER, IN_DIM, IN_DIM);
}